// round 6
// baseline (speedup 1.0000x reference)
#include <cuda_runtime.h>
#include <cuda_fp16.h>
#include <cstdint>

#define Bn   512
#define Sn   200
#define Dn   512
#define Hn   8
#define FFn  1024
#define EMBn 128
#define HIDn 1024
#define FINn 64
#define UD   1152        // D + 5*EMB
#define BS   (Bn*Sn)     // 102400

// ---------------- scratch (static device globals; no runtime allocation) ----
__device__ float  g_x[(size_t)BS*Dn];      // fp32 embeddings -> later x_final
__device__ float  g_f[(size_t)BS*Dn];      // fp32 attn_proj / f2 (LN "p" input)
__device__ float  g_xn[(size_t)BS*Dn];     // fp32 x after first LN chain
__device__ __half g_xh[(size_t)BS*Dn];     // half embeddings
__device__ __half g_qkvh[(size_t)BS*3*Dn]; // half qkv
__device__ __half g_attnh[(size_t)BS*Dn];  // half attention out
__device__ __half g_xnh[(size_t)BS*Dn];    // half x_new
__device__ __half g_hh[(size_t)BS*FFn];    // half FFN hidden
__device__ __half g_inwh[1536*Dn];
__device__ __half g_outwh[Dn*Dn];
__device__ __half g_l1wh[FFn*Dn];
__device__ __half g_l2wh[Dn*FFn];
__device__ float  g_mask[BS];
__device__ float  g_u[Bn*UD];
__device__ float  g_h2[Bn*HIDn];

__device__ __forceinline__ uint32_t pack_h2(float a, float b) {
    __half2 h = __floats2half2_rn(a, b);
    return *(uint32_t*)&h;
}

__device__ __forceinline__ void mma16816(float* c,
    uint32_t a0, uint32_t a1, uint32_t a2, uint32_t a3,
    uint32_t b0, uint32_t b1)
{
    asm volatile(
        "mma.sync.aligned.m16n8k16.row.col.f32.f16.f16.f32 "
        "{%0,%1,%2,%3}, {%4,%5,%6,%7}, {%8,%9}, {%0,%1,%2,%3};"
        : "+f"(c[0]), "+f"(c[1]), "+f"(c[2]), "+f"(c[3])
        : "r"(a0), "r"(a1), "r"(a2), "r"(a3), "r"(b0), "r"(b1));
}

// ---------------- weight fp32 -> fp16 convert -------------------------------
__global__ void w2h_kernel(const float* __restrict__ w, __half* __restrict__ o, int n4)
{
    int i = blockIdx.x * 256 + threadIdx.x;
    if (i < n4) {
        float4 v = ((const float4*)w)[i];
        ((uint2*)o)[i] = make_uint2(pack_h2(v.x, v.y), pack_h2(v.z, v.w));
    }
}

// =================== fp16 GEMM: C[M,N] = epi(A @ W^T + bias) ================
// A half [M,K], W half [N,K]. CTA tile 256x128, BK=16. 8 warps 4Mx2N,
// warp tile 64x64. M mult of 256, N mult of 128, K mult of 16.
// Smem: 8-b32 rows, XOR swizzle c^(r&7) -> conflict-free STS + fragment LDS.
__global__ __launch_bounds__(256) void hgemm(
    const __half* __restrict__ A, const __half* __restrict__ W,
    const float* __restrict__ bias, float* __restrict__ Cf, __half* __restrict__ Ch,
    int N, int K, float lo, float hi, int relu)
{
    __shared__ uint32_t As[2][256*8];
    __shared__ uint32_t Bs[2][128*8];

    const int tid  = threadIdx.x;
    const int lane = tid & 31;
    const int wid  = tid >> 5;
    const int gid  = lane >> 2;
    const int tig  = lane & 3;
    const int mw = (wid >> 1) * 64;
    const int nw = (wid & 1) * 64;
    const int K2 = K >> 1;

    const size_t rowA0 = (size_t)blockIdx.y * 256;
    const size_t rowW0 = (size_t)blockIdx.x * 128;
    const uint32_t* A2 = (const uint32_t*)A + rowA0 * K2;
    const uint32_t* W2 = (const uint32_t*)W + rowW0 * K2;
    const int lr = tid >> 3;   // 0..31
    const int lc = tid & 7;    // 0..7

    float acc[4][8][4];
#pragma unroll
    for (int mi = 0; mi < 4; mi++)
#pragma unroll
        for (int ni = 0; ni < 8; ni++)
#pragma unroll
            for (int j = 0; j < 4; j++) acc[mi][ni][j] = 0.f;

    const int nit = K >> 4;
    uint32_t pa[8], pb[4];
#pragma unroll
    for (int i = 0; i < 8; i++) pa[i] = A2[(size_t)(lr + i * 32) * K2 + lc];
#pragma unroll
    for (int i = 0; i < 4; i++) pb[i] = W2[(size_t)(lr + i * 32) * K2 + lc];

    for (int ck = 0; ck < nit; ck++) {
        const int buf = ck & 1;
#pragma unroll
        for (int i = 0; i < 8; i++) {
            int r = lr + i * 32;
            As[buf][r * 8 + (lc ^ (r & 7))] = pa[i];
        }
#pragma unroll
        for (int i = 0; i < 4; i++) {
            int r = lr + i * 32;
            Bs[buf][r * 8 + (lc ^ (r & 7))] = pb[i];
        }
        __syncthreads();

        if (ck + 1 < nit) {
            int ko = (ck + 1) * 8 + lc;
#pragma unroll
            for (int i = 0; i < 8; i++) pa[i] = A2[(size_t)(lr + i * 32) * K2 + ko];
#pragma unroll
            for (int i = 0; i < 4; i++) pb[i] = W2[(size_t)(lr + i * 32) * K2 + ko];
        }

        uint32_t af[4][4], bf[8][2];
#pragma unroll
        for (int mi = 0; mi < 4; mi++) {
            int ra = mw + mi * 16 + gid, rb = ra + 8;
            af[mi][0] = As[buf][ra * 8 + (tig ^ (ra & 7))];
            af[mi][1] = As[buf][rb * 8 + (tig ^ (rb & 7))];
            af[mi][2] = As[buf][ra * 8 + ((tig + 4) ^ (ra & 7))];
            af[mi][3] = As[buf][rb * 8 + ((tig + 4) ^ (rb & 7))];
        }
#pragma unroll
        for (int ni = 0; ni < 8; ni++) {
            int n = nw + ni * 8 + gid;
            bf[ni][0] = Bs[buf][n * 8 + (tig ^ (n & 7))];
            bf[ni][1] = Bs[buf][n * 8 + ((tig + 4) ^ (n & 7))];
        }
#pragma unroll
        for (int mi = 0; mi < 4; mi++)
#pragma unroll
            for (int ni = 0; ni < 8; ni++)
                mma16816(acc[mi][ni], af[mi][0], af[mi][1], af[mi][2], af[mi][3],
                         bf[ni][0], bf[ni][1]);
    }

    const int bn0 = blockIdx.x * 128 + nw;
#pragma unroll
    for (int mi = 0; mi < 4; mi++) {
        size_t row = rowA0 + mw + mi * 16 + gid;
#pragma unroll
        for (int ni = 0; ni < 8; ni++) {
            int col = bn0 + ni * 8 + 2 * tig;
            float b0 = bias ? bias[col]     : 0.f;
            float b1 = bias ? bias[col + 1] : 0.f;
            float v0 = acc[mi][ni][0] + b0, v1 = acc[mi][ni][1] + b1;
            float v2 = acc[mi][ni][2] + b0, v3 = acc[mi][ni][3] + b1;
            v0 = fminf(fmaxf(v0, lo), hi); v1 = fminf(fmaxf(v1, lo), hi);
            v2 = fminf(fmaxf(v2, lo), hi); v3 = fminf(fmaxf(v3, lo), hi);
            if (relu) {
                v0 = fmaxf(v0, 0.f); v1 = fmaxf(v1, 0.f);
                v2 = fmaxf(v2, 0.f); v3 = fmaxf(v3, 0.f);
            }
            if (Cf) {
                *(float2*)(Cf + row * N + col)       = make_float2(v0, v1);
                *(float2*)(Cf + (row + 8) * N + col) = make_float2(v2, v3);
            }
            if (Ch) {
                *(uint32_t*)(Ch + row * N + col)       = pack_h2(v0, v1);
                *(uint32_t*)(Ch + (row + 8) * N + col) = pack_h2(v2, v3);
            }
        }
    }
}

// =================== tensor-core attention per (b,h), fp16 I/O ==============
#define SP 208
#define QK_STRIDE 36
#define P_STRIDE 108
#define OFF_Q 44928
#define OFF_K 59904
#define OFF_VT 44928
#define SMEM_HALFS 74880
#define ATTN_SMEM (SMEM_HALFS*2 + SP*4*2)

__global__ __launch_bounds__(256) void attn_mma_kernel()
{
    extern __shared__ __half sm[];
    float* linv = (float*)(sm + SMEM_HALFS);
    float* msk  = linv + SP;
    uint32_t* P2 = (uint32_t*)sm;
    uint32_t* Q2 = (uint32_t*)(sm + OFF_Q);
    uint32_t* K2 = (uint32_t*)(sm + OFF_K);
    uint32_t* V2 = (uint32_t*)(sm + OFF_VT);

    const int h = blockIdx.x, b = blockIdx.y;
    const int tid = threadIdx.x;
    const int lane = tid & 31, wid = tid >> 5;
    const int gid = lane >> 2, tig = lane & 3;
    const __half* base = g_qkvh + (size_t)b * Sn * 1536 + h * 64;

    for (int idx = tid; idx < SP * 32; idx += 256) {
        int row = idx >> 5, c2 = idx & 31;
        uint32_t pq = 0u, pk = 0u;
        if (row < Sn) {
            const uint32_t* rp = (const uint32_t*)(base + (size_t)row * 1536);
            pq = rp[c2];
            pk = rp[256 + c2];
        }
        Q2[row * QK_STRIDE + c2] = pq;
        K2[row * QK_STRIDE + c2] = pk;
    }
    if (tid < SP) msk[tid] = (tid < Sn) ? g_mask[b * Sn + tid] : 0.f;
    __syncthreads();

    for (int mt = wid; mt < 13; mt += 8) {
        int r = mt * 16 + gid;
        uint32_t af[4][4];
#pragma unroll
        for (int kc = 0; kc < 4; kc++) {
            af[kc][0] = Q2[r * QK_STRIDE + kc * 8 + tig];
            af[kc][1] = Q2[(r + 8) * QK_STRIDE + kc * 8 + tig];
            af[kc][2] = Q2[r * QK_STRIDE + kc * 8 + tig + 4];
            af[kc][3] = Q2[(r + 8) * QK_STRIDE + kc * 8 + tig + 4];
        }
        for (int nt = 0; nt < 26; nt++) {
            float sacc[4] = {0.f, 0.f, 0.f, 0.f};
            int n = nt * 8 + gid;
#pragma unroll
            for (int kc = 0; kc < 4; kc++) {
                uint32_t b0 = K2[n * QK_STRIDE + kc * 8 + tig];
                uint32_t b1 = K2[n * QK_STRIDE + kc * 8 + tig + 4];
                mma16816(sacc, af[kc][0], af[kc][1], af[kc][2], af[kc][3], b0, b1);
            }
            int c = nt * 8 + 2 * tig;
            float m0 = msk[c], m1 = msk[c + 1];
            float e0 = m0 * __expf(fminf(fmaxf(sacc[0] * 2.5f, -3.f), 3.f) - 3.f);
            float e1 = m1 * __expf(fminf(fmaxf(sacc[1] * 2.5f, -3.f), 3.f) - 3.f);
            float e2 = m0 * __expf(fminf(fmaxf(sacc[2] * 2.5f, -3.f), 3.f) - 3.f);
            float e3 = m1 * __expf(fminf(fmaxf(sacc[3] * 2.5f, -3.f), 3.f) - 3.f);
            P2[r * P_STRIDE + nt * 4 + tig]       = pack_h2(e0, e1);
            P2[(r + 8) * P_STRIDE + nt * 4 + tig] = pack_h2(e2, e3);
        }
    }
    __syncthreads();

    for (int idx = tid; idx < SP * 64; idx += 256) {
        int row = idx >> 6, col = idx & 63;
        __half v = (row < Sn) ? base[(size_t)row * 1536 + 1024 + col] : __half(0.f);
        sm[OFF_VT + col * (2 * P_STRIDE) + row] = v;
    }
    for (int t = tid; t < SP; t += 256) {
        float s = 0.f;
        for (int i = 0; i < 104; i++) {
            __half2 hv = *(__half2*)&P2[t * P_STRIDE + i];
            float2 f = __half22float2(hv);
            s += f.x + f.y;
        }
        linv[t] = 1.f / s;
    }
    __syncthreads();

    for (int mt = wid; mt < 13; mt += 8) {
        int r = mt * 16 + gid;
        float acc[8][4];
#pragma unroll
        for (int nt = 0; nt < 8; nt++)
#pragma unroll
            for (int j = 0; j < 4; j++) acc[nt][j] = 0.f;

        for (int kc = 0; kc < 13; kc++) {
            uint32_t a0 = P2[r * P_STRIDE + kc * 8 + tig];
            uint32_t a1 = P2[(r + 8) * P_STRIDE + kc * 8 + tig];
            uint32_t a2 = P2[r * P_STRIDE + kc * 8 + tig + 4];
            uint32_t a3 = P2[(r + 8) * P_STRIDE + kc * 8 + tig + 4];
#pragma unroll
            for (int nt = 0; nt < 8; nt++) {
                int d = nt * 8 + gid;
                uint32_t b0 = V2[d * P_STRIDE + kc * 8 + tig];
                uint32_t b1 = V2[d * P_STRIDE + kc * 8 + tig + 4];
                mma16816(acc[nt], a0, a1, a2, a3, b0, b1);
            }
        }
        float i0 = linv[r];
        float i1 = linv[r + 8];
        if (r < Sn) {
            __half* op = g_attnh + (size_t)(b * Sn + r) * Dn + h * 64 + 2 * tig;
#pragma unroll
            for (int nt = 0; nt < 8; nt++)
                *(uint32_t*)(op + nt * 8) = pack_h2(acc[nt][0] * i0, acc[nt][1] * i0);
        }
        if (r + 8 < Sn) {
            __half* op = g_attnh + (size_t)(b * Sn + r + 8) * Dn + h * 64 + 2 * tig;
#pragma unroll
            for (int nt = 0; nt < 8; nt++)
                *(uint32_t*)(op + nt * 8) = pack_h2(acc[nt][2] * i1, acc[nt][3] * i1);
        }
    }
}

// ---------------- embedding + mask (fp32 + fp16 outputs) --------------------
__global__ void embed_kernel(const int* __restrict__ seq, const float* __restrict__ tab)
{
    int i = blockIdx.x;
    int t = threadIdx.x;
    int item = seq[i];
    if (t == 0) g_mask[i] = (item == 0) ? 0.f : 1.f;
    float4 v = ((const float4*)(tab + (size_t)item * Dn))[t];
    v.x = fminf(fmaxf(v.x * 0.5f, -1.f), 1.f);
    v.y = fminf(fmaxf(v.y * 0.5f, -1.f), 1.f);
    v.z = fminf(fmaxf(v.z * 0.5f, -1.f), 1.f);
    v.w = fminf(fmaxf(v.w * 0.5f, -1.f), 1.f);
    ((float4*)(g_x + (size_t)i * Dn))[t] = v;
    ((uint2*)(g_xh + (size_t)i * Dn))[t] = make_uint2(pack_h2(v.x, v.y), pack_h2(v.z, v.w));
}

// ---------------- fp32 SIMT GEMM (small head GEMMs only) --------------------
__global__ __launch_bounds__(256) void gemm_nt(
    const float* __restrict__ A, const float* __restrict__ W,
    const float* __restrict__ bias, float* __restrict__ C,
    int M, int N, int K, float lo, float hi, int relu)
{
    __shared__ float As[16][128];
    __shared__ float Bs[16][128];
    int tid = threadIdx.x;
    int tx = tid & 15, ty = tid >> 4;
    int lrow = tid >> 2;
    int lc4  = (tid & 3) * 4;
    const float* Ab = A + (size_t)blockIdx.y * 128 * K;
    const float* Wb = W + (size_t)blockIdx.x * 128 * K;
    int nbase = blockIdx.x * 128;

    float acc[8][8];
#pragma unroll
    for (int i = 0; i < 8; i++)
#pragma unroll
        for (int j = 0; j < 8; j++) acc[i][j] = 0.f;

    for (int k0 = 0; k0 < K; k0 += 16) {
#pragma unroll
        for (int r = 0; r < 2; r++) {
            int row = lrow + r * 64;
            float4 a = *(const float4*)(Ab + (size_t)row * K + k0 + lc4);
            As[lc4+0][row] = a.x; As[lc4+1][row] = a.y;
            As[lc4+2][row] = a.z; As[lc4+3][row] = a.w;
            float4 w4 = make_float4(0.f, 0.f, 0.f, 0.f);
            if (nbase + row < N)
                w4 = *(const float4*)(Wb + (size_t)row * K + k0 + lc4);
            Bs[lc4+0][row] = w4.x; Bs[lc4+1][row] = w4.y;
            Bs[lc4+2][row] = w4.z; Bs[lc4+3][row] = w4.w;
        }
        __syncthreads();
#pragma unroll
        for (int kk = 0; kk < 16; kk++) {
            float af[8], bf[8];
            *(float4*)&af[0] = *(const float4*)&As[kk][ty*8];
            *(float4*)&af[4] = *(const float4*)&As[kk][ty*8+4];
            *(float4*)&bf[0] = *(const float4*)&Bs[kk][tx*8];
            *(float4*)&bf[4] = *(const float4*)&Bs[kk][tx*8+4];
#pragma unroll
            for (int i = 0; i < 8; i++)
#pragma unroll
                for (int j = 0; j < 8; j++)
                    acc[i][j] = fmaf(af[i], bf[j], acc[i][j]);
        }
        __syncthreads();
    }

    int row0 = blockIdx.y * 128 + ty * 8;
    int col0 = nbase + tx * 8;
#pragma unroll
    for (int i = 0; i < 8; i++) {
#pragma unroll
        for (int j = 0; j < 8; j++) {
            int c = col0 + j;
            if (c < N) {
                float v = acc[i][j] + (bias ? bias[c] : 0.f);
                v = fminf(fmaxf(v, lo), hi);
                if (relu) v = fmaxf(v, 0.f);
                C[(size_t)(row0 + i) * N + c] = v;
            }
        }
    }
}

// ---------------- fused double residual+LN ---------------------------------
__device__ __forceinline__ void block_reduce2(float& a, float& b, float* red)
{
    __syncthreads();
#pragma unroll
    for (int o = 16; o > 0; o >>= 1) {
        a += __shfl_xor_sync(0xffffffffu, a, o);
        b += __shfl_xor_sync(0xffffffffu, b, o);
    }
    int w = threadIdx.x >> 5;
    if ((threadIdx.x & 31) == 0) { red[w] = a; red[w + 8] = b; }
    __syncthreads();
    if (threadIdx.x == 0) {
        float ta = 0.f, tb = 0.f;
        for (int i = 0; i < 8; i++) { ta += red[i]; tb += red[i + 8]; }
        red[0] = ta; red[8] = tb;
    }
    __syncthreads();
    a = red[0]; b = red[8];
}

// out = LN(x + LN(x + p)); optional clip; optional fp16 copy out2
__global__ __launch_bounds__(256) void ln_chain_kernel(
    const float* __restrict__ x, const float* __restrict__ p,
    const float* __restrict__ g, const float* __restrict__ bt,
    float* __restrict__ out, __half* __restrict__ out2, float clipv)
{
    __shared__ float red[16];
    int row = blockIdx.x;
    int t = threadIdx.x;
    float2 xv = ((const float2*)(x + (size_t)row * Dn))[t];
    float2 pv = ((const float2*)(p + (size_t)row * Dn))[t];
    float t0 = xv.x + pv.x, t1 = xv.y + pv.y;
    float s1 = t0 + t1, s2 = t0 * t0 + t1 * t1;
    block_reduce2(s1, s2, red);
    float mean = s1 * (1.f / Dn);
    float inv = rsqrtf(s2 * (1.f / Dn) - mean * mean + 1e-6f);
    float2 gv = ((const float2*)g)[t];
    float2 bv = ((const float2*)bt)[t];
    float sa0 = (t0 - mean) * inv * gv.x + bv.x;
    float sa1 = (t1 - mean) * inv * gv.y + bv.y;
    float u0 = xv.x + sa0, u1 = xv.y + sa1;
    s1 = u0 + u1; s2 = u0 * u0 + u1 * u1;
    block_reduce2(s1, s2, red);
    mean = s1 * (1.f / Dn);
    inv = rsqrtf(s2 * (1.f / Dn) - mean * mean + 1e-6f);
    float o0 = (u0 - mean) * inv * gv.x + bv.x;
    float o1 = (u1 - mean) * inv * gv.y + bv.y;
    if (clipv > 0.f) {
        o0 = fminf(fmaxf(o0, -clipv), clipv);
        o1 = fminf(fmaxf(o1, -clipv), clipv);
    }
    ((float2*)(out + (size_t)row * Dn))[t] = make_float2(o0, o1);
    if (out2)
        ((uint32_t*)(out2 + (size_t)row * Dn))[t] = pack_h2(o0, o1);
}

// ---------------- masked mean pool + user feature concat --------------------
__global__ void pool_u_kernel(
    const float* __restrict__ uctr, const float* __restrict__ uti,
    const int* __restrict__ age, const int* __restrict__ gen, const int* __restrict__ cms,
    const float* __restrict__ atab, const float* __restrict__ gtab, const float* __restrict__ ctab,
    const float* __restrict__ cw, const float* __restrict__ cb,
    const float* __restrict__ tw, const float* __restrict__ tb)
{
    int b = blockIdx.x, j = threadIdx.x;
    const float* base = g_x + (size_t)b * Sn * Dn;
    float sum = 0.f, ms = 0.f;
    for (int s = 0; s < Sn; s++) {
        float m = g_mask[b * Sn + s];
        sum = fmaf(base[(size_t)s * Dn + j], m, sum);
        ms += m;
    }
    float rep = sum / (ms + 1e-8f);
    rep = fminf(fmaxf(rep, -5.f), 5.f);
    float* u = g_u + b * UD;
    u[j] = rep;
    if (j < EMBn) {
        u[512 + j]  = fmaf(uctr[b], cw[j], cb[j]);
        u[640 + j]  = fmaf(uti[b],  tw[j], tb[j]);
        u[768 + j]  = atab[age[b] * EMBn + j];
        u[896 + j]  = gtab[gen[b] * EMBn + j];
        u[1024 + j] = ctab[cms[b] * EMBn + j];
    }
}

// ---------------- launch ----------------------------------------------------
extern "C" void kernel_launch(void* const* d_in, const int* in_sizes, int n_in,
                              void* d_out, int out_size)
{
    const int*   item_seq = (const int*)d_in[0];
    const float* uctr = (const float*)d_in[1];
    const float* uti  = (const float*)d_in[2];
    const int*   age  = (const int*)d_in[3];
    const int*   gen  = (const int*)d_in[4];
    const int*   cms  = (const int*)d_in[5];
    const float* emb  = (const float*)d_in[6];
    const float* inw  = (const float*)d_in[7];
    const float* outw = (const float*)d_in[8];
    const float* outb = (const float*)d_in[9];
    const float* ln1g = (const float*)d_in[10];
    const float* ln1b = (const float*)d_in[11];
    const float* ln2g = (const float*)d_in[12];
    const float* ln2b = (const float*)d_in[13];
    const float* l1w  = (const float*)d_in[14];
    const float* l1b  = (const float*)d_in[15];
    const float* l2w  = (const float*)d_in[16];
    const float* l2b  = (const float*)d_in[17];
    const float* atab = (const float*)d_in[18];
    const float* gtab = (const float*)d_in[19];
    const float* ctab = (const float*)d_in[20];
    const float* cw   = (const float*)d_in[21];
    const float* cb   = (const float*)d_in[22];
    const float* tw   = (const float*)d_in[23];
    const float* tb   = (const float*)d_in[24];
    const float* m1w  = (const float*)d_in[25];
    const float* m1b  = (const float*)d_in[26];
    const float* m2w  = (const float*)d_in[27];
    const float* m2b  = (const float*)d_in[28];
    float* out = (float*)d_out;

    float  *px, *pf, *pxn, *pu, *ph2, *pmask;
    __half *pxh, *pqkvh, *pattnh, *pxnh, *phh, *pinwh, *poutwh, *pl1wh, *pl2wh;
    cudaGetSymbolAddress((void**)&px,     g_x);
    cudaGetSymbolAddress((void**)&pf,     g_f);
    cudaGetSymbolAddress((void**)&pxn,    g_xn);
    cudaGetSymbolAddress((void**)&pu,     g_u);
    cudaGetSymbolAddress((void**)&ph2,    g_h2);
    cudaGetSymbolAddress((void**)&pmask,  g_mask);
    cudaGetSymbolAddress((void**)&pxh,    g_xh);
    cudaGetSymbolAddress((void**)&pqkvh,  g_qkvh);
    cudaGetSymbolAddress((void**)&pattnh, g_attnh);
    cudaGetSymbolAddress((void**)&pxnh,   g_xnh);
    cudaGetSymbolAddress((void**)&phh,    g_hh);
    cudaGetSymbolAddress((void**)&pinwh,  g_inwh);
    cudaGetSymbolAddress((void**)&poutwh, g_outwh);
    cudaGetSymbolAddress((void**)&pl1wh,  g_l1wh);
    cudaGetSymbolAddress((void**)&pl2wh,  g_l2wh);

    cudaFuncSetAttribute(attn_mma_kernel,
                         cudaFuncAttributeMaxDynamicSharedMemorySize, ATTN_SMEM);

    const float INF = 1e30f;

    // weight conversions (fp32 -> fp16)
    w2h_kernel<<<(1536*Dn/4 + 255)/256, 256>>>(inw,  pinwh, 1536*Dn/4);
    w2h_kernel<<<(Dn*Dn/4   + 255)/256, 256>>>(outw, poutwh, Dn*Dn/4);
    w2h_kernel<<<(FFn*Dn/4  + 255)/256, 256>>>(l1w,  pl1wh, FFn*Dn/4);
    w2h_kernel<<<(Dn*FFn/4  + 255)/256, 256>>>(l2w,  pl2wh, Dn*FFn/4);

    // x = clip(emb*0.5) -> fp32 + fp16, mask
    embed_kernel<<<BS, 128>>>(item_seq, emb);
    // qkv = clip(x @ in_proj^T, +-1) -> fp16 only
    hgemm<<<dim3(12, 400), 256>>>(pxh, pinwh, nullptr, nullptr, pqkvh, 1536, 512, -1.f, 1.f, 0);
    // tensor-core attention (fp16 in/out)
    attn_mma_kernel<<<dim3(Hn, Bn), 256, ATTN_SMEM>>>();
    // attn_proj = clip(attn @ out_w^T + b, +-3) -> fp32
    hgemm<<<dim3(4, 400), 256>>>(pattnh, poutwh, outb, pf, nullptr, 512, 512, -3.f, 3.f, 0);
    // x_new = LN(x + LN(x + attn_proj)) -> fp32 + fp16
    ln_chain_kernel<<<BS, 256>>>(px, pf, ln1g, ln1b, pxn, pxnh, 0.f);
    // h = relu(clip(x_new @ lin1^T + b, +-2)) -> fp16 only
    hgemm<<<dim3(8, 400), 256>>>(pxnh, pl1wh, l1b, nullptr, phh, 1024, 512, -2.f, 2.f, 1);
    // f2 = clip(h @ lin2^T + b, +-2) -> fp32
    hgemm<<<dim3(4, 400), 256>>>(phh, pl2wh, l2b, pf, nullptr, 512, 1024, -2.f, 2.f, 0);
    // x_final = clip(LN(x_new + LN(x_new + f2)), +-5) -> fp32 g_x
    ln_chain_kernel<<<BS, 256>>>(pxn, pf, ln2g, ln2b, px, nullptr, 5.f);
    // seq_rep + user features -> u
    pool_u_kernel<<<Bn, 512>>>(uctr, uti, age, gen, cms, atab, gtab, ctab, cw, cb, tw, tb);
    // mlp head (tiny; fp32 SIMT)
    gemm_nt<<<dim3(8, 4), 256>>>(pu, m1w, m1b, ph2, Bn, HIDn, UD, -INF, INF, 1);
    gemm_nt<<<dim3(1, 4), 256>>>(ph2, m2w, m2b, out, Bn, FINn, HIDn, -INF, INF, 0);
}

// round 7
// speedup vs baseline: 1.2324x; 1.2324x over previous
#include <cuda_runtime.h>
#include <cuda_fp16.h>
#include <cstdint>

#define Bn   512
#define Sn   200
#define Dn   512
#define Hn   8
#define FFn  1024
#define EMBn 128
#define HIDn 1024
#define FINn 64
#define UD   1152        // D + 5*EMB
#define BS   (Bn*Sn)     // 102400

// ---------------- scratch (static device globals; no runtime allocation) ----
__device__ float  g_x[(size_t)BS*Dn];      // fp32 embeddings -> later x_final
__device__ float  g_f[(size_t)BS*Dn];      // fp32 attn_proj / f2 (LN "p" input)
__device__ float  g_xn[(size_t)BS*Dn];     // fp32 x after first LN chain
__device__ __half g_xh[(size_t)BS*Dn];     // half embeddings
__device__ __half g_qkvh[(size_t)BS*3*Dn]; // half qkv
__device__ __half g_attnh[(size_t)BS*Dn];  // half attention out
__device__ __half g_xnh[(size_t)BS*Dn];    // half x_new
__device__ __half g_hh[(size_t)BS*FFn];    // half FFN hidden
__device__ __half g_inwh[1536*Dn];
__device__ __half g_outwh[Dn*Dn];
__device__ __half g_l1wh[FFn*Dn];
__device__ __half g_l2wh[Dn*FFn];
__device__ float  g_mask[BS];
__device__ float  g_u[Bn*UD];
__device__ float  g_h2[Bn*HIDn];

__device__ __forceinline__ uint32_t pack_h2(float a, float b) {
    __half2 h = __floats2half2_rn(a, b);
    return *(uint32_t*)&h;
}

__device__ __forceinline__ void mma16816(float* c,
    uint32_t a0, uint32_t a1, uint32_t a2, uint32_t a3,
    uint32_t b0, uint32_t b1)
{
    asm volatile(
        "mma.sync.aligned.m16n8k16.row.col.f32.f16.f16.f32 "
        "{%0,%1,%2,%3}, {%4,%5,%6,%7}, {%8,%9}, {%0,%1,%2,%3};"
        : "+f"(c[0]), "+f"(c[1]), "+f"(c[2]), "+f"(c[3])
        : "r"(a0), "r"(a1), "r"(a2), "r"(a3), "r"(b0), "r"(b1));
}

__device__ __forceinline__ void ldsm_x4(uint32_t* r, uint32_t saddr) {
    asm volatile("ldmatrix.sync.aligned.m8n8.x4.shared.b16 {%0,%1,%2,%3}, [%4];"
        : "=r"(r[0]), "=r"(r[1]), "=r"(r[2]), "=r"(r[3]) : "r"(saddr));
}

// ---------------- weight fp32 -> fp16 convert -------------------------------
__global__ void w2h_kernel(const float* __restrict__ w, __half* __restrict__ o, int n4)
{
    int i = blockIdx.x * 256 + threadIdx.x;
    if (i < n4) {
        float4 v = ((const float4*)w)[i];
        ((uint2*)o)[i] = make_uint2(pack_h2(v.x, v.y), pack_h2(v.z, v.w));
    }
}

// =================== fp16 GEMM: C[M,N] = epi(A @ W^T + bias) ================
// A half [M,K], W half [N,K]. CTA 128x128, BK=32, 8 warps (2M x 4N), warp 64x32.
// M,N multiples of 128; K multiple of 32. Double buffer, 1 sync/iter.
// Smem rows of 20 uint32 (16 used, 80B stride) -> LDSM conflict-free.
#define PADB 20

__global__ __launch_bounds__(256, 2) void hgemm(
    const __half* __restrict__ A, const __half* __restrict__ W,
    const float* __restrict__ bias, float* __restrict__ Cf, __half* __restrict__ Ch,
    int N, int K, float lo, float hi, int relu)
{
    __shared__ uint32_t As[2][128*PADB];
    __shared__ uint32_t Bs[2][128*PADB];

    const int tid  = threadIdx.x;
    const int lane = tid & 31;
    const int wid  = tid >> 5;
    const int gid  = lane >> 2;
    const int tig  = lane & 3;
    const int mw = (wid >> 2) * 64;
    const int nw = (wid & 3) * 32;

    const size_t rowA0 = (size_t)blockIdx.y * 128;
    const size_t rowW0 = (size_t)blockIdx.x * 128;
    const int K4 = K >> 3;                    // uint4 per row
    const uint4* A4 = (const uint4*)A + rowA0 * K4;
    const uint4* W4 = (const uint4*)W + rowW0 * K4;

    // LDG mapping: thread -> rows (tid>>2, +64), uint4 col (tid&3) within BK=32
    const int gr = tid >> 2;                  // 0..63
    const int gc = tid & 3;                   // 0..3

    // LDSM lane offsets
    const int aRow = (lane & 7) + ((lane >> 3) & 1) * 8;
    const int aCol = (lane >> 4) * 4;
    const int bRow = (lane & 7) + (lane >> 4) * 8;
    const int bCol = ((lane >> 3) & 1) * 4;

    const uint32_t aBase = (uint32_t)__cvta_generic_to_shared(&As[0][0]);
    const uint32_t bBase = (uint32_t)__cvta_generic_to_shared(&Bs[0][0]);

    float acc[4][4][4];
#pragma unroll
    for (int mi = 0; mi < 4; mi++)
#pragma unroll
        for (int ni = 0; ni < 4; ni++)
#pragma unroll
            for (int j = 0; j < 4; j++) acc[mi][ni][j] = 0.f;

    const int nit = K >> 5;
    uint4 pa0, pa1, pb0, pb1;
    pa0 = A4[(size_t)gr * K4 + gc];
    pa1 = A4[(size_t)(gr + 64) * K4 + gc];
    pb0 = W4[(size_t)gr * K4 + gc];
    pb1 = W4[(size_t)(gr + 64) * K4 + gc];

    for (int ck = 0; ck < nit; ck++) {
        const int buf = ck & 1;
        *(uint4*)&As[buf][gr * PADB + gc * 4]        = pa0;
        *(uint4*)&As[buf][(gr + 64) * PADB + gc * 4] = pa1;
        *(uint4*)&Bs[buf][gr * PADB + gc * 4]        = pb0;
        *(uint4*)&Bs[buf][(gr + 64) * PADB + gc * 4] = pb1;
        __syncthreads();

        if (ck + 1 < nit) {
            int ko = (ck + 1) * 4 + gc;
            pa0 = A4[(size_t)gr * K4 + ko];
            pa1 = A4[(size_t)(gr + 64) * K4 + ko];
            pb0 = W4[(size_t)gr * K4 + ko];
            pb1 = W4[(size_t)(gr + 64) * K4 + ko];
        }

        const uint32_t aB = aBase + (uint32_t)buf * (128 * PADB * 4);
        const uint32_t bB = bBase + (uint32_t)buf * (128 * PADB * 4);
#pragma unroll
        for (int ks = 0; ks < 2; ks++) {
            uint32_t af[4][4], bf[4][2];
#pragma unroll
            for (int mi = 0; mi < 4; mi++)
                ldsm_x4(af[mi], aB + ((mw + mi * 16 + aRow) * PADB + ks * 8 + aCol) * 4);
#pragma unroll
            for (int p = 0; p < 2; p++) {
                uint32_t t[4];
                ldsm_x4(t, bB + ((nw + p * 16 + bRow) * PADB + ks * 8 + bCol) * 4);
                bf[2*p][0] = t[0]; bf[2*p][1] = t[1];
                bf[2*p+1][0] = t[2]; bf[2*p+1][1] = t[3];
            }
#pragma unroll
            for (int mi = 0; mi < 4; mi++)
#pragma unroll
                for (int ni = 0; ni < 4; ni++)
                    mma16816(acc[mi][ni], af[mi][0], af[mi][1], af[mi][2], af[mi][3],
                             bf[ni][0], bf[ni][1]);
        }
        __syncthreads();
    }

    const int bn0 = blockIdx.x * 128 + nw;
#pragma unroll
    for (int mi = 0; mi < 4; mi++) {
        size_t row = rowA0 + mw + mi * 16 + gid;
#pragma unroll
        for (int ni = 0; ni < 4; ni++) {
            int col = bn0 + ni * 8 + 2 * tig;
            float b0 = bias ? bias[col]     : 0.f;
            float b1 = bias ? bias[col + 1] : 0.f;
            float v0 = acc[mi][ni][0] + b0, v1 = acc[mi][ni][1] + b1;
            float v2 = acc[mi][ni][2] + b0, v3 = acc[mi][ni][3] + b1;
            v0 = fminf(fmaxf(v0, lo), hi); v1 = fminf(fmaxf(v1, lo), hi);
            v2 = fminf(fmaxf(v2, lo), hi); v3 = fminf(fmaxf(v3, lo), hi);
            if (relu) {
                v0 = fmaxf(v0, 0.f); v1 = fmaxf(v1, 0.f);
                v2 = fmaxf(v2, 0.f); v3 = fmaxf(v3, 0.f);
            }
            if (Cf) {
                *(float2*)(Cf + row * N + col)       = make_float2(v0, v1);
                *(float2*)(Cf + (row + 8) * N + col) = make_float2(v2, v3);
            }
            if (Ch) {
                *(uint32_t*)(Ch + row * N + col)       = pack_h2(v0, v1);
                *(uint32_t*)(Ch + (row + 8) * N + col) = pack_h2(v2, v3);
            }
        }
    }
}

// =================== tensor-core attention per (b,h), fp16 I/O ==============
#define SP 208
#define QK_STRIDE 36
#define P_STRIDE 108
#define OFF_Q 44928
#define OFF_K 59904
#define OFF_VT 44928
#define SMEM_HALFS 74880
#define ATTN_SMEM (SMEM_HALFS*2 + SP*4*2)

__global__ __launch_bounds__(256) void attn_mma_kernel()
{
    extern __shared__ __half sm[];
    float* linv = (float*)(sm + SMEM_HALFS);
    float* msk  = linv + SP;
    uint32_t* P2 = (uint32_t*)sm;
    uint32_t* Q2 = (uint32_t*)(sm + OFF_Q);
    uint32_t* K2 = (uint32_t*)(sm + OFF_K);
    uint32_t* V2 = (uint32_t*)(sm + OFF_VT);

    const int h = blockIdx.x, b = blockIdx.y;
    const int tid = threadIdx.x;
    const int lane = tid & 31, wid = tid >> 5;
    const int gid = lane >> 2, tig = lane & 3;
    const __half* base = g_qkvh + (size_t)b * Sn * 1536 + h * 64;

    for (int idx = tid; idx < SP * 32; idx += 256) {
        int row = idx >> 5, c2 = idx & 31;
        uint32_t pq = 0u, pk = 0u;
        if (row < Sn) {
            const uint32_t* rp = (const uint32_t*)(base + (size_t)row * 1536);
            pq = rp[c2];
            pk = rp[256 + c2];
        }
        Q2[row * QK_STRIDE + c2] = pq;
        K2[row * QK_STRIDE + c2] = pk;
    }
    if (tid < SP) msk[tid] = (tid < Sn) ? g_mask[b * Sn + tid] : 0.f;
    __syncthreads();

    for (int mt = wid; mt < 13; mt += 8) {
        int r = mt * 16 + gid;
        uint32_t af[4][4];
#pragma unroll
        for (int kc = 0; kc < 4; kc++) {
            af[kc][0] = Q2[r * QK_STRIDE + kc * 8 + tig];
            af[kc][1] = Q2[(r + 8) * QK_STRIDE + kc * 8 + tig];
            af[kc][2] = Q2[r * QK_STRIDE + kc * 8 + tig + 4];
            af[kc][3] = Q2[(r + 8) * QK_STRIDE + kc * 8 + tig + 4];
        }
        for (int nt = 0; nt < 26; nt++) {
            float sacc[4] = {0.f, 0.f, 0.f, 0.f};
            int n = nt * 8 + gid;
#pragma unroll
            for (int kc = 0; kc < 4; kc++) {
                uint32_t b0 = K2[n * QK_STRIDE + kc * 8 + tig];
                uint32_t b1 = K2[n * QK_STRIDE + kc * 8 + tig + 4];
                mma16816(sacc, af[kc][0], af[kc][1], af[kc][2], af[kc][3], b0, b1);
            }
            int c = nt * 8 + 2 * tig;
            float m0 = msk[c], m1 = msk[c + 1];
            float e0 = m0 * __expf(fminf(fmaxf(sacc[0] * 2.5f, -3.f), 3.f) - 3.f);
            float e1 = m1 * __expf(fminf(fmaxf(sacc[1] * 2.5f, -3.f), 3.f) - 3.f);
            float e2 = m0 * __expf(fminf(fmaxf(sacc[2] * 2.5f, -3.f), 3.f) - 3.f);
            float e3 = m1 * __expf(fminf(fmaxf(sacc[3] * 2.5f, -3.f), 3.f) - 3.f);
            P2[r * P_STRIDE + nt * 4 + tig]       = pack_h2(e0, e1);
            P2[(r + 8) * P_STRIDE + nt * 4 + tig] = pack_h2(e2, e3);
        }
    }
    __syncthreads();

    for (int idx = tid; idx < SP * 64; idx += 256) {
        int row = idx >> 6, col = idx & 63;
        __half v = (row < Sn) ? base[(size_t)row * 1536 + 1024 + col] : __half(0.f);
        sm[OFF_VT + col * (2 * P_STRIDE) + row] = v;
    }
    for (int t = tid; t < SP; t += 256) {
        float s = 0.f;
        for (int i = 0; i < 104; i++) {
            __half2 hv = *(__half2*)&P2[t * P_STRIDE + i];
            float2 f = __half22float2(hv);
            s += f.x + f.y;
        }
        linv[t] = 1.f / s;
    }
    __syncthreads();

    for (int mt = wid; mt < 13; mt += 8) {
        int r = mt * 16 + gid;
        float acc[8][4];
#pragma unroll
        for (int nt = 0; nt < 8; nt++)
#pragma unroll
            for (int j = 0; j < 4; j++) acc[nt][j] = 0.f;

        for (int kc = 0; kc < 13; kc++) {
            uint32_t a0 = P2[r * P_STRIDE + kc * 8 + tig];
            uint32_t a1 = P2[(r + 8) * P_STRIDE + kc * 8 + tig];
            uint32_t a2 = P2[r * P_STRIDE + kc * 8 + tig + 4];
            uint32_t a3 = P2[(r + 8) * P_STRIDE + kc * 8 + tig + 4];
#pragma unroll
            for (int nt = 0; nt < 8; nt++) {
                int d = nt * 8 + gid;
                uint32_t b0 = V2[d * P_STRIDE + kc * 8 + tig];
                uint32_t b1 = V2[d * P_STRIDE + kc * 8 + tig + 4];
                mma16816(acc[nt], a0, a1, a2, a3, b0, b1);
            }
        }
        float i0 = linv[r];
        float i1 = linv[r + 8];
        if (r < Sn) {
            __half* op = g_attnh + (size_t)(b * Sn + r) * Dn + h * 64 + 2 * tig;
#pragma unroll
            for (int nt = 0; nt < 8; nt++)
                *(uint32_t*)(op + nt * 8) = pack_h2(acc[nt][0] * i0, acc[nt][1] * i0);
        }
        if (r + 8 < Sn) {
            __half* op = g_attnh + (size_t)(b * Sn + r + 8) * Dn + h * 64 + 2 * tig;
#pragma unroll
            for (int nt = 0; nt < 8; nt++)
                *(uint32_t*)(op + nt * 8) = pack_h2(acc[nt][2] * i1, acc[nt][3] * i1);
        }
    }
}

// ---------------- embedding + mask (fp32 + fp16 outputs) --------------------
__global__ void embed_kernel(const int* __restrict__ seq, const float* __restrict__ tab)
{
    int i = blockIdx.x;
    int t = threadIdx.x;
    int item = seq[i];
    if (t == 0) g_mask[i] = (item == 0) ? 0.f : 1.f;
    float4 v = ((const float4*)(tab + (size_t)item * Dn))[t];
    v.x = fminf(fmaxf(v.x * 0.5f, -1.f), 1.f);
    v.y = fminf(fmaxf(v.y * 0.5f, -1.f), 1.f);
    v.z = fminf(fmaxf(v.z * 0.5f, -1.f), 1.f);
    v.w = fminf(fmaxf(v.w * 0.5f, -1.f), 1.f);
    ((float4*)(g_x + (size_t)i * Dn))[t] = v;
    ((uint2*)(g_xh + (size_t)i * Dn))[t] = make_uint2(pack_h2(v.x, v.y), pack_h2(v.z, v.w));
}

// ---------------- fp32 SIMT GEMM (small head GEMMs only) --------------------
__global__ __launch_bounds__(256) void gemm_nt(
    const float* __restrict__ A, const float* __restrict__ W,
    const float* __restrict__ bias, float* __restrict__ C,
    int M, int N, int K, float lo, float hi, int relu)
{
    __shared__ float As[16][128];
    __shared__ float Bs[16][128];
    int tid = threadIdx.x;
    int tx = tid & 15, ty = tid >> 4;
    int lrow = tid >> 2;
    int lc4  = (tid & 3) * 4;
    const float* Ab = A + (size_t)blockIdx.y * 128 * K;
    const float* Wb = W + (size_t)blockIdx.x * 128 * K;
    int nbase = blockIdx.x * 128;

    float acc[8][8];
#pragma unroll
    for (int i = 0; i < 8; i++)
#pragma unroll
        for (int j = 0; j < 8; j++) acc[i][j] = 0.f;

    for (int k0 = 0; k0 < K; k0 += 16) {
#pragma unroll
        for (int r = 0; r < 2; r++) {
            int row = lrow + r * 64;
            float4 a = *(const float4*)(Ab + (size_t)row * K + k0 + lc4);
            As[lc4+0][row] = a.x; As[lc4+1][row] = a.y;
            As[lc4+2][row] = a.z; As[lc4+3][row] = a.w;
            float4 w4 = make_float4(0.f, 0.f, 0.f, 0.f);
            if (nbase + row < N)
                w4 = *(const float4*)(Wb + (size_t)row * K + k0 + lc4);
            Bs[lc4+0][row] = w4.x; Bs[lc4+1][row] = w4.y;
            Bs[lc4+2][row] = w4.z; Bs[lc4+3][row] = w4.w;
        }
        __syncthreads();
#pragma unroll
        for (int kk = 0; kk < 16; kk++) {
            float af[8], bf[8];
            *(float4*)&af[0] = *(const float4*)&As[kk][ty*8];
            *(float4*)&af[4] = *(const float4*)&As[kk][ty*8+4];
            *(float4*)&bf[0] = *(const float4*)&Bs[kk][tx*8];
            *(float4*)&bf[4] = *(const float4*)&Bs[kk][tx*8+4];
#pragma unroll
            for (int i = 0; i < 8; i++)
#pragma unroll
                for (int j = 0; j < 8; j++)
                    acc[i][j] = fmaf(af[i], bf[j], acc[i][j]);
        }
        __syncthreads();
    }

    int row0 = blockIdx.y * 128 + ty * 8;
    int col0 = nbase + tx * 8;
#pragma unroll
    for (int i = 0; i < 8; i++) {
#pragma unroll
        for (int j = 0; j < 8; j++) {
            int c = col0 + j;
            if (c < N) {
                float v = acc[i][j] + (bias ? bias[c] : 0.f);
                v = fminf(fmaxf(v, lo), hi);
                if (relu) v = fmaxf(v, 0.f);
                C[(size_t)(row0 + i) * N + c] = v;
            }
        }
    }
}

// ---------------- fused double residual+LN ---------------------------------
__device__ __forceinline__ void block_reduce2(float& a, float& b, float* red)
{
    __syncthreads();
#pragma unroll
    for (int o = 16; o > 0; o >>= 1) {
        a += __shfl_xor_sync(0xffffffffu, a, o);
        b += __shfl_xor_sync(0xffffffffu, b, o);
    }
    int w = threadIdx.x >> 5;
    if ((threadIdx.x & 31) == 0) { red[w] = a; red[w + 8] = b; }
    __syncthreads();
    if (threadIdx.x == 0) {
        float ta = 0.f, tb = 0.f;
        for (int i = 0; i < 8; i++) { ta += red[i]; tb += red[i + 8]; }
        red[0] = ta; red[8] = tb;
    }
    __syncthreads();
    a = red[0]; b = red[8];
}

__global__ __launch_bounds__(256) void ln_chain_kernel(
    const float* __restrict__ x, const float* __restrict__ p,
    const float* __restrict__ g, const float* __restrict__ bt,
    float* __restrict__ out, __half* __restrict__ out2, float clipv)
{
    __shared__ float red[16];
    int row = blockIdx.x;
    int t = threadIdx.x;
    float2 xv = ((const float2*)(x + (size_t)row * Dn))[t];
    float2 pv = ((const float2*)(p + (size_t)row * Dn))[t];
    float t0 = xv.x + pv.x, t1 = xv.y + pv.y;
    float s1 = t0 + t1, s2 = t0 * t0 + t1 * t1;
    block_reduce2(s1, s2, red);
    float mean = s1 * (1.f / Dn);
    float inv = rsqrtf(s2 * (1.f / Dn) - mean * mean + 1e-6f);
    float2 gv = ((const float2*)g)[t];
    float2 bv = ((const float2*)bt)[t];
    float sa0 = (t0 - mean) * inv * gv.x + bv.x;
    float sa1 = (t1 - mean) * inv * gv.y + bv.y;
    float u0 = xv.x + sa0, u1 = xv.y + sa1;
    s1 = u0 + u1; s2 = u0 * u0 + u1 * u1;
    block_reduce2(s1, s2, red);
    mean = s1 * (1.f / Dn);
    inv = rsqrtf(s2 * (1.f / Dn) - mean * mean + 1e-6f);
    float o0 = (u0 - mean) * inv * gv.x + bv.x;
    float o1 = (u1 - mean) * inv * gv.y + bv.y;
    if (clipv > 0.f) {
        o0 = fminf(fmaxf(o0, -clipv), clipv);
        o1 = fminf(fmaxf(o1, -clipv), clipv);
    }
    ((float2*)(out + (size_t)row * Dn))[t] = make_float2(o0, o1);
    if (out2)
        ((uint32_t*)(out2 + (size_t)row * Dn))[t] = pack_h2(o0, o1);
}

// ---------------- masked mean pool + user feature concat --------------------
__global__ void pool_u_kernel(
    const float* __restrict__ uctr, const float* __restrict__ uti,
    const int* __restrict__ age, const int* __restrict__ gen, const int* __restrict__ cms,
    const float* __restrict__ atab, const float* __restrict__ gtab, const float* __restrict__ ctab,
    const float* __restrict__ cw, const float* __restrict__ cb,
    const float* __restrict__ tw, const float* __restrict__ tb)
{
    int b = blockIdx.x, j = threadIdx.x;
    const float* base = g_x + (size_t)b * Sn * Dn;
    float sum = 0.f, ms = 0.f;
    for (int s = 0; s < Sn; s++) {
        float m = g_mask[b * Sn + s];
        sum = fmaf(base[(size_t)s * Dn + j], m, sum);
        ms += m;
    }
    float rep = sum / (ms + 1e-8f);
    rep = fminf(fmaxf(rep, -5.f), 5.f);
    float* u = g_u + b * UD;
    u[j] = rep;
    if (j < EMBn) {
        u[512 + j]  = fmaf(uctr[b], cw[j], cb[j]);
        u[640 + j]  = fmaf(uti[b],  tw[j], tb[j]);
        u[768 + j]  = atab[age[b] * EMBn + j];
        u[896 + j]  = gtab[gen[b] * EMBn + j];
        u[1024 + j] = ctab[cms[b] * EMBn + j];
    }
}

// ---------------- launch ----------------------------------------------------
extern "C" void kernel_launch(void* const* d_in, const int* in_sizes, int n_in,
                              void* d_out, int out_size)
{
    const int*   item_seq = (const int*)d_in[0];
    const float* uctr = (const float*)d_in[1];
    const float* uti  = (const float*)d_in[2];
    const int*   age  = (const int*)d_in[3];
    const int*   gen  = (const int*)d_in[4];
    const int*   cms  = (const int*)d_in[5];
    const float* emb  = (const float*)d_in[6];
    const float* inw  = (const float*)d_in[7];
    const float* outw = (const float*)d_in[8];
    const float* outb = (const float*)d_in[9];
    const float* ln1g = (const float*)d_in[10];
    const float* ln1b = (const float*)d_in[11];
    const float* ln2g = (const float*)d_in[12];
    const float* ln2b = (const float*)d_in[13];
    const float* l1w  = (const float*)d_in[14];
    const float* l1b  = (const float*)d_in[15];
    const float* l2w  = (const float*)d_in[16];
    const float* l2b  = (const float*)d_in[17];
    const float* atab = (const float*)d_in[18];
    const float* gtab = (const float*)d_in[19];
    const float* ctab = (const float*)d_in[20];
    const float* cw   = (const float*)d_in[21];
    const float* cb   = (const float*)d_in[22];
    const float* tw   = (const float*)d_in[23];
    const float* tb   = (const float*)d_in[24];
    const float* m1w  = (const float*)d_in[25];
    const float* m1b  = (const float*)d_in[26];
    const float* m2w  = (const float*)d_in[27];
    const float* m2b  = (const float*)d_in[28];
    float* out = (float*)d_out;

    float  *px, *pf, *pxn, *pu, *ph2;
    __half *pxh, *pqkvh, *pattnh, *pxnh, *phh, *pinwh, *poutwh, *pl1wh, *pl2wh;
    cudaGetSymbolAddress((void**)&px,     g_x);
    cudaGetSymbolAddress((void**)&pf,     g_f);
    cudaGetSymbolAddress((void**)&pxn,    g_xn);
    cudaGetSymbolAddress((void**)&pu,     g_u);
    cudaGetSymbolAddress((void**)&ph2,    g_h2);
    cudaGetSymbolAddress((void**)&pxh,    g_xh);
    cudaGetSymbolAddress((void**)&pqkvh,  g_qkvh);
    cudaGetSymbolAddress((void**)&pattnh, g_attnh);
    cudaGetSymbolAddress((void**)&pxnh,   g_xnh);
    cudaGetSymbolAddress((void**)&phh,    g_hh);
    cudaGetSymbolAddress((void**)&pinwh,  g_inwh);
    cudaGetSymbolAddress((void**)&poutwh, g_outwh);
    cudaGetSymbolAddress((void**)&pl1wh,  g_l1wh);
    cudaGetSymbolAddress((void**)&pl2wh,  g_l2wh);

    cudaFuncSetAttribute(attn_mma_kernel,
                         cudaFuncAttributeMaxDynamicSharedMemorySize, ATTN_SMEM);

    const float INF = 1e30f;

    // weight conversions (fp32 -> fp16)
    w2h_kernel<<<(1536*Dn/4 + 255)/256, 256>>>(inw,  pinwh, 1536*Dn/4);
    w2h_kernel<<<(Dn*Dn/4   + 255)/256, 256>>>(outw, poutwh, Dn*Dn/4);
    w2h_kernel<<<(FFn*Dn/4  + 255)/256, 256>>>(l1w,  pl1wh, FFn*Dn/4);
    w2h_kernel<<<(Dn*FFn/4  + 255)/256, 256>>>(l2w,  pl2wh, Dn*FFn/4);

    // x = clip(emb*0.5) -> fp32 + fp16, mask
    embed_kernel<<<BS, 128>>>(item_seq, emb);
    // qkv = clip(x @ in_proj^T, +-1) -> fp16 only
    hgemm<<<dim3(12, 800), 256>>>(pxh, pinwh, nullptr, nullptr, pqkvh, 1536, 512, -1.f, 1.f, 0);
    // tensor-core attention (fp16 in/out)
    attn_mma_kernel<<<dim3(Hn, Bn), 256, ATTN_SMEM>>>();
    // attn_proj = clip(attn @ out_w^T + b, +-3) -> fp32
    hgemm<<<dim3(4, 800), 256>>>(pattnh, poutwh, outb, pf, nullptr, 512, 512, -3.f, 3.f, 0);
    // x_new = LN(x + LN(x + attn_proj)) -> fp32 + fp16
    ln_chain_kernel<<<BS, 256>>>(px, pf, ln1g, ln1b, pxn, pxnh, 0.f);
    // h = relu(clip(x_new @ lin1^T + b, +-2)) -> fp16 only
    hgemm<<<dim3(8, 800), 256>>>(pxnh, pl1wh, l1b, nullptr, phh, 1024, 512, -2.f, 2.f, 1);
    // f2 = clip(h @ lin2^T + b, +-2) -> fp32
    hgemm<<<dim3(4, 800), 256>>>(phh, pl2wh, l2b, pf, nullptr, 512, 1024, -2.f, 2.f, 0);
    // x_final = clip(LN(x_new + LN(x_new + f2)), +-5) -> fp32 g_x
    ln_chain_kernel<<<BS, 256>>>(pxn, pf, ln2g, ln2b, px, nullptr, 5.f);
    // seq_rep + user features -> u
    pool_u_kernel<<<Bn, 512>>>(uctr, uti, age, gen, cms, atab, gtab, ctab, cw, cb, tw, tb);
    // mlp head (tiny; fp32 SIMT)
    gemm_nt<<<dim3(8, 4), 256>>>(pu, m1w, m1b, ph2, Bn, HIDn, UD, -INF, INF, 1);
    gemm_nt<<<dim3(1, 4), 256>>>(ph2, m2w, m2b, out, Bn, FINn, HIDn, -INF, INF, 0);
}

// round 8
// speedup vs baseline: 1.4036x; 1.1389x over previous
#include <cuda_runtime.h>
#include <cuda_fp16.h>
#include <cstdint>

#define Bn   512
#define Sn   200
#define Dn   512
#define Hn   8
#define FFn  1024
#define EMBn 128
#define HIDn 1024
#define FINn 64
#define UD   1152        // D + 5*EMB
#define BS   (Bn*Sn)     // 102400

// ---------------- scratch (static device globals; no runtime allocation) ----
__device__ float  g_x[(size_t)BS*Dn];      // fp32 embeddings -> later x_final
__device__ float  g_xn[(size_t)BS*Dn];     // fp32 x after first LN chain
__device__ __half g_fh[(size_t)BS*Dn];     // half attn_proj / f2 (LN "p" input)
__device__ __half g_xh[(size_t)BS*Dn];     // half embeddings
__device__ __half g_qkvh[(size_t)BS*3*Dn]; // half qkv
__device__ __half g_attnh[(size_t)BS*Dn];  // half attention out
__device__ __half g_xnh[(size_t)BS*Dn];    // half x_new
__device__ __half g_hh[(size_t)BS*FFn];    // half FFN hidden
__device__ __half g_inwh[1536*Dn];
__device__ __half g_outwh[Dn*Dn];
__device__ __half g_l1wh[FFn*Dn];
__device__ __half g_l2wh[Dn*FFn];
__device__ __half g_m1wh[HIDn*UD];
__device__ __half g_uh[Bn*UD];
__device__ float  g_mask[BS];
__device__ float  g_h2[Bn*HIDn];

__device__ __forceinline__ uint32_t pack_h2(float a, float b) {
    __half2 h = __floats2half2_rn(a, b);
    return *(uint32_t*)&h;
}

__device__ __forceinline__ void mma16816(float* c,
    uint32_t a0, uint32_t a1, uint32_t a2, uint32_t a3,
    uint32_t b0, uint32_t b1)
{
    asm volatile(
        "mma.sync.aligned.m16n8k16.row.col.f32.f16.f16.f32 "
        "{%0,%1,%2,%3}, {%4,%5,%6,%7}, {%8,%9}, {%0,%1,%2,%3};"
        : "+f"(c[0]), "+f"(c[1]), "+f"(c[2]), "+f"(c[3])
        : "r"(a0), "r"(a1), "r"(a2), "r"(a3), "r"(b0), "r"(b1));
}

__device__ __forceinline__ void ldsm_x4(uint32_t* r, uint32_t saddr) {
    asm volatile("ldmatrix.sync.aligned.m8n8.x4.shared.b16 {%0,%1,%2,%3}, [%4];"
        : "=r"(r[0]), "=r"(r[1]), "=r"(r[2]), "=r"(r[3]) : "r"(saddr));
}

__device__ __forceinline__ void cp16(uint32_t saddr, const void* g) {
    asm volatile("cp.async.cg.shared.global [%0], [%1], 16;" :: "r"(saddr), "l"(g));
}

// ---------------- weight fp32 -> fp16 convert -------------------------------
__global__ void w2h_kernel(const float* __restrict__ w, __half* __restrict__ o, int n4)
{
    int i = blockIdx.x * 256 + threadIdx.x;
    if (i < n4) {
        float4 v = ((const float4*)w)[i];
        ((uint2*)o)[i] = make_uint2(pack_h2(v.x, v.y), pack_h2(v.z, v.w));
    }
}

// =================== fp16 GEMM: C[M,N] = epi(A @ W^T + bias) ================
// A half [M,K], W half [N,K]. CTA 128x128, BK=32, 8 warps (2M x 4N), warp 64x32.
// M,N multiples of 128; K multiple of 32. cp.async 3-stage pipeline.
// Smem rows of 20 uint32 (16 used, 80B stride) -> LDSM conflict-free.
#define PADB 20
#define TILE_B (128*PADB*4)          // 10240 bytes per stage per operand
#define HG_SMEM (3*2*TILE_B)         // 61440 bytes

__global__ __launch_bounds__(256) void hgemm(
    const __half* __restrict__ A, const __half* __restrict__ W,
    const float* __restrict__ bias, float* __restrict__ Cf, __half* __restrict__ Ch,
    int N, int K, float lo, float hi, int relu)
{
    extern __shared__ uint32_t ds[];
    const uint32_t sb = (uint32_t)__cvta_generic_to_shared(ds);

    const int tid  = threadIdx.x;
    const int lane = tid & 31;
    const int wid  = tid >> 5;
    const int gid  = lane >> 2;
    const int tig  = lane & 3;
    const int mw = (wid >> 2) * 64;
    const int nw = (wid & 3) * 32;

    const size_t rowA0 = (size_t)blockIdx.y * 128;
    const size_t rowW0 = (size_t)blockIdx.x * 128;
    const int K4 = K >> 3;                    // uint4 per row
    const uint4* A4 = (const uint4*)A + rowA0 * K4;
    const uint4* W4 = (const uint4*)W + rowW0 * K4;
    const int gr = tid >> 2;                  // 0..63
    const int gc = tid & 3;                   // 0..3
    const uint32_t gdst = (uint32_t)(gr * PADB + gc * 4) * 4;

    const int aRow = (lane & 7) + ((lane >> 3) & 1) * 8;
    const int aCol = (lane >> 4) * 4;
    const int bRow = (lane & 7) + (lane >> 4) * 8;
    const int bCol = ((lane >> 3) & 1) * 4;

    float acc[4][4][4];
#pragma unroll
    for (int mi = 0; mi < 4; mi++)
#pragma unroll
        for (int ni = 0; ni < 4; ni++)
#pragma unroll
            for (int j = 0; j < 4; j++) acc[mi][ni][j] = 0.f;

    const int nit = K >> 5;

    // prologue: stages 0,1
#pragma unroll
    for (int s = 0; s < 2; s++) {
        uint32_t ao = sb + (uint32_t)s * TILE_B + gdst;
        uint32_t bo = ao + 3u * TILE_B;
        int ko = s * 4 + gc;
        cp16(ao,                  &A4[(size_t)gr * K4 + ko]);
        cp16(ao + 64 * PADB * 4,  &A4[(size_t)(gr + 64) * K4 + ko]);
        cp16(bo,                  &W4[(size_t)gr * K4 + ko]);
        cp16(bo + 64 * PADB * 4,  &W4[(size_t)(gr + 64) * K4 + ko]);
        asm volatile("cp.async.commit_group;");
    }

    for (int ck = 0; ck < nit; ck++) {
        asm volatile("cp.async.wait_group 1;");
        __syncthreads();
        const int buf = ck % 3;
        const uint32_t aB = sb + (uint32_t)buf * TILE_B;
        const uint32_t bB = aB + 3u * TILE_B;
#pragma unroll
        for (int ks = 0; ks < 2; ks++) {
            uint32_t af[4][4], bf[4][2];
#pragma unroll
            for (int mi = 0; mi < 4; mi++)
                ldsm_x4(af[mi], aB + ((mw + mi * 16 + aRow) * PADB + ks * 8 + aCol) * 4);
#pragma unroll
            for (int p = 0; p < 2; p++) {
                uint32_t t[4];
                ldsm_x4(t, bB + ((nw + p * 16 + bRow) * PADB + ks * 8 + bCol) * 4);
                bf[2*p][0] = t[0]; bf[2*p][1] = t[1];
                bf[2*p+1][0] = t[2]; bf[2*p+1][1] = t[3];
            }
#pragma unroll
            for (int mi = 0; mi < 4; mi++)
#pragma unroll
                for (int ni = 0; ni < 4; ni++)
                    mma16816(acc[mi][ni], af[mi][0], af[mi][1], af[mi][2], af[mi][3],
                             bf[ni][0], bf[ni][1]);
        }
        // issue stage ck+2 (or empty commit to keep group counting exact)
        const int s = ck + 2;
        if (s < nit) {
            uint32_t ao = sb + (uint32_t)(s % 3) * TILE_B + gdst;
            uint32_t bo = ao + 3u * TILE_B;
            int ko = s * 4 + gc;
            cp16(ao,                  &A4[(size_t)gr * K4 + ko]);
            cp16(ao + 64 * PADB * 4,  &A4[(size_t)(gr + 64) * K4 + ko]);
            cp16(bo,                  &W4[(size_t)gr * K4 + ko]);
            cp16(bo + 64 * PADB * 4,  &W4[(size_t)(gr + 64) * K4 + ko]);
        }
        asm volatile("cp.async.commit_group;");
    }

    const int bn0 = blockIdx.x * 128 + nw;
#pragma unroll
    for (int mi = 0; mi < 4; mi++) {
        size_t row = rowA0 + mw + mi * 16 + gid;
#pragma unroll
        for (int ni = 0; ni < 4; ni++) {
            int col = bn0 + ni * 8 + 2 * tig;
            float b0 = bias ? bias[col]     : 0.f;
            float b1 = bias ? bias[col + 1] : 0.f;
            float v0 = acc[mi][ni][0] + b0, v1 = acc[mi][ni][1] + b1;
            float v2 = acc[mi][ni][2] + b0, v3 = acc[mi][ni][3] + b1;
            v0 = fminf(fmaxf(v0, lo), hi); v1 = fminf(fmaxf(v1, lo), hi);
            v2 = fminf(fmaxf(v2, lo), hi); v3 = fminf(fmaxf(v3, lo), hi);
            if (relu) {
                v0 = fmaxf(v0, 0.f); v1 = fmaxf(v1, 0.f);
                v2 = fmaxf(v2, 0.f); v3 = fmaxf(v3, 0.f);
            }
            if (Cf) {
                *(float2*)(Cf + row * N + col)       = make_float2(v0, v1);
                *(float2*)(Cf + (row + 8) * N + col) = make_float2(v2, v3);
            }
            if (Ch) {
                *(uint32_t*)(Ch + row * N + col)       = pack_h2(v0, v1);
                *(uint32_t*)(Ch + (row + 8) * N + col) = pack_h2(v2, v3);
            }
        }
    }
}

// =================== tensor-core attention per (b,h), fp16 I/O ==============
#define SP 208
#define QK_STRIDE 36
#define P_STRIDE 108
#define OFF_Q 44928
#define OFF_K 59904
#define OFF_VT 44928
#define SMEM_HALFS 74880
#define ATTN_SMEM (SMEM_HALFS*2 + SP*4*2)

__global__ __launch_bounds__(256) void attn_mma_kernel()
{
    extern __shared__ __half sm[];
    float* linv = (float*)(sm + SMEM_HALFS);
    float* msk  = linv + SP;
    uint32_t* P2 = (uint32_t*)sm;
    uint32_t* Q2 = (uint32_t*)(sm + OFF_Q);
    uint32_t* K2 = (uint32_t*)(sm + OFF_K);
    uint32_t* V2 = (uint32_t*)(sm + OFF_VT);

    const int h = blockIdx.x, b = blockIdx.y;
    const int tid = threadIdx.x;
    const int lane = tid & 31, wid = tid >> 5;
    const int gid = lane >> 2, tig = lane & 3;
    const __half* base = g_qkvh + (size_t)b * Sn * 1536 + h * 64;

    for (int idx = tid; idx < SP * 32; idx += 256) {
        int row = idx >> 5, c2 = idx & 31;
        uint32_t pq = 0u, pk = 0u;
        if (row < Sn) {
            const uint32_t* rp = (const uint32_t*)(base + (size_t)row * 1536);
            pq = rp[c2];
            pk = rp[256 + c2];
        }
        Q2[row * QK_STRIDE + c2] = pq;
        K2[row * QK_STRIDE + c2] = pk;
    }
    if (tid < SP) msk[tid] = (tid < Sn) ? g_mask[b * Sn + tid] : 0.f;
    __syncthreads();

    for (int mt = wid; mt < 13; mt += 8) {
        int r = mt * 16 + gid;
        uint32_t af[4][4];
#pragma unroll
        for (int kc = 0; kc < 4; kc++) {
            af[kc][0] = Q2[r * QK_STRIDE + kc * 8 + tig];
            af[kc][1] = Q2[(r + 8) * QK_STRIDE + kc * 8 + tig];
            af[kc][2] = Q2[r * QK_STRIDE + kc * 8 + tig + 4];
            af[kc][3] = Q2[(r + 8) * QK_STRIDE + kc * 8 + tig + 4];
        }
        for (int nt = 0; nt < 26; nt++) {
            float sacc[4] = {0.f, 0.f, 0.f, 0.f};
            int n = nt * 8 + gid;
#pragma unroll
            for (int kc = 0; kc < 4; kc++) {
                uint32_t b0 = K2[n * QK_STRIDE + kc * 8 + tig];
                uint32_t b1 = K2[n * QK_STRIDE + kc * 8 + tig + 4];
                mma16816(sacc, af[kc][0], af[kc][1], af[kc][2], af[kc][3], b0, b1);
            }
            int c = nt * 8 + 2 * tig;
            float m0 = msk[c], m1 = msk[c + 1];
            float e0 = m0 * __expf(fminf(fmaxf(sacc[0] * 2.5f, -3.f), 3.f) - 3.f);
            float e1 = m1 * __expf(fminf(fmaxf(sacc[1] * 2.5f, -3.f), 3.f) - 3.f);
            float e2 = m0 * __expf(fminf(fmaxf(sacc[2] * 2.5f, -3.f), 3.f) - 3.f);
            float e3 = m1 * __expf(fminf(fmaxf(sacc[3] * 2.5f, -3.f), 3.f) - 3.f);
            P2[r * P_STRIDE + nt * 4 + tig]       = pack_h2(e0, e1);
            P2[(r + 8) * P_STRIDE + nt * 4 + tig] = pack_h2(e2, e3);
        }
    }
    __syncthreads();

    for (int idx = tid; idx < SP * 64; idx += 256) {
        int row = idx >> 6, col = idx & 63;
        __half v = (row < Sn) ? base[(size_t)row * 1536 + 1024 + col] : __half(0.f);
        sm[OFF_VT + col * (2 * P_STRIDE) + row] = v;
    }
    for (int t = tid; t < SP; t += 256) {
        float s = 0.f;
        for (int i = 0; i < 104; i++) {
            __half2 hv = *(__half2*)&P2[t * P_STRIDE + i];
            float2 f = __half22float2(hv);
            s += f.x + f.y;
        }
        linv[t] = 1.f / s;
    }
    __syncthreads();

    for (int mt = wid; mt < 13; mt += 8) {
        int r = mt * 16 + gid;
        float acc[8][4];
#pragma unroll
        for (int nt = 0; nt < 8; nt++)
#pragma unroll
            for (int j = 0; j < 4; j++) acc[nt][j] = 0.f;

        for (int kc = 0; kc < 13; kc++) {
            uint32_t a0 = P2[r * P_STRIDE + kc * 8 + tig];
            uint32_t a1 = P2[(r + 8) * P_STRIDE + kc * 8 + tig];
            uint32_t a2 = P2[r * P_STRIDE + kc * 8 + tig + 4];
            uint32_t a3 = P2[(r + 8) * P_STRIDE + kc * 8 + tig + 4];
#pragma unroll
            for (int nt = 0; nt < 8; nt++) {
                int d = nt * 8 + gid;
                uint32_t b0 = V2[d * P_STRIDE + kc * 8 + tig];
                uint32_t b1 = V2[d * P_STRIDE + kc * 8 + tig + 4];
                mma16816(acc[nt], a0, a1, a2, a3, b0, b1);
            }
        }
        float i0 = linv[r];
        float i1 = linv[r + 8];
        if (r < Sn) {
            __half* op = g_attnh + (size_t)(b * Sn + r) * Dn + h * 64 + 2 * tig;
#pragma unroll
            for (int nt = 0; nt < 8; nt++)
                *(uint32_t*)(op + nt * 8) = pack_h2(acc[nt][0] * i0, acc[nt][1] * i0);
        }
        if (r + 8 < Sn) {
            __half* op = g_attnh + (size_t)(b * Sn + r + 8) * Dn + h * 64 + 2 * tig;
#pragma unroll
            for (int nt = 0; nt < 8; nt++)
                *(uint32_t*)(op + nt * 8) = pack_h2(acc[nt][2] * i1, acc[nt][3] * i1);
        }
    }
}

// ---------------- embedding + mask (fp32 + fp16 outputs) --------------------
__global__ void embed_kernel(const int* __restrict__ seq, const float* __restrict__ tab)
{
    int i = blockIdx.x;
    int t = threadIdx.x;
    int item = seq[i];
    if (t == 0) g_mask[i] = (item == 0) ? 0.f : 1.f;
    float4 v = ((const float4*)(tab + (size_t)item * Dn))[t];
    v.x = fminf(fmaxf(v.x * 0.5f, -1.f), 1.f);
    v.y = fminf(fmaxf(v.y * 0.5f, -1.f), 1.f);
    v.z = fminf(fmaxf(v.z * 0.5f, -1.f), 1.f);
    v.w = fminf(fmaxf(v.w * 0.5f, -1.f), 1.f);
    ((float4*)(g_x + (size_t)i * Dn))[t] = v;
    ((uint2*)(g_xh + (size_t)i * Dn))[t] = make_uint2(pack_h2(v.x, v.y), pack_h2(v.z, v.w));
}

// ---------------- fp32 SIMT GEMM (final tiny head GEMM only) ----------------
__global__ __launch_bounds__(256) void gemm_nt(
    const float* __restrict__ A, const float* __restrict__ W,
    const float* __restrict__ bias, float* __restrict__ C,
    int M, int N, int K, float lo, float hi, int relu)
{
    __shared__ float As[16][128];
    __shared__ float Bs[16][128];
    int tid = threadIdx.x;
    int tx = tid & 15, ty = tid >> 4;
    int lrow = tid >> 2;
    int lc4  = (tid & 3) * 4;
    const float* Ab = A + (size_t)blockIdx.y * 128 * K;
    const float* Wb = W + (size_t)blockIdx.x * 128 * K;
    int nbase = blockIdx.x * 128;

    float acc[8][8];
#pragma unroll
    for (int i = 0; i < 8; i++)
#pragma unroll
        for (int j = 0; j < 8; j++) acc[i][j] = 0.f;

    for (int k0 = 0; k0 < K; k0 += 16) {
#pragma unroll
        for (int r = 0; r < 2; r++) {
            int row = lrow + r * 64;
            float4 a = *(const float4*)(Ab + (size_t)row * K + k0 + lc4);
            As[lc4+0][row] = a.x; As[lc4+1][row] = a.y;
            As[lc4+2][row] = a.z; As[lc4+3][row] = a.w;
            float4 w4 = make_float4(0.f, 0.f, 0.f, 0.f);
            if (nbase + row < N)
                w4 = *(const float4*)(Wb + (size_t)row * K + k0 + lc4);
            Bs[lc4+0][row] = w4.x; Bs[lc4+1][row] = w4.y;
            Bs[lc4+2][row] = w4.z; Bs[lc4+3][row] = w4.w;
        }
        __syncthreads();
#pragma unroll
        for (int kk = 0; kk < 16; kk++) {
            float af[8], bf[8];
            *(float4*)&af[0] = *(const float4*)&As[kk][ty*8];
            *(float4*)&af[4] = *(const float4*)&As[kk][ty*8+4];
            *(float4*)&bf[0] = *(const float4*)&Bs[kk][tx*8];
            *(float4*)&bf[4] = *(const float4*)&Bs[kk][tx*8+4];
#pragma unroll
            for (int i = 0; i < 8; i++)
#pragma unroll
                for (int j = 0; j < 8; j++)
                    acc[i][j] = fmaf(af[i], bf[j], acc[i][j]);
        }
        __syncthreads();
    }

    int row0 = blockIdx.y * 128 + ty * 8;
    int col0 = nbase + tx * 8;
#pragma unroll
    for (int i = 0; i < 8; i++) {
#pragma unroll
        for (int j = 0; j < 8; j++) {
            int c = col0 + j;
            if (c < N) {
                float v = acc[i][j] + (bias ? bias[c] : 0.f);
                v = fminf(fmaxf(v, lo), hi);
                if (relu) v = fmaxf(v, 0.f);
                C[(size_t)(row0 + i) * N + c] = v;
            }
        }
    }
}

// ---------------- fused double residual+LN (p operand fp16) -----------------
__device__ __forceinline__ void block_reduce2(float& a, float& b, float* red)
{
    __syncthreads();
#pragma unroll
    for (int o = 16; o > 0; o >>= 1) {
        a += __shfl_xor_sync(0xffffffffu, a, o);
        b += __shfl_xor_sync(0xffffffffu, b, o);
    }
    int w = threadIdx.x >> 5;
    if ((threadIdx.x & 31) == 0) { red[w] = a; red[w + 8] = b; }
    __syncthreads();
    if (threadIdx.x == 0) {
        float ta = 0.f, tb = 0.f;
        for (int i = 0; i < 8; i++) { ta += red[i]; tb += red[i + 8]; }
        red[0] = ta; red[8] = tb;
    }
    __syncthreads();
    a = red[0]; b = red[8];
}

__global__ __launch_bounds__(256) void ln_chain_kernel(
    const float* __restrict__ x, const __half* __restrict__ p,
    const float* __restrict__ g, const float* __restrict__ bt,
    float* __restrict__ out, __half* __restrict__ out2, float clipv)
{
    __shared__ float red[16];
    int row = blockIdx.x;
    int t = threadIdx.x;
    float2 xv = ((const float2*)(x + (size_t)row * Dn))[t];
    float2 pv = __half22float2(((const __half2*)(p + (size_t)row * Dn))[t]);
    float t0 = xv.x + pv.x, t1 = xv.y + pv.y;
    float s1 = t0 + t1, s2 = t0 * t0 + t1 * t1;
    block_reduce2(s1, s2, red);
    float mean = s1 * (1.f / Dn);
    float inv = rsqrtf(s2 * (1.f / Dn) - mean * mean + 1e-6f);
    float2 gv = ((const float2*)g)[t];
    float2 bv = ((const float2*)bt)[t];
    float sa0 = (t0 - mean) * inv * gv.x + bv.x;
    float sa1 = (t1 - mean) * inv * gv.y + bv.y;
    float u0 = xv.x + sa0, u1 = xv.y + sa1;
    s1 = u0 + u1; s2 = u0 * u0 + u1 * u1;
    block_reduce2(s1, s2, red);
    mean = s1 * (1.f / Dn);
    inv = rsqrtf(s2 * (1.f / Dn) - mean * mean + 1e-6f);
    float o0 = (u0 - mean) * inv * gv.x + bv.x;
    float o1 = (u1 - mean) * inv * gv.y + bv.y;
    if (clipv > 0.f) {
        o0 = fminf(fmaxf(o0, -clipv), clipv);
        o1 = fminf(fmaxf(o1, -clipv), clipv);
    }
    ((float2*)(out + (size_t)row * Dn))[t] = make_float2(o0, o1);
    if (out2)
        ((uint32_t*)(out2 + (size_t)row * Dn))[t] = pack_h2(o0, o1);
}

// ---------------- masked mean pool + user feature concat (fp16 u) -----------
__global__ void pool_u_kernel(
    const float* __restrict__ uctr, const float* __restrict__ uti,
    const int* __restrict__ age, const int* __restrict__ gen, const int* __restrict__ cms,
    const float* __restrict__ atab, const float* __restrict__ gtab, const float* __restrict__ ctab,
    const float* __restrict__ cw, const float* __restrict__ cb,
    const float* __restrict__ tw, const float* __restrict__ tb)
{
    int b = blockIdx.x, j = threadIdx.x;
    const float* base = g_x + (size_t)b * Sn * Dn;
    float sum = 0.f, ms = 0.f;
    for (int s = 0; s < Sn; s++) {
        float m = g_mask[b * Sn + s];
        sum = fmaf(base[(size_t)s * Dn + j], m, sum);
        ms += m;
    }
    float rep = sum / (ms + 1e-8f);
    rep = fminf(fmaxf(rep, -5.f), 5.f);
    __half* u = g_uh + b * UD;
    u[j] = __float2half(rep);
    if (j < EMBn) {
        u[512 + j]  = __float2half(fmaf(uctr[b], cw[j], cb[j]));
        u[640 + j]  = __float2half(fmaf(uti[b],  tw[j], tb[j]));
        u[768 + j]  = __float2half(atab[age[b] * EMBn + j]);
        u[896 + j]  = __float2half(gtab[gen[b] * EMBn + j]);
        u[1024 + j] = __float2half(ctab[cms[b] * EMBn + j]);
    }
}

// ---------------- launch ----------------------------------------------------
extern "C" void kernel_launch(void* const* d_in, const int* in_sizes, int n_in,
                              void* d_out, int out_size)
{
    const int*   item_seq = (const int*)d_in[0];
    const float* uctr = (const float*)d_in[1];
    const float* uti  = (const float*)d_in[2];
    const int*   age  = (const int*)d_in[3];
    const int*   gen  = (const int*)d_in[4];
    const int*   cms  = (const int*)d_in[5];
    const float* emb  = (const float*)d_in[6];
    const float* inw  = (const float*)d_in[7];
    const float* outw = (const float*)d_in[8];
    const float* outb = (const float*)d_in[9];
    const float* ln1g = (const float*)d_in[10];
    const float* ln1b = (const float*)d_in[11];
    const float* ln2g = (const float*)d_in[12];
    const float* ln2b = (const float*)d_in[13];
    const float* l1w  = (const float*)d_in[14];
    const float* l1b  = (const float*)d_in[15];
    const float* l2w  = (const float*)d_in[16];
    const float* l2b  = (const float*)d_in[17];
    const float* atab = (const float*)d_in[18];
    const float* gtab = (const float*)d_in[19];
    const float* ctab = (const float*)d_in[20];
    const float* cw   = (const float*)d_in[21];
    const float* cb   = (const float*)d_in[22];
    const float* tw   = (const float*)d_in[23];
    const float* tb   = (const float*)d_in[24];
    const float* m1w  = (const float*)d_in[25];
    const float* m1b  = (const float*)d_in[26];
    const float* m2w  = (const float*)d_in[27];
    const float* m2b  = (const float*)d_in[28];
    float* out = (float*)d_out;

    float  *px, *pxn, *ph2;
    __half *pxh, *pqkvh, *pattnh, *pxnh, *phh, *pfh, *puh;
    __half *pinwh, *poutwh, *pl1wh, *pl2wh, *pm1wh;
    cudaGetSymbolAddress((void**)&px,     g_x);
    cudaGetSymbolAddress((void**)&pxn,    g_xn);
    cudaGetSymbolAddress((void**)&ph2,    g_h2);
    cudaGetSymbolAddress((void**)&pxh,    g_xh);
    cudaGetSymbolAddress((void**)&pqkvh,  g_qkvh);
    cudaGetSymbolAddress((void**)&pattnh, g_attnh);
    cudaGetSymbolAddress((void**)&pxnh,   g_xnh);
    cudaGetSymbolAddress((void**)&phh,    g_hh);
    cudaGetSymbolAddress((void**)&pfh,    g_fh);
    cudaGetSymbolAddress((void**)&puh,    g_uh);
    cudaGetSymbolAddress((void**)&pinwh,  g_inwh);
    cudaGetSymbolAddress((void**)&poutwh, g_outwh);
    cudaGetSymbolAddress((void**)&pl1wh,  g_l1wh);
    cudaGetSymbolAddress((void**)&pl2wh,  g_l2wh);
    cudaGetSymbolAddress((void**)&pm1wh,  g_m1wh);

    cudaFuncSetAttribute(attn_mma_kernel,
                         cudaFuncAttributeMaxDynamicSharedMemorySize, ATTN_SMEM);
    cudaFuncSetAttribute(hgemm,
                         cudaFuncAttributeMaxDynamicSharedMemorySize, HG_SMEM);

    const float INF = 1e30f;

    // weight conversions (fp32 -> fp16)
    w2h_kernel<<<(1536*Dn/4 + 255)/256, 256>>>(inw,  pinwh, 1536*Dn/4);
    w2h_kernel<<<(Dn*Dn/4   + 255)/256, 256>>>(outw, poutwh, Dn*Dn/4);
    w2h_kernel<<<(FFn*Dn/4  + 255)/256, 256>>>(l1w,  pl1wh, FFn*Dn/4);
    w2h_kernel<<<(Dn*FFn/4  + 255)/256, 256>>>(l2w,  pl2wh, Dn*FFn/4);
    w2h_kernel<<<(HIDn*UD/4 + 255)/256, 256>>>(m1w,  pm1wh, HIDn*UD/4);

    // x = clip(emb*0.5) -> fp32 + fp16, mask
    embed_kernel<<<BS, 128>>>(item_seq, emb);
    // qkv = clip(x @ in_proj^T, +-1) -> fp16
    hgemm<<<dim3(12, 800), 256, HG_SMEM>>>(pxh, pinwh, nullptr, nullptr, pqkvh, 1536, 512, -1.f, 1.f, 0);
    // tensor-core attention (fp16 in/out)
    attn_mma_kernel<<<dim3(Hn, Bn), 256, ATTN_SMEM>>>();
    // attn_proj = clip(attn @ out_w^T + b, +-3) -> fp16
    hgemm<<<dim3(4, 800), 256, HG_SMEM>>>(pattnh, poutwh, outb, nullptr, pfh, 512, 512, -3.f, 3.f, 0);
    // x_new = LN(x + LN(x + attn_proj)) -> fp32 + fp16
    ln_chain_kernel<<<BS, 256>>>(px, pfh, ln1g, ln1b, pxn, pxnh, 0.f);
    // h = relu(clip(x_new @ lin1^T + b, +-2)) -> fp16
    hgemm<<<dim3(8, 800), 256, HG_SMEM>>>(pxnh, pl1wh, l1b, nullptr, phh, 1024, 512, -2.f, 2.f, 1);
    // f2 = clip(h @ lin2^T + b, +-2) -> fp16
    hgemm<<<dim3(4, 800), 256, HG_SMEM>>>(phh, pl2wh, l2b, nullptr, pfh, 512, 1024, -2.f, 2.f, 0);
    // x_final = clip(LN(x_new + LN(x_new + f2)), +-5) -> fp32 g_x
    ln_chain_kernel<<<BS, 256>>>(pxn, pfh, ln2g, ln2b, px, nullptr, 5.f);
    // seq_rep + user features -> u (fp16)
    pool_u_kernel<<<Bn, 512>>>(uctr, uti, age, gen, cms, atab, gtab, ctab, cw, cb, tw, tb);
    // mlp head: h2 = relu(u @ m1w^T + b)  [fp16 mma]
    hgemm<<<dim3(8, 4), 256, HG_SMEM>>>(puh, pm1wh, m1b, ph2, nullptr, 1024, 1152, -INF, INF, 1);
    // out = h2 @ m2w^T + b  (tiny; fp32 SIMT)
    gemm_nt<<<dim3(1, 4), 256>>>(ph2, m2w, m2b, out, Bn, FINn, HIDn, -INF, INF, 0);
}

// round 9
// speedup vs baseline: 1.6331x; 1.1635x over previous
#include <cuda_runtime.h>
#include <cuda_fp16.h>
#include <cstdint>

#define Bn   512
#define Sn   200
#define Dn   512
#define Hn   8
#define FFn  1024
#define EMBn 128
#define HIDn 1024
#define FINn 64
#define UD   1152        // D + 5*EMB
#define BS   (Bn*Sn)     // 102400

// ---------------- scratch (static device globals; no runtime allocation) ----
__device__ float  g_x[(size_t)BS*Dn];      // fp32 embeddings -> later x_final
__device__ float  g_xn[(size_t)BS*Dn];     // fp32 x after first LN chain
__device__ __half g_fh[(size_t)BS*Dn];     // half attn_proj / f2 (LN "p" input)
__device__ __half g_xh[(size_t)BS*Dn];     // half embeddings
__device__ __half g_qkvh[(size_t)BS*3*Dn]; // half qkv
__device__ __half g_attnh[(size_t)BS*Dn];  // half attention out
__device__ __half g_xnh[(size_t)BS*Dn];    // half x_new
__device__ __half g_hh[(size_t)BS*FFn];    // half FFN hidden
__device__ __half g_inwh[1536*Dn];
__device__ __half g_outwh[Dn*Dn];
__device__ __half g_l1wh[FFn*Dn];
__device__ __half g_l2wh[Dn*FFn];
__device__ __half g_m1wh[HIDn*UD];
__device__ __half g_uh[Bn*UD];
__device__ float  g_mask[BS];
__device__ float  g_h2[Bn*HIDn];

__device__ __forceinline__ uint32_t pack_h2(float a, float b) {
    __half2 h = __floats2half2_rn(a, b);
    return *(uint32_t*)&h;
}

__device__ __forceinline__ void mma16816(float* c,
    uint32_t a0, uint32_t a1, uint32_t a2, uint32_t a3,
    uint32_t b0, uint32_t b1)
{
    asm volatile(
        "mma.sync.aligned.m16n8k16.row.col.f32.f16.f16.f32 "
        "{%0,%1,%2,%3}, {%4,%5,%6,%7}, {%8,%9}, {%0,%1,%2,%3};"
        : "+f"(c[0]), "+f"(c[1]), "+f"(c[2]), "+f"(c[3])
        : "r"(a0), "r"(a1), "r"(a2), "r"(a3), "r"(b0), "r"(b1));
}

__device__ __forceinline__ void ldsm_x4(uint32_t* r, uint32_t saddr) {
    asm volatile("ldmatrix.sync.aligned.m8n8.x4.shared.b16 {%0,%1,%2,%3}, [%4];"
        : "=r"(r[0]), "=r"(r[1]), "=r"(r[2]), "=r"(r[3]) : "r"(saddr));
}

__device__ __forceinline__ void cp16(uint32_t saddr, const void* g) {
    asm volatile("cp.async.cg.shared.global [%0], [%1], 16;" :: "r"(saddr), "l"(g));
}

// ---------------- weight fp32 -> fp16 convert -------------------------------
__global__ void w2h_kernel(const float* __restrict__ w, __half* __restrict__ o, int n4)
{
    int i = blockIdx.x * 256 + threadIdx.x;
    if (i < n4) {
        float4 v = ((const float4*)w)[i];
        ((uint2*)o)[i] = make_uint2(pack_h2(v.x, v.y), pack_h2(v.z, v.w));
    }
}

// =================== fp16 GEMM: C[M,N] = epi(A @ W^T + bias) ================
// CTA 128x128, BK=32, 8 warps (2M x 4N), warp 64x32. cp.async 3-stage pipeline.
#define PADB 20
#define TILE_B (128*PADB*4)
#define HG_SMEM (3*2*TILE_B)

__global__ __launch_bounds__(256) void hgemm(
    const __half* __restrict__ A, const __half* __restrict__ W,
    const float* __restrict__ bias, float* __restrict__ Cf, __half* __restrict__ Ch,
    int N, int K, float lo, float hi, int relu)
{
    extern __shared__ uint32_t ds[];
    const uint32_t sb = (uint32_t)__cvta_generic_to_shared(ds);

    const int tid  = threadIdx.x;
    const int lane = tid & 31;
    const int wid  = tid >> 5;
    const int gid  = lane >> 2;
    const int tig  = lane & 3;
    const int mw = (wid >> 2) * 64;
    const int nw = (wid & 3) * 32;

    const size_t rowA0 = (size_t)blockIdx.y * 128;
    const size_t rowW0 = (size_t)blockIdx.x * 128;
    const int K4 = K >> 3;
    const uint4* A4 = (const uint4*)A + rowA0 * K4;
    const uint4* W4 = (const uint4*)W + rowW0 * K4;
    const int gr = tid >> 2;
    const int gc = tid & 3;
    const uint32_t gdst = (uint32_t)(gr * PADB + gc * 4) * 4;

    const int aRow = (lane & 7) + ((lane >> 3) & 1) * 8;
    const int aCol = (lane >> 4) * 4;
    const int bRow = (lane & 7) + (lane >> 4) * 8;
    const int bCol = ((lane >> 3) & 1) * 4;

    float acc[4][4][4];
#pragma unroll
    for (int mi = 0; mi < 4; mi++)
#pragma unroll
        for (int ni = 0; ni < 4; ni++)
#pragma unroll
            for (int j = 0; j < 4; j++) acc[mi][ni][j] = 0.f;

    const int nit = K >> 5;

#pragma unroll
    for (int s = 0; s < 2; s++) {
        uint32_t ao = sb + (uint32_t)s * TILE_B + gdst;
        uint32_t bo = ao + 3u * TILE_B;
        int ko = s * 4 + gc;
        cp16(ao,                  &A4[(size_t)gr * K4 + ko]);
        cp16(ao + 64 * PADB * 4,  &A4[(size_t)(gr + 64) * K4 + ko]);
        cp16(bo,                  &W4[(size_t)gr * K4 + ko]);
        cp16(bo + 64 * PADB * 4,  &W4[(size_t)(gr + 64) * K4 + ko]);
        asm volatile("cp.async.commit_group;");
    }

    for (int ck = 0; ck < nit; ck++) {
        asm volatile("cp.async.wait_group 1;");
        __syncthreads();
        const int buf = ck % 3;
        const uint32_t aB = sb + (uint32_t)buf * TILE_B;
        const uint32_t bB = aB + 3u * TILE_B;
#pragma unroll
        for (int ks = 0; ks < 2; ks++) {
            uint32_t af[4][4], bf[4][2];
#pragma unroll
            for (int mi = 0; mi < 4; mi++)
                ldsm_x4(af[mi], aB + ((mw + mi * 16 + aRow) * PADB + ks * 8 + aCol) * 4);
#pragma unroll
            for (int p = 0; p < 2; p++) {
                uint32_t t[4];
                ldsm_x4(t, bB + ((nw + p * 16 + bRow) * PADB + ks * 8 + bCol) * 4);
                bf[2*p][0] = t[0]; bf[2*p][1] = t[1];
                bf[2*p+1][0] = t[2]; bf[2*p+1][1] = t[3];
            }
#pragma unroll
            for (int mi = 0; mi < 4; mi++)
#pragma unroll
                for (int ni = 0; ni < 4; ni++)
                    mma16816(acc[mi][ni], af[mi][0], af[mi][1], af[mi][2], af[mi][3],
                             bf[ni][0], bf[ni][1]);
        }
        const int s = ck + 2;
        if (s < nit) {
            uint32_t ao = sb + (uint32_t)(s % 3) * TILE_B + gdst;
            uint32_t bo = ao + 3u * TILE_B;
            int ko = s * 4 + gc;
            cp16(ao,                  &A4[(size_t)gr * K4 + ko]);
            cp16(ao + 64 * PADB * 4,  &A4[(size_t)(gr + 64) * K4 + ko]);
            cp16(bo,                  &W4[(size_t)gr * K4 + ko]);
            cp16(bo + 64 * PADB * 4,  &W4[(size_t)(gr + 64) * K4 + ko]);
        }
        asm volatile("cp.async.commit_group;");
    }

    const int bn0 = blockIdx.x * 128 + nw;
#pragma unroll
    for (int mi = 0; mi < 4; mi++) {
        size_t row = rowA0 + mw + mi * 16 + gid;
#pragma unroll
        for (int ni = 0; ni < 4; ni++) {
            int col = bn0 + ni * 8 + 2 * tig;
            float b0 = bias ? bias[col]     : 0.f;
            float b1 = bias ? bias[col + 1] : 0.f;
            float v0 = acc[mi][ni][0] + b0, v1 = acc[mi][ni][1] + b1;
            float v2 = acc[mi][ni][2] + b0, v3 = acc[mi][ni][3] + b1;
            v0 = fminf(fmaxf(v0, lo), hi); v1 = fminf(fmaxf(v1, lo), hi);
            v2 = fminf(fmaxf(v2, lo), hi); v3 = fminf(fmaxf(v3, lo), hi);
            if (relu) {
                v0 = fmaxf(v0, 0.f); v1 = fmaxf(v1, 0.f);
                v2 = fmaxf(v2, 0.f); v3 = fmaxf(v3, 0.f);
            }
            if (Cf) {
                *(float2*)(Cf + row * N + col)       = make_float2(v0, v1);
                *(float2*)(Cf + (row + 8) * N + col) = make_float2(v2, v3);
            }
            if (Ch) {
                *(uint32_t*)(Ch + row * N + col)       = pack_h2(v0, v1);
                *(uint32_t*)(Ch + (row + 8) * N + col) = pack_h2(v2, v3);
            }
        }
    }
}

// =============== flash-style tensor-core attention per (b,h) ================
// Single pass: S fragments -> exp in regs -> P fragments (C layout == A layout)
// -> PV accumulation in regs. Fixed-max softmax (scores clipped +-3).
#define SP 208
#define QKS 36    // b32 stride for Q/K rows
#define VTS 108   // b32 stride for Vt rows (104 used + 4 pad)
#define ATTN_SMEM ((SP*QKS*2 + 64*VTS)*4 + SP*4)   // 88384 bytes -> 2 CTAs/SM

__global__ __launch_bounds__(256, 2) void attn_flash_kernel()
{
    extern __shared__ uint32_t smu[];
    uint32_t* Q2 = smu;
    uint32_t* K2 = smu + SP * QKS;
    uint32_t* V2 = K2 + SP * QKS;
    float* msk = (float*)(V2 + 64 * VTS);
    __half* Vh = (__half*)V2;

    const int h = blockIdx.x, b = blockIdx.y;
    const int tid = threadIdx.x;
    const int lane = tid & 31, wid = tid >> 5;
    const int gid = lane >> 2, tig = lane & 3;
    const __half* base = g_qkvh + (size_t)b * Sn * 1536 + h * 64;

    // load Q, K (row-major, padded rows zero)
    for (int idx = tid; idx < SP * 32; idx += 256) {
        int row = idx >> 5, c2 = idx & 31;
        uint32_t pq = 0u, pk = 0u;
        if (row < Sn) {
            const uint32_t* rp = (const uint32_t*)(base + (size_t)row * 1536);
            pq = rp[c2];
            pk = rp[256 + c2];
        }
        Q2[row * QKS + c2] = pq;
        K2[row * QKS + c2] = pk;
    }
    // load V transposed: Vt[d][key]
    for (int idx = tid; idx < SP * 64; idx += 256) {
        int row = idx >> 6, col = idx & 63;
        __half v = (row < Sn) ? base[(size_t)row * 1536 + 1024 + col] : __half(0.f);
        Vh[col * (2 * VTS) + row] = v;
    }
    if (tid < SP) msk[tid] = (tid < Sn) ? g_mask[b * Sn + tid] : 0.f;
    __syncthreads();

    for (int mt = wid; mt < 13; mt += 8) {
        int r = mt * 16 + gid;
        uint32_t af[4][4];
#pragma unroll
        for (int kc = 0; kc < 4; kc++) {
            af[kc][0] = Q2[r * QKS + kc * 8 + tig];
            af[kc][1] = Q2[(r + 8) * QKS + kc * 8 + tig];
            af[kc][2] = Q2[r * QKS + kc * 8 + tig + 4];
            af[kc][3] = Q2[(r + 8) * QKS + kc * 8 + tig + 4];
        }
        float o[8][4];
#pragma unroll
        for (int nt = 0; nt < 8; nt++)
#pragma unroll
            for (int j = 0; j < 4; j++) o[nt][j] = 0.f;
        float lr = 0.f, lr8 = 0.f;

        for (int ch = 0; ch < 13; ch++) {           // 16-key chunks
            float s0[4] = {0.f,0.f,0.f,0.f}, s1[4] = {0.f,0.f,0.f,0.f};
            int n0 = ch * 16 + gid, n1 = n0 + 8;
#pragma unroll
            for (int kc = 0; kc < 4; kc++) {
                mma16816(s0, af[kc][0], af[kc][1], af[kc][2], af[kc][3],
                         K2[n0 * QKS + kc * 8 + tig], K2[n0 * QKS + kc * 8 + tig + 4]);
                mma16816(s1, af[kc][0], af[kc][1], af[kc][2], af[kc][3],
                         K2[n1 * QKS + kc * 8 + tig], K2[n1 * QKS + kc * 8 + tig + 4]);
            }
            int c0 = ch * 16 + 2 * tig;
            float m00 = msk[c0], m01 = msk[c0 + 1];
            float m10 = msk[c0 + 8], m11 = msk[c0 + 9];
            float e00 = m00 * __expf(fminf(fmaxf(s0[0] * 2.5f, -3.f), 3.f) - 3.f);
            float e01 = m01 * __expf(fminf(fmaxf(s0[1] * 2.5f, -3.f), 3.f) - 3.f);
            float e02 = m00 * __expf(fminf(fmaxf(s0[2] * 2.5f, -3.f), 3.f) - 3.f);
            float e03 = m01 * __expf(fminf(fmaxf(s0[3] * 2.5f, -3.f), 3.f) - 3.f);
            float e10 = m10 * __expf(fminf(fmaxf(s1[0] * 2.5f, -3.f), 3.f) - 3.f);
            float e11 = m11 * __expf(fminf(fmaxf(s1[1] * 2.5f, -3.f), 3.f) - 3.f);
            float e12 = m10 * __expf(fminf(fmaxf(s1[2] * 2.5f, -3.f), 3.f) - 3.f);
            float e13 = m11 * __expf(fminf(fmaxf(s1[3] * 2.5f, -3.f), 3.f) - 3.f);
            lr  += e00 + e01 + e10 + e11;
            lr8 += e02 + e03 + e12 + e13;
            // C layout == A layout: pack exp'd scores into P fragments
            uint32_t a0 = pack_h2(e00, e01);   // (r,   k=2tig..)
            uint32_t a1 = pack_h2(e02, e03);   // (r+8, k=2tig..)
            uint32_t a2 = pack_h2(e10, e11);   // (r,   k=8+2tig..)
            uint32_t a3 = pack_h2(e12, e13);   // (r+8, k=8+2tig..)
#pragma unroll
            for (int nt = 0; nt < 8; nt++) {
                int d = nt * 8 + gid;
                mma16816(o[nt], a0, a1, a2, a3,
                         V2[d * VTS + ch * 8 + tig], V2[d * VTS + ch * 8 + tig + 4]);
            }
        }
        // reduce row sums across the quad (lanes gid*4 + tig)
        lr  += __shfl_xor_sync(0xffffffffu, lr, 1);
        lr  += __shfl_xor_sync(0xffffffffu, lr, 2);
        lr8 += __shfl_xor_sync(0xffffffffu, lr8, 1);
        lr8 += __shfl_xor_sync(0xffffffffu, lr8, 2);
        float i0 = 1.f / lr, i1 = 1.f / lr8;

        if (r < Sn) {
            __half* op = g_attnh + (size_t)(b * Sn + r) * Dn + h * 64 + 2 * tig;
#pragma unroll
            for (int nt = 0; nt < 8; nt++)
                *(uint32_t*)(op + nt * 8) = pack_h2(o[nt][0] * i0, o[nt][1] * i0);
        }
        if (r + 8 < Sn) {
            __half* op = g_attnh + (size_t)(b * Sn + r + 8) * Dn + h * 64 + 2 * tig;
#pragma unroll
            for (int nt = 0; nt < 8; nt++)
                *(uint32_t*)(op + nt * 8) = pack_h2(o[nt][2] * i1, o[nt][3] * i1);
        }
    }
}

// ---------------- embedding + mask (fp32 + fp16 outputs) --------------------
__global__ void embed_kernel(const int* __restrict__ seq, const float* __restrict__ tab)
{
    int i = blockIdx.x;
    int t = threadIdx.x;
    int item = seq[i];
    if (t == 0) g_mask[i] = (item == 0) ? 0.f : 1.f;
    float4 v = ((const float4*)(tab + (size_t)item * Dn))[t];
    v.x = fminf(fmaxf(v.x * 0.5f, -1.f), 1.f);
    v.y = fminf(fmaxf(v.y * 0.5f, -1.f), 1.f);
    v.z = fminf(fmaxf(v.z * 0.5f, -1.f), 1.f);
    v.w = fminf(fmaxf(v.w * 0.5f, -1.f), 1.f);
    ((float4*)(g_x + (size_t)i * Dn))[t] = v;
    ((uint2*)(g_xh + (size_t)i * Dn))[t] = make_uint2(pack_h2(v.x, v.y), pack_h2(v.z, v.w));
}

// ---------------- fp32 SIMT GEMM (final tiny head GEMM only) ----------------
__global__ __launch_bounds__(256) void gemm_nt(
    const float* __restrict__ A, const float* __restrict__ W,
    const float* __restrict__ bias, float* __restrict__ C,
    int M, int N, int K, float lo, float hi, int relu)
{
    __shared__ float As[16][128];
    __shared__ float Bs[16][128];
    int tid = threadIdx.x;
    int tx = tid & 15, ty = tid >> 4;
    int lrow = tid >> 2;
    int lc4  = (tid & 3) * 4;
    const float* Ab = A + (size_t)blockIdx.y * 128 * K;
    const float* Wb = W + (size_t)blockIdx.x * 128 * K;
    int nbase = blockIdx.x * 128;

    float acc[8][8];
#pragma unroll
    for (int i = 0; i < 8; i++)
#pragma unroll
        for (int j = 0; j < 8; j++) acc[i][j] = 0.f;

    for (int k0 = 0; k0 < K; k0 += 16) {
#pragma unroll
        for (int r = 0; r < 2; r++) {
            int row = lrow + r * 64;
            float4 a = *(const float4*)(Ab + (size_t)row * K + k0 + lc4);
            As[lc4+0][row] = a.x; As[lc4+1][row] = a.y;
            As[lc4+2][row] = a.z; As[lc4+3][row] = a.w;
            float4 w4 = make_float4(0.f, 0.f, 0.f, 0.f);
            if (nbase + row < N)
                w4 = *(const float4*)(Wb + (size_t)row * K + k0 + lc4);
            Bs[lc4+0][row] = w4.x; Bs[lc4+1][row] = w4.y;
            Bs[lc4+2][row] = w4.z; Bs[lc4+3][row] = w4.w;
        }
        __syncthreads();
#pragma unroll
        for (int kk = 0; kk < 16; kk++) {
            float af[8], bf[8];
            *(float4*)&af[0] = *(const float4*)&As[kk][ty*8];
            *(float4*)&af[4] = *(const float4*)&As[kk][ty*8+4];
            *(float4*)&bf[0] = *(const float4*)&Bs[kk][tx*8];
            *(float4*)&bf[4] = *(const float4*)&Bs[kk][tx*8+4];
#pragma unroll
            for (int i = 0; i < 8; i++)
#pragma unroll
                for (int j = 0; j < 8; j++)
                    acc[i][j] = fmaf(af[i], bf[j], acc[i][j]);
        }
        __syncthreads();
    }

    int row0 = blockIdx.y * 128 + ty * 8;
    int col0 = nbase + tx * 8;
#pragma unroll
    for (int i = 0; i < 8; i++) {
#pragma unroll
        for (int j = 0; j < 8; j++) {
            int c = col0 + j;
            if (c < N) {
                float v = acc[i][j] + (bias ? bias[c] : 0.f);
                v = fminf(fmaxf(v, lo), hi);
                if (relu) v = fmaxf(v, 0.f);
                C[(size_t)(row0 + i) * N + c] = v;
            }
        }
    }
}

// ---------------- fused double residual+LN (p operand fp16) -----------------
__device__ __forceinline__ void block_reduce2(float& a, float& b, float* red)
{
    __syncthreads();
#pragma unroll
    for (int o = 16; o > 0; o >>= 1) {
        a += __shfl_xor_sync(0xffffffffu, a, o);
        b += __shfl_xor_sync(0xffffffffu, b, o);
    }
    int w = threadIdx.x >> 5;
    if ((threadIdx.x & 31) == 0) { red[w] = a; red[w + 8] = b; }
    __syncthreads();
    if (threadIdx.x == 0) {
        float ta = 0.f, tb = 0.f;
        for (int i = 0; i < 8; i++) { ta += red[i]; tb += red[i + 8]; }
        red[0] = ta; red[8] = tb;
    }
    __syncthreads();
    a = red[0]; b = red[8];
}

__global__ __launch_bounds__(256) void ln_chain_kernel(
    const float* __restrict__ x, const __half* __restrict__ p,
    const float* __restrict__ g, const float* __restrict__ bt,
    float* __restrict__ out, __half* __restrict__ out2, float clipv)
{
    __shared__ float red[16];
    int row = blockIdx.x;
    int t = threadIdx.x;
    float2 xv = ((const float2*)(x + (size_t)row * Dn))[t];
    float2 pv = __half22float2(((const __half2*)(p + (size_t)row * Dn))[t]);
    float t0 = xv.x + pv.x, t1 = xv.y + pv.y;
    float s1 = t0 + t1, s2 = t0 * t0 + t1 * t1;
    block_reduce2(s1, s2, red);
    float mean = s1 * (1.f / Dn);
    float inv = rsqrtf(s2 * (1.f / Dn) - mean * mean + 1e-6f);
    float2 gv = ((const float2*)g)[t];
    float2 bv = ((const float2*)bt)[t];
    float sa0 = (t0 - mean) * inv * gv.x + bv.x;
    float sa1 = (t1 - mean) * inv * gv.y + bv.y;
    float u0 = xv.x + sa0, u1 = xv.y + sa1;
    s1 = u0 + u1; s2 = u0 * u0 + u1 * u1;
    block_reduce2(s1, s2, red);
    mean = s1 * (1.f / Dn);
    inv = rsqrtf(s2 * (1.f / Dn) - mean * mean + 1e-6f);
    float o0 = (u0 - mean) * inv * gv.x + bv.x;
    float o1 = (u1 - mean) * inv * gv.y + bv.y;
    if (clipv > 0.f) {
        o0 = fminf(fmaxf(o0, -clipv), clipv);
        o1 = fminf(fmaxf(o1, -clipv), clipv);
    }
    ((float2*)(out + (size_t)row * Dn))[t] = make_float2(o0, o1);
    if (out2)
        ((uint32_t*)(out2 + (size_t)row * Dn))[t] = pack_h2(o0, o1);
}

// ---------------- masked mean pool + user feature concat (fp16 u) -----------
__global__ void pool_u_kernel(
    const float* __restrict__ uctr, const float* __restrict__ uti,
    const int* __restrict__ age, const int* __restrict__ gen, const int* __restrict__ cms,
    const float* __restrict__ atab, const float* __restrict__ gtab, const float* __restrict__ ctab,
    const float* __restrict__ cw, const float* __restrict__ cb,
    const float* __restrict__ tw, const float* __restrict__ tb)
{
    int b = blockIdx.x, j = threadIdx.x;
    const float* base = g_x + (size_t)b * Sn * Dn;
    float sum = 0.f, ms = 0.f;
    for (int s = 0; s < Sn; s++) {
        float m = g_mask[b * Sn + s];
        sum = fmaf(base[(size_t)s * Dn + j], m, sum);
        ms += m;
    }
    float rep = sum / (ms + 1e-8f);
    rep = fminf(fmaxf(rep, -5.f), 5.f);
    __half* u = g_uh + b * UD;
    u[j] = __float2half(rep);
    if (j < EMBn) {
        u[512 + j]  = __float2half(fmaf(uctr[b], cw[j], cb[j]));
        u[640 + j]  = __float2half(fmaf(uti[b],  tw[j], tb[j]));
        u[768 + j]  = __float2half(atab[age[b] * EMBn + j]);
        u[896 + j]  = __float2half(gtab[gen[b] * EMBn + j]);
        u[1024 + j] = __float2half(ctab[cms[b] * EMBn + j]);
    }
}

// ---------------- launch ----------------------------------------------------
extern "C" void kernel_launch(void* const* d_in, const int* in_sizes, int n_in,
                              void* d_out, int out_size)
{
    const int*   item_seq = (const int*)d_in[0];
    const float* uctr = (const float*)d_in[1];
    const float* uti  = (const float*)d_in[2];
    const int*   age  = (const int*)d_in[3];
    const int*   gen  = (const int*)d_in[4];
    const int*   cms  = (const int*)d_in[5];
    const float* emb  = (const float*)d_in[6];
    const float* inw  = (const float*)d_in[7];
    const float* outw = (const float*)d_in[8];
    const float* outb = (const float*)d_in[9];
    const float* ln1g = (const float*)d_in[10];
    const float* ln1b = (const float*)d_in[11];
    const float* ln2g = (const float*)d_in[12];
    const float* ln2b = (const float*)d_in[13];
    const float* l1w  = (const float*)d_in[14];
    const float* l1b  = (const float*)d_in[15];
    const float* l2w  = (const float*)d_in[16];
    const float* l2b  = (const float*)d_in[17];
    const float* atab = (const float*)d_in[18];
    const float* gtab = (const float*)d_in[19];
    const float* ctab = (const float*)d_in[20];
    const float* cw   = (const float*)d_in[21];
    const float* cb   = (const float*)d_in[22];
    const float* tw   = (const float*)d_in[23];
    const float* tb   = (const float*)d_in[24];
    const float* m1w  = (const float*)d_in[25];
    const float* m1b  = (const float*)d_in[26];
    const float* m2w  = (const float*)d_in[27];
    const float* m2b  = (const float*)d_in[28];
    float* out = (float*)d_out;

    float  *px, *pxn, *ph2;
    __half *pxh, *pqkvh, *pattnh, *pxnh, *phh, *pfh, *puh;
    __half *pinwh, *poutwh, *pl1wh, *pl2wh, *pm1wh;
    cudaGetSymbolAddress((void**)&px,     g_x);
    cudaGetSymbolAddress((void**)&pxn,    g_xn);
    cudaGetSymbolAddress((void**)&ph2,    g_h2);
    cudaGetSymbolAddress((void**)&pxh,    g_xh);
    cudaGetSymbolAddress((void**)&pqkvh,  g_qkvh);
    cudaGetSymbolAddress((void**)&pattnh, g_attnh);
    cudaGetSymbolAddress((void**)&pxnh,   g_xnh);
    cudaGetSymbolAddress((void**)&phh,    g_hh);
    cudaGetSymbolAddress((void**)&pfh,    g_fh);
    cudaGetSymbolAddress((void**)&puh,    g_uh);
    cudaGetSymbolAddress((void**)&pinwh,  g_inwh);
    cudaGetSymbolAddress((void**)&poutwh, g_outwh);
    cudaGetSymbolAddress((void**)&pl1wh,  g_l1wh);
    cudaGetSymbolAddress((void**)&pl2wh,  g_l2wh);
    cudaGetSymbolAddress((void**)&pm1wh,  g_m1wh);

    cudaFuncSetAttribute(attn_flash_kernel,
                         cudaFuncAttributeMaxDynamicSharedMemorySize, ATTN_SMEM);
    cudaFuncSetAttribute(hgemm,
                         cudaFuncAttributeMaxDynamicSharedMemorySize, HG_SMEM);

    const float INF = 1e30f;

    // weight conversions (fp32 -> fp16)
    w2h_kernel<<<(1536*Dn/4 + 255)/256, 256>>>(inw,  pinwh, 1536*Dn/4);
    w2h_kernel<<<(Dn*Dn/4   + 255)/256, 256>>>(outw, poutwh, Dn*Dn/4);
    w2h_kernel<<<(FFn*Dn/4  + 255)/256, 256>>>(l1w,  pl1wh, FFn*Dn/4);
    w2h_kernel<<<(Dn*FFn/4  + 255)/256, 256>>>(l2w,  pl2wh, Dn*FFn/4);
    w2h_kernel<<<(HIDn*UD/4 + 255)/256, 256>>>(m1w,  pm1wh, HIDn*UD/4);

    // x = clip(emb*0.5) -> fp32 + fp16, mask
    embed_kernel<<<BS, 128>>>(item_seq, emb);
    // qkv = clip(x @ in_proj^T, +-1) -> fp16
    hgemm<<<dim3(12, 800), 256, HG_SMEM>>>(pxh, pinwh, nullptr, nullptr, pqkvh, 1536, 512, -1.f, 1.f, 0);
    // flash tensor-core attention (fp16 in/out)
    attn_flash_kernel<<<dim3(Hn, Bn), 256, ATTN_SMEM>>>();
    // attn_proj = clip(attn @ out_w^T + b, +-3) -> fp16
    hgemm<<<dim3(4, 800), 256, HG_SMEM>>>(pattnh, poutwh, outb, nullptr, pfh, 512, 512, -3.f, 3.f, 0);
    // x_new = LN(x + LN(x + attn_proj)) -> fp32 + fp16
    ln_chain_kernel<<<BS, 256>>>(px, pfh, ln1g, ln1b, pxn, pxnh, 0.f);
    // h = relu(clip(x_new @ lin1^T + b, +-2)) -> fp16
    hgemm<<<dim3(8, 800), 256, HG_SMEM>>>(pxnh, pl1wh, l1b, nullptr, phh, 1024, 512, -2.f, 2.f, 1);
    // f2 = clip(h @ lin2^T + b, +-2) -> fp16
    hgemm<<<dim3(4, 800), 256, HG_SMEM>>>(phh, pl2wh, l2b, nullptr, pfh, 512, 1024, -2.f, 2.f, 0);
    // x_final = clip(LN(x_new + LN(x_new + f2)), +-5) -> fp32 g_x
    ln_chain_kernel<<<BS, 256>>>(pxn, pfh, ln2g, ln2b, px, nullptr, 5.f);
    // seq_rep + user features -> u (fp16)
    pool_u_kernel<<<Bn, 512>>>(uctr, uti, age, gen, cms, atab, gtab, ctab, cw, cb, tw, tb);
    // mlp head: h2 = relu(u @ m1w^T + b)  [fp16 mma]
    hgemm<<<dim3(8, 4), 256, HG_SMEM>>>(puh, pm1wh, m1b, ph2, nullptr, 1024, 1152, -INF, INF, 1);
    // out = h2 @ m2w^T + b  (tiny; fp32 SIMT)
    gemm_nt<<<dim3(1, 4), 256>>>(ph2, m2w, m2b, out, Bn, FINn, HIDn, -INF, INF, 0);
}

// round 10
// speedup vs baseline: 1.6674x; 1.0210x over previous
#include <cuda_runtime.h>
#include <cuda_fp16.h>
#include <cstdint>

#define Bn   512
#define Sn   200
#define Dn   512
#define Hn   8
#define FFn  1024
#define EMBn 128
#define HIDn 1024
#define FINn 64
#define UD   1152        // D + 5*EMB
#define BS   (Bn*Sn)     // 102400

// ---------------- scratch (static device globals; no runtime allocation) ----
__device__ __half g_fh[(size_t)BS*Dn];     // half attn_proj / f2 (LN "p" input)
__device__ __half g_xh[(size_t)BS*Dn];     // half embeddings -> later x_final
__device__ __half g_qkvh[(size_t)BS*3*Dn]; // half qkv
__device__ __half g_attnh[(size_t)BS*Dn];  // half attention out
__device__ __half g_xnh[(size_t)BS*Dn];    // half x_new
__device__ __half g_hh[(size_t)BS*FFn];    // half FFN hidden
__device__ __half g_inwh[1536*Dn];
__device__ __half g_outwh[Dn*Dn];
__device__ __half g_l1wh[FFn*Dn];
__device__ __half g_l2wh[Dn*FFn];
__device__ __half g_m1wh[HIDn*UD];
__device__ __half g_uh[Bn*UD];
__device__ float  g_mask[BS];
__device__ float  g_h2[Bn*HIDn];

__device__ __forceinline__ uint32_t pack_h2(float a, float b) {
    __half2 h = __floats2half2_rn(a, b);
    return *(uint32_t*)&h;
}

__device__ __forceinline__ void mma16816(float* c,
    uint32_t a0, uint32_t a1, uint32_t a2, uint32_t a3,
    uint32_t b0, uint32_t b1)
{
    asm volatile(
        "mma.sync.aligned.m16n8k16.row.col.f32.f16.f16.f32 "
        "{%0,%1,%2,%3}, {%4,%5,%6,%7}, {%8,%9}, {%0,%1,%2,%3};"
        : "+f"(c[0]), "+f"(c[1]), "+f"(c[2]), "+f"(c[3])
        : "r"(a0), "r"(a1), "r"(a2), "r"(a3), "r"(b0), "r"(b1));
}

__device__ __forceinline__ void ldsm_x4(uint32_t* r, uint32_t saddr) {
    asm volatile("ldmatrix.sync.aligned.m8n8.x4.shared.b16 {%0,%1,%2,%3}, [%4];"
        : "=r"(r[0]), "=r"(r[1]), "=r"(r[2]), "=r"(r[3]) : "r"(saddr));
}

__device__ __forceinline__ void cp16(uint32_t saddr, const void* g) {
    asm volatile("cp.async.cg.shared.global [%0], [%1], 16;" :: "r"(saddr), "l"(g));
}

// ---------------- all weight fp32 -> fp16 in one launch ---------------------
// segments (uint4 counts): inw 196608 | outw 65536 | l1w 131072 | l2w 131072 | m1w 294912
__global__ void w2h_all_kernel(const float* __restrict__ s0, const float* __restrict__ s1,
                               const float* __restrict__ s2, const float* __restrict__ s3,
                               const float* __restrict__ s4,
                               __half* __restrict__ d0, __half* __restrict__ d1,
                               __half* __restrict__ d2, __half* __restrict__ d3,
                               __half* __restrict__ d4)
{
    int i = blockIdx.x * 256 + threadIdx.x;   // 0..819199
    const float* s; __half* d; int off;
    if      (i < 196608) { s = s0; d = d0; off = i; }
    else if (i < 262144) { s = s1; d = d1; off = i - 196608; }
    else if (i < 393216) { s = s2; d = d2; off = i - 262144; }
    else if (i < 524288) { s = s3; d = d3; off = i - 393216; }
    else                 { s = s4; d = d4; off = i - 524288; }
    float4 v = ((const float4*)s)[off];
    ((uint2*)d)[off] = make_uint2(pack_h2(v.x, v.y), pack_h2(v.z, v.w));
}

// =================== fp16 GEMM: C[M,N] = epi(A @ W^T + bias) ================
// CTA 128x128, BK=32, 8 warps (2M x 4N), warp 64x32. cp.async 3-stage pipeline.
#define PADB 20
#define TILE_B (128*PADB*4)
#define HG_SMEM (3*2*TILE_B)

__global__ __launch_bounds__(256) void hgemm(
    const __half* __restrict__ A, const __half* __restrict__ W,
    const float* __restrict__ bias, float* __restrict__ Cf, __half* __restrict__ Ch,
    int N, int K, float lo, float hi, int relu)
{
    extern __shared__ uint32_t ds[];
    const uint32_t sb = (uint32_t)__cvta_generic_to_shared(ds);

    const int tid  = threadIdx.x;
    const int lane = tid & 31;
    const int wid  = tid >> 5;
    const int gid  = lane >> 2;
    const int tig  = lane & 3;
    const int mw = (wid >> 2) * 64;
    const int nw = (wid & 3) * 32;

    const size_t rowA0 = (size_t)blockIdx.y * 128;
    const size_t rowW0 = (size_t)blockIdx.x * 128;
    const int K4 = K >> 3;
    const uint4* A4 = (const uint4*)A + rowA0 * K4;
    const uint4* W4 = (const uint4*)W + rowW0 * K4;
    const int gr = tid >> 2;
    const int gc = tid & 3;
    const uint32_t gdst = (uint32_t)(gr * PADB + gc * 4) * 4;

    const int aRow = (lane & 7) + ((lane >> 3) & 1) * 8;
    const int aCol = (lane >> 4) * 4;
    const int bRow = (lane & 7) + (lane >> 4) * 8;
    const int bCol = ((lane >> 3) & 1) * 4;

    float acc[4][4][4];
#pragma unroll
    for (int mi = 0; mi < 4; mi++)
#pragma unroll
        for (int ni = 0; ni < 4; ni++)
#pragma unroll
            for (int j = 0; j < 4; j++) acc[mi][ni][j] = 0.f;

    const int nit = K >> 5;

#pragma unroll
    for (int s = 0; s < 2; s++) {
        uint32_t ao = sb + (uint32_t)s * TILE_B + gdst;
        uint32_t bo = ao + 3u * TILE_B;
        int ko = s * 4 + gc;
        cp16(ao,                  &A4[(size_t)gr * K4 + ko]);
        cp16(ao + 64 * PADB * 4,  &A4[(size_t)(gr + 64) * K4 + ko]);
        cp16(bo,                  &W4[(size_t)gr * K4 + ko]);
        cp16(bo + 64 * PADB * 4,  &W4[(size_t)(gr + 64) * K4 + ko]);
        asm volatile("cp.async.commit_group;");
    }

    for (int ck = 0; ck < nit; ck++) {
        asm volatile("cp.async.wait_group 1;");
        __syncthreads();
        const int buf = ck % 3;
        const uint32_t aB = sb + (uint32_t)buf * TILE_B;
        const uint32_t bB = aB + 3u * TILE_B;
#pragma unroll
        for (int ks = 0; ks < 2; ks++) {
            uint32_t af[4][4], bf[4][2];
#pragma unroll
            for (int mi = 0; mi < 4; mi++)
                ldsm_x4(af[mi], aB + ((mw + mi * 16 + aRow) * PADB + ks * 8 + aCol) * 4);
#pragma unroll
            for (int p = 0; p < 2; p++) {
                uint32_t t[4];
                ldsm_x4(t, bB + ((nw + p * 16 + bRow) * PADB + ks * 8 + bCol) * 4);
                bf[2*p][0] = t[0]; bf[2*p][1] = t[1];
                bf[2*p+1][0] = t[2]; bf[2*p+1][1] = t[3];
            }
#pragma unroll
            for (int mi = 0; mi < 4; mi++)
#pragma unroll
                for (int ni = 0; ni < 4; ni++)
                    mma16816(acc[mi][ni], af[mi][0], af[mi][1], af[mi][2], af[mi][3],
                             bf[ni][0], bf[ni][1]);
        }
        const int s = ck + 2;
        if (s < nit) {
            uint32_t ao = sb + (uint32_t)(s % 3) * TILE_B + gdst;
            uint32_t bo = ao + 3u * TILE_B;
            int ko = s * 4 + gc;
            cp16(ao,                  &A4[(size_t)gr * K4 + ko]);
            cp16(ao + 64 * PADB * 4,  &A4[(size_t)(gr + 64) * K4 + ko]);
            cp16(bo,                  &W4[(size_t)gr * K4 + ko]);
            cp16(bo + 64 * PADB * 4,  &W4[(size_t)(gr + 64) * K4 + ko]);
        }
        asm volatile("cp.async.commit_group;");
    }

    const int bn0 = blockIdx.x * 128 + nw;
#pragma unroll
    for (int mi = 0; mi < 4; mi++) {
        size_t row = rowA0 + mw + mi * 16 + gid;
#pragma unroll
        for (int ni = 0; ni < 4; ni++) {
            int col = bn0 + ni * 8 + 2 * tig;
            float b0 = bias ? bias[col]     : 0.f;
            float b1 = bias ? bias[col + 1] : 0.f;
            float v0 = acc[mi][ni][0] + b0, v1 = acc[mi][ni][1] + b1;
            float v2 = acc[mi][ni][2] + b0, v3 = acc[mi][ni][3] + b1;
            v0 = fminf(fmaxf(v0, lo), hi); v1 = fminf(fmaxf(v1, lo), hi);
            v2 = fminf(fmaxf(v2, lo), hi); v3 = fminf(fmaxf(v3, lo), hi);
            if (relu) {
                v0 = fmaxf(v0, 0.f); v1 = fmaxf(v1, 0.f);
                v2 = fmaxf(v2, 0.f); v3 = fmaxf(v3, 0.f);
            }
            if (Cf) {
                *(float2*)(Cf + row * N + col)       = make_float2(v0, v1);
                *(float2*)(Cf + (row + 8) * N + col) = make_float2(v2, v3);
            }
            if (Ch) {
                *(uint32_t*)(Ch + row * N + col)       = pack_h2(v0, v1);
                *(uint32_t*)(Ch + (row + 8) * N + col) = pack_h2(v2, v3);
            }
        }
    }
}

// =============== flash-style tensor-core attention per (b,h) ================
#define SP 208
#define QKS 36
#define VTS 108
#define ATTN_SMEM ((SP*QKS*2 + 64*VTS)*4 + SP*4)   // 88384 bytes -> 2 CTAs/SM

__global__ __launch_bounds__(256, 2) void attn_flash_kernel()
{
    extern __shared__ uint32_t smu[];
    uint32_t* Q2 = smu;
    uint32_t* K2 = smu + SP * QKS;
    uint32_t* V2 = K2 + SP * QKS;
    float* msk = (float*)(V2 + 64 * VTS);
    __half* Vh = (__half*)V2;

    const int h = blockIdx.x, b = blockIdx.y;
    const int tid = threadIdx.x;
    const int lane = tid & 31, wid = tid >> 5;
    const int gid = lane >> 2, tig = lane & 3;
    const __half* base = g_qkvh + (size_t)b * Sn * 1536 + h * 64;

    for (int idx = tid; idx < SP * 32; idx += 256) {
        int row = idx >> 5, c2 = idx & 31;
        uint32_t pq = 0u, pk = 0u;
        if (row < Sn) {
            const uint32_t* rp = (const uint32_t*)(base + (size_t)row * 1536);
            pq = rp[c2];
            pk = rp[256 + c2];
        }
        Q2[row * QKS + c2] = pq;
        K2[row * QKS + c2] = pk;
    }
    for (int idx = tid; idx < SP * 64; idx += 256) {
        int row = idx >> 6, col = idx & 63;
        __half v = (row < Sn) ? base[(size_t)row * 1536 + 1024 + col] : __half(0.f);
        Vh[col * (2 * VTS) + row] = v;
    }
    if (tid < SP) msk[tid] = (tid < Sn) ? g_mask[b * Sn + tid] : 0.f;
    __syncthreads();

    for (int mt = wid; mt < 13; mt += 8) {
        int r = mt * 16 + gid;
        uint32_t af[4][4];
#pragma unroll
        for (int kc = 0; kc < 4; kc++) {
            af[kc][0] = Q2[r * QKS + kc * 8 + tig];
            af[kc][1] = Q2[(r + 8) * QKS + kc * 8 + tig];
            af[kc][2] = Q2[r * QKS + kc * 8 + tig + 4];
            af[kc][3] = Q2[(r + 8) * QKS + kc * 8 + tig + 4];
        }
        float o[8][4];
#pragma unroll
        for (int nt = 0; nt < 8; nt++)
#pragma unroll
            for (int j = 0; j < 4; j++) o[nt][j] = 0.f;
        float lr = 0.f, lr8 = 0.f;

        for (int ch = 0; ch < 13; ch++) {
            float s0[4] = {0.f,0.f,0.f,0.f}, s1[4] = {0.f,0.f,0.f,0.f};
            int n0 = ch * 16 + gid, n1 = n0 + 8;
#pragma unroll
            for (int kc = 0; kc < 4; kc++) {
                mma16816(s0, af[kc][0], af[kc][1], af[kc][2], af[kc][3],
                         K2[n0 * QKS + kc * 8 + tig], K2[n0 * QKS + kc * 8 + tig + 4]);
                mma16816(s1, af[kc][0], af[kc][1], af[kc][2], af[kc][3],
                         K2[n1 * QKS + kc * 8 + tig], K2[n1 * QKS + kc * 8 + tig + 4]);
            }
            int c0 = ch * 16 + 2 * tig;
            float m00 = msk[c0], m01 = msk[c0 + 1];
            float m10 = msk[c0 + 8], m11 = msk[c0 + 9];
            float e00 = m00 * __expf(fminf(fmaxf(s0[0] * 2.5f, -3.f), 3.f) - 3.f);
            float e01 = m01 * __expf(fminf(fmaxf(s0[1] * 2.5f, -3.f), 3.f) - 3.f);
            float e02 = m00 * __expf(fminf(fmaxf(s0[2] * 2.5f, -3.f), 3.f) - 3.f);
            float e03 = m01 * __expf(fminf(fmaxf(s0[3] * 2.5f, -3.f), 3.f) - 3.f);
            float e10 = m10 * __expf(fminf(fmaxf(s1[0] * 2.5f, -3.f), 3.f) - 3.f);
            float e11 = m11 * __expf(fminf(fmaxf(s1[1] * 2.5f, -3.f), 3.f) - 3.f);
            float e12 = m10 * __expf(fminf(fmaxf(s1[2] * 2.5f, -3.f), 3.f) - 3.f);
            float e13 = m11 * __expf(fminf(fmaxf(s1[3] * 2.5f, -3.f), 3.f) - 3.f);
            lr  += e00 + e01 + e10 + e11;
            lr8 += e02 + e03 + e12 + e13;
            uint32_t a0 = pack_h2(e00, e01);
            uint32_t a1 = pack_h2(e02, e03);
            uint32_t a2 = pack_h2(e10, e11);
            uint32_t a3 = pack_h2(e12, e13);
#pragma unroll
            for (int nt = 0; nt < 8; nt++) {
                int d = nt * 8 + gid;
                mma16816(o[nt], a0, a1, a2, a3,
                         V2[d * VTS + ch * 8 + tig], V2[d * VTS + ch * 8 + tig + 4]);
            }
        }
        lr  += __shfl_xor_sync(0xffffffffu, lr, 1);
        lr  += __shfl_xor_sync(0xffffffffu, lr, 2);
        lr8 += __shfl_xor_sync(0xffffffffu, lr8, 1);
        lr8 += __shfl_xor_sync(0xffffffffu, lr8, 2);
        float i0 = 1.f / lr, i1 = 1.f / lr8;

        if (r < Sn) {
            __half* op = g_attnh + (size_t)(b * Sn + r) * Dn + h * 64 + 2 * tig;
#pragma unroll
            for (int nt = 0; nt < 8; nt++)
                *(uint32_t*)(op + nt * 8) = pack_h2(o[nt][0] * i0, o[nt][1] * i0);
        }
        if (r + 8 < Sn) {
            __half* op = g_attnh + (size_t)(b * Sn + r + 8) * Dn + h * 64 + 2 * tig;
#pragma unroll
            for (int nt = 0; nt < 8; nt++)
                *(uint32_t*)(op + nt * 8) = pack_h2(o[nt][2] * i1, o[nt][3] * i1);
        }
    }
}

// ---------------- embedding + mask (fp16 output only) -----------------------
__global__ void embed_kernel(const int* __restrict__ seq, const float* __restrict__ tab)
{
    int i = blockIdx.x;
    int t = threadIdx.x;
    int item = seq[i];
    if (t == 0) g_mask[i] = (item == 0) ? 0.f : 1.f;
    float4 v = ((const float4*)(tab + (size_t)item * Dn))[t];
    v.x = fminf(fmaxf(v.x * 0.5f, -1.f), 1.f);
    v.y = fminf(fmaxf(v.y * 0.5f, -1.f), 1.f);
    v.z = fminf(fmaxf(v.z * 0.5f, -1.f), 1.f);
    v.w = fminf(fmaxf(v.w * 0.5f, -1.f), 1.f);
    ((uint2*)(g_xh + (size_t)i * Dn))[t] = make_uint2(pack_h2(v.x, v.y), pack_h2(v.z, v.w));
}

// ---------------- fp32 SIMT GEMM (final tiny head GEMM only) ----------------
__global__ __launch_bounds__(256) void gemm_nt(
    const float* __restrict__ A, const float* __restrict__ W,
    const float* __restrict__ bias, float* __restrict__ C,
    int M, int N, int K, float lo, float hi, int relu)
{
    __shared__ float As[16][128];
    __shared__ float Bs[16][128];
    int tid = threadIdx.x;
    int tx = tid & 15, ty = tid >> 4;
    int lrow = tid >> 2;
    int lc4  = (tid & 3) * 4;
    const float* Ab = A + (size_t)blockIdx.y * 128 * K;
    const float* Wb = W + (size_t)blockIdx.x * 128 * K;
    int nbase = blockIdx.x * 128;

    float acc[8][8];
#pragma unroll
    for (int i = 0; i < 8; i++)
#pragma unroll
        for (int j = 0; j < 8; j++) acc[i][j] = 0.f;

    for (int k0 = 0; k0 < K; k0 += 16) {
#pragma unroll
        for (int r = 0; r < 2; r++) {
            int row = lrow + r * 64;
            float4 a = *(const float4*)(Ab + (size_t)row * K + k0 + lc4);
            As[lc4+0][row] = a.x; As[lc4+1][row] = a.y;
            As[lc4+2][row] = a.z; As[lc4+3][row] = a.w;
            float4 w4 = make_float4(0.f, 0.f, 0.f, 0.f);
            if (nbase + row < N)
                w4 = *(const float4*)(Wb + (size_t)row * K + k0 + lc4);
            Bs[lc4+0][row] = w4.x; Bs[lc4+1][row] = w4.y;
            Bs[lc4+2][row] = w4.z; Bs[lc4+3][row] = w4.w;
        }
        __syncthreads();
#pragma unroll
        for (int kk = 0; kk < 16; kk++) {
            float af[8], bf[8];
            *(float4*)&af[0] = *(const float4*)&As[kk][ty*8];
            *(float4*)&af[4] = *(const float4*)&As[kk][ty*8+4];
            *(float4*)&bf[0] = *(const float4*)&Bs[kk][tx*8];
            *(float4*)&bf[4] = *(const float4*)&Bs[kk][tx*8+4];
#pragma unroll
            for (int i = 0; i < 8; i++)
#pragma unroll
                for (int j = 0; j < 8; j++)
                    acc[i][j] = fmaf(af[i], bf[j], acc[i][j]);
        }
        __syncthreads();
    }

    int row0 = blockIdx.y * 128 + ty * 8;
    int col0 = nbase + tx * 8;
#pragma unroll
    for (int i = 0; i < 8; i++) {
#pragma unroll
        for (int j = 0; j < 8; j++) {
            int c = col0 + j;
            if (c < N) {
                float v = acc[i][j] + (bias ? bias[c] : 0.f);
                v = fminf(fmaxf(v, lo), hi);
                if (relu) v = fmaxf(v, 0.f);
                C[(size_t)(row0 + i) * N + c] = v;
            }
        }
    }
}

// ---------------- fused double residual+LN (all fp16 I/O, fp32 math) --------
__device__ __forceinline__ void block_reduce2(float& a, float& b, float* red)
{
    __syncthreads();
#pragma unroll
    for (int o = 16; o > 0; o >>= 1) {
        a += __shfl_xor_sync(0xffffffffu, a, o);
        b += __shfl_xor_sync(0xffffffffu, b, o);
    }
    int w = threadIdx.x >> 5;
    if ((threadIdx.x & 31) == 0) { red[w] = a; red[w + 8] = b; }
    __syncthreads();
    if (threadIdx.x == 0) {
        float ta = 0.f, tb = 0.f;
        for (int i = 0; i < 8; i++) { ta += red[i]; tb += red[i + 8]; }
        red[0] = ta; red[8] = tb;
    }
    __syncthreads();
    a = red[0]; b = red[8];
}

__global__ __launch_bounds__(256) void ln_chain_kernel(
    const __half* __restrict__ x, const __half* __restrict__ p,
    const float* __restrict__ g, const float* __restrict__ bt,
    __half* __restrict__ out, float clipv)
{
    __shared__ float red[16];
    int row = blockIdx.x;
    int t = threadIdx.x;
    float2 xv = __half22float2(((const __half2*)(x + (size_t)row * Dn))[t]);
    float2 pv = __half22float2(((const __half2*)(p + (size_t)row * Dn))[t]);
    float t0 = xv.x + pv.x, t1 = xv.y + pv.y;
    float s1 = t0 + t1, s2 = t0 * t0 + t1 * t1;
    block_reduce2(s1, s2, red);
    float mean = s1 * (1.f / Dn);
    float inv = rsqrtf(s2 * (1.f / Dn) - mean * mean + 1e-6f);
    float2 gv = ((const float2*)g)[t];
    float2 bv = ((const float2*)bt)[t];
    float sa0 = (t0 - mean) * inv * gv.x + bv.x;
    float sa1 = (t1 - mean) * inv * gv.y + bv.y;
    float u0 = xv.x + sa0, u1 = xv.y + sa1;
    s1 = u0 + u1; s2 = u0 * u0 + u1 * u1;
    block_reduce2(s1, s2, red);
    mean = s1 * (1.f / Dn);
    inv = rsqrtf(s2 * (1.f / Dn) - mean * mean + 1e-6f);
    float o0 = (u0 - mean) * inv * gv.x + bv.x;
    float o1 = (u1 - mean) * inv * gv.y + bv.y;
    if (clipv > 0.f) {
        o0 = fminf(fmaxf(o0, -clipv), clipv);
        o1 = fminf(fmaxf(o1, -clipv), clipv);
    }
    ((uint32_t*)(out + (size_t)row * Dn))[t] = pack_h2(o0, o1);
}

// ---------------- masked mean pool + user feature concat (fp16 in/out) ------
__global__ void pool_u_kernel(
    const float* __restrict__ uctr, const float* __restrict__ uti,
    const int* __restrict__ age, const int* __restrict__ gen, const int* __restrict__ cms,
    const float* __restrict__ atab, const float* __restrict__ gtab, const float* __restrict__ ctab,
    const float* __restrict__ cw, const float* __restrict__ cb,
    const float* __restrict__ tw, const float* __restrict__ tb)
{
    int b = blockIdx.x, j = threadIdx.x;
    const __half* base = g_xh + (size_t)b * Sn * Dn;
    float sum = 0.f, ms = 0.f;
    for (int s = 0; s < Sn; s++) {
        float m = g_mask[b * Sn + s];
        sum = fmaf(__half2float(base[(size_t)s * Dn + j]), m, sum);
        ms += m;
    }
    float rep = sum / (ms + 1e-8f);
    rep = fminf(fmaxf(rep, -5.f), 5.f);
    __half* u = g_uh + b * UD;
    u[j] = __float2half(rep);
    if (j < EMBn) {
        u[512 + j]  = __float2half(fmaf(uctr[b], cw[j], cb[j]));
        u[640 + j]  = __float2half(fmaf(uti[b],  tw[j], tb[j]));
        u[768 + j]  = __float2half(atab[age[b] * EMBn + j]);
        u[896 + j]  = __float2half(gtab[gen[b] * EMBn + j]);
        u[1024 + j] = __float2half(ctab[cms[b] * EMBn + j]);
    }
}

// ---------------- launch ----------------------------------------------------
extern "C" void kernel_launch(void* const* d_in, const int* in_sizes, int n_in,
                              void* d_out, int out_size)
{
    const int*   item_seq = (const int*)d_in[0];
    const float* uctr = (const float*)d_in[1];
    const float* uti  = (const float*)d_in[2];
    const int*   age  = (const int*)d_in[3];
    const int*   gen  = (const int*)d_in[4];
    const int*   cms  = (const int*)d_in[5];
    const float* emb  = (const float*)d_in[6];
    const float* inw  = (const float*)d_in[7];
    const float* outw = (const float*)d_in[8];
    const float* outb = (const float*)d_in[9];
    const float* ln1g = (const float*)d_in[10];
    const float* ln1b = (const float*)d_in[11];
    const float* ln2g = (const float*)d_in[12];
    const float* ln2b = (const float*)d_in[13];
    const float* l1w  = (const float*)d_in[14];
    const float* l1b  = (const float*)d_in[15];
    const float* l2w  = (const float*)d_in[16];
    const float* l2b  = (const float*)d_in[17];
    const float* atab = (const float*)d_in[18];
    const float* gtab = (const float*)d_in[19];
    const float* ctab = (const float*)d_in[20];
    const float* cw   = (const float*)d_in[21];
    const float* cb   = (const float*)d_in[22];
    const float* tw   = (const float*)d_in[23];
    const float* tb   = (const float*)d_in[24];
    const float* m1w  = (const float*)d_in[25];
    const float* m1b  = (const float*)d_in[26];
    const float* m2w  = (const float*)d_in[27];
    const float* m2b  = (const float*)d_in[28];
    float* out = (float*)d_out;

    float  *ph2;
    __half *pxh, *pqkvh, *pattnh, *pxnh, *phh, *pfh, *puh;
    __half *pinwh, *poutwh, *pl1wh, *pl2wh, *pm1wh;
    cudaGetSymbolAddress((void**)&ph2,    g_h2);
    cudaGetSymbolAddress((void**)&pxh,    g_xh);
    cudaGetSymbolAddress((void**)&pqkvh,  g_qkvh);
    cudaGetSymbolAddress((void**)&pattnh, g_attnh);
    cudaGetSymbolAddress((void**)&pxnh,   g_xnh);
    cudaGetSymbolAddress((void**)&phh,    g_hh);
    cudaGetSymbolAddress((void**)&pfh,    g_fh);
    cudaGetSymbolAddress((void**)&puh,    g_uh);
    cudaGetSymbolAddress((void**)&pinwh,  g_inwh);
    cudaGetSymbolAddress((void**)&poutwh, g_outwh);
    cudaGetSymbolAddress((void**)&pl1wh,  g_l1wh);
    cudaGetSymbolAddress((void**)&pl2wh,  g_l2wh);
    cudaGetSymbolAddress((void**)&pm1wh,  g_m1wh);

    cudaFuncSetAttribute(attn_flash_kernel,
                         cudaFuncAttributeMaxDynamicSharedMemorySize, ATTN_SMEM);
    cudaFuncSetAttribute(hgemm,
                         cudaFuncAttributeMaxDynamicSharedMemorySize, HG_SMEM);

    const float INF = 1e30f;

    // all weight conversions in one launch (819200 uint4s)
    w2h_all_kernel<<<3200, 256>>>(inw, outw, l1w, l2w, m1w,
                                  pinwh, poutwh, pl1wh, pl2wh, pm1wh);

    // x = clip(emb*0.5) -> fp16, mask
    embed_kernel<<<BS, 128>>>(item_seq, emb);
    // qkv = clip(x @ in_proj^T, +-1) -> fp16
    hgemm<<<dim3(12, 800), 256, HG_SMEM>>>(pxh, pinwh, nullptr, nullptr, pqkvh, 1536, 512, -1.f, 1.f, 0);
    // flash tensor-core attention (fp16 in/out)
    attn_flash_kernel<<<dim3(Hn, Bn), 256, ATTN_SMEM>>>();
    // attn_proj = clip(attn @ out_w^T + b, +-3) -> fp16
    hgemm<<<dim3(4, 800), 256, HG_SMEM>>>(pattnh, poutwh, outb, nullptr, pfh, 512, 512, -3.f, 3.f, 0);
    // x_new = LN(x + LN(x + attn_proj)) -> fp16
    ln_chain_kernel<<<BS, 256>>>(pxh, pfh, ln1g, ln1b, pxnh, 0.f);
    // h = relu(clip(x_new @ lin1^T + b, +-2)) -> fp16
    hgemm<<<dim3(8, 800), 256, HG_SMEM>>>(pxnh, pl1wh, l1b, nullptr, phh, 1024, 512, -2.f, 2.f, 1);
    // f2 = clip(h @ lin2^T + b, +-2) -> fp16
    hgemm<<<dim3(4, 800), 256, HG_SMEM>>>(phh, pl2wh, l2b, nullptr, pfh, 512, 1024, -2.f, 2.f, 0);
    // x_final = clip(LN(x_new + LN(x_new + f2)), +-5) -> fp16 (reuse g_xh)
    ln_chain_kernel<<<BS, 256>>>(pxnh, pfh, ln2g, ln2b, pxh, 5.f);
    // seq_rep + user features -> u (fp16)
    pool_u_kernel<<<Bn, 512>>>(uctr, uti, age, gen, cms, atab, gtab, ctab, cw, cb, tw, tb);
    // mlp head: h2 = relu(u @ m1w^T + b)  [fp16 mma]
    hgemm<<<dim3(8, 4), 256, HG_SMEM>>>(puh, pm1wh, m1b, ph2, nullptr, 1024, 1152, -INF, INF, 1);
    // out = h2 @ m2w^T + b  (tiny; fp32 SIMT)
    gemm_nt<<<dim3(1, 4), 256>>>(ph2, m2w, m2b, out, Bn, FINn, HIDn, -INF, INF, 0);
}

// round 11
// speedup vs baseline: 1.7863x; 1.0713x over previous
#include <cuda_runtime.h>
#include <cuda_fp16.h>
#include <cstdint>

#define Bn   512
#define Sn   200
#define Dn   512
#define Hn   8
#define FFn  1024
#define EMBn 128
#define HIDn 1024
#define FINn 64
#define UD   1152        // D + 5*EMB
#define BS   (Bn*Sn)     // 102400

// ---------------- scratch (static device globals; no runtime allocation) ----
__device__ __half g_fh[(size_t)BS*Dn];     // half attn_proj / f2 (LN "p" input)
__device__ __half g_xh[(size_t)BS*Dn];     // half embeddings -> later x_final
__device__ __half g_qkvh[(size_t)BS*3*Dn]; // half qkv
__device__ __half g_attnh[(size_t)BS*Dn];  // half attention out
__device__ __half g_xnh[(size_t)BS*Dn];    // half x_new
__device__ __half g_hh[(size_t)BS*FFn];    // half FFN hidden
__device__ __half g_inwh[1536*Dn];
__device__ __half g_outwh[Dn*Dn];
__device__ __half g_l1wh[FFn*Dn];
__device__ __half g_l2wh[Dn*FFn];
__device__ __half g_m1wh[HIDn*UD];
__device__ __half g_uh[Bn*UD];
__device__ float  g_mask[BS];
__device__ float  g_h2[Bn*HIDn];

__device__ __forceinline__ uint32_t pack_h2(float a, float b) {
    __half2 h = __floats2half2_rn(a, b);
    return *(uint32_t*)&h;
}

__device__ __forceinline__ void mma16816(float* c,
    uint32_t a0, uint32_t a1, uint32_t a2, uint32_t a3,
    uint32_t b0, uint32_t b1)
{
    asm volatile(
        "mma.sync.aligned.m16n8k16.row.col.f32.f16.f16.f32 "
        "{%0,%1,%2,%3}, {%4,%5,%6,%7}, {%8,%9}, {%0,%1,%2,%3};"
        : "+f"(c[0]), "+f"(c[1]), "+f"(c[2]), "+f"(c[3])
        : "r"(a0), "r"(a1), "r"(a2), "r"(a3), "r"(b0), "r"(b1));
}

__device__ __forceinline__ void ldsm_x4(uint32_t* r, uint32_t saddr) {
    asm volatile("ldmatrix.sync.aligned.m8n8.x4.shared.b16 {%0,%1,%2,%3}, [%4];"
        : "=r"(r[0]), "=r"(r[1]), "=r"(r[2]), "=r"(r[3]) : "r"(saddr));
}

__device__ __forceinline__ void cp16(uint32_t saddr, const void* g) {
    asm volatile("cp.async.cg.shared.global [%0], [%1], 16;" :: "r"(saddr), "l"(g));
}

// ---------------- all weight fp32 -> fp16 in one launch ---------------------
__global__ void w2h_all_kernel(const float* __restrict__ s0, const float* __restrict__ s1,
                               const float* __restrict__ s2, const float* __restrict__ s3,
                               const float* __restrict__ s4,
                               __half* __restrict__ d0, __half* __restrict__ d1,
                               __half* __restrict__ d2, __half* __restrict__ d3,
                               __half* __restrict__ d4)
{
    int i = blockIdx.x * 256 + threadIdx.x;   // 0..819199
    const float* s; __half* d; int off;
    if      (i < 196608) { s = s0; d = d0; off = i; }
    else if (i < 262144) { s = s1; d = d1; off = i - 196608; }
    else if (i < 393216) { s = s2; d = d2; off = i - 262144; }
    else if (i < 524288) { s = s3; d = d3; off = i - 393216; }
    else                 { s = s4; d = d4; off = i - 524288; }
    float4 v = ((const float4*)s)[off];
    ((uint2*)d)[off] = make_uint2(pack_h2(v.x, v.y), pack_h2(v.z, v.w));
}

// =================== fp16 GEMM: C[M,N] = epi(A @ W^T + bias) ================
// CTA 128x128, BK=32, 8 warps (2M x 4N), warp 64x32. cp.async 4-stage pipeline.
#define PADB 20
#define TILE_B (128*PADB*4)
#define HG_STAGES 4
#define HG_SMEM (HG_STAGES*2*TILE_B)       // 81920 bytes

__global__ __launch_bounds__(256) void hgemm(
    const __half* __restrict__ A, const __half* __restrict__ W,
    const float* __restrict__ bias, float* __restrict__ Cf, __half* __restrict__ Ch,
    int N, int K, float lo, float hi, int relu)
{
    extern __shared__ uint32_t ds[];
    const uint32_t sb = (uint32_t)__cvta_generic_to_shared(ds);

    const int tid  = threadIdx.x;
    const int lane = tid & 31;
    const int wid  = tid >> 5;
    const int gid  = lane >> 2;
    const int tig  = lane & 3;
    const int mw = (wid >> 2) * 64;
    const int nw = (wid & 3) * 32;

    const size_t rowA0 = (size_t)blockIdx.y * 128;
    const size_t rowW0 = (size_t)blockIdx.x * 128;
    const int K4 = K >> 3;
    const uint4* A4 = (const uint4*)A + rowA0 * K4;
    const uint4* W4 = (const uint4*)W + rowW0 * K4;
    const int gr = tid >> 2;
    const int gc = tid & 3;
    const uint32_t gdst = (uint32_t)(gr * PADB + gc * 4) * 4;

    const int aRow = (lane & 7) + ((lane >> 3) & 1) * 8;
    const int aCol = (lane >> 4) * 4;
    const int bRow = (lane & 7) + (lane >> 4) * 8;
    const int bCol = ((lane >> 3) & 1) * 4;

    float acc[4][4][4];
#pragma unroll
    for (int mi = 0; mi < 4; mi++)
#pragma unroll
        for (int ni = 0; ni < 4; ni++)
#pragma unroll
            for (int j = 0; j < 4; j++) acc[mi][ni][j] = 0.f;

    const int nit = K >> 5;

    // prologue: stages 0..2
#pragma unroll
    for (int s = 0; s < 3; s++) {
        uint32_t ao = sb + (uint32_t)s * TILE_B + gdst;
        uint32_t bo = ao + (uint32_t)HG_STAGES * TILE_B;
        int ko = s * 4 + gc;
        if (s < nit) {
            cp16(ao,                  &A4[(size_t)gr * K4 + ko]);
            cp16(ao + 64 * PADB * 4,  &A4[(size_t)(gr + 64) * K4 + ko]);
            cp16(bo,                  &W4[(size_t)gr * K4 + ko]);
            cp16(bo + 64 * PADB * 4,  &W4[(size_t)(gr + 64) * K4 + ko]);
        }
        asm volatile("cp.async.commit_group;");
    }

    for (int ck = 0; ck < nit; ck++) {
        asm volatile("cp.async.wait_group 2;");
        __syncthreads();
        const int buf = ck & (HG_STAGES - 1);
        const uint32_t aB = sb + (uint32_t)buf * TILE_B;
        const uint32_t bB = aB + (uint32_t)HG_STAGES * TILE_B;
#pragma unroll
        for (int ks = 0; ks < 2; ks++) {
            uint32_t af[4][4], bf[4][2];
#pragma unroll
            for (int mi = 0; mi < 4; mi++)
                ldsm_x4(af[mi], aB + ((mw + mi * 16 + aRow) * PADB + ks * 8 + aCol) * 4);
#pragma unroll
            for (int p = 0; p < 2; p++) {
                uint32_t t[4];
                ldsm_x4(t, bB + ((nw + p * 16 + bRow) * PADB + ks * 8 + bCol) * 4);
                bf[2*p][0] = t[0]; bf[2*p][1] = t[1];
                bf[2*p+1][0] = t[2]; bf[2*p+1][1] = t[3];
            }
#pragma unroll
            for (int mi = 0; mi < 4; mi++)
#pragma unroll
                for (int ni = 0; ni < 4; ni++)
                    mma16816(acc[mi][ni], af[mi][0], af[mi][1], af[mi][2], af[mi][3],
                             bf[ni][0], bf[ni][1]);
        }
        const int s = ck + 3;
        if (s < nit) {
            uint32_t ao = sb + (uint32_t)(s & (HG_STAGES - 1)) * TILE_B + gdst;
            uint32_t bo = ao + (uint32_t)HG_STAGES * TILE_B;
            int ko = s * 4 + gc;
            cp16(ao,                  &A4[(size_t)gr * K4 + ko]);
            cp16(ao + 64 * PADB * 4,  &A4[(size_t)(gr + 64) * K4 + ko]);
            cp16(bo,                  &W4[(size_t)gr * K4 + ko]);
            cp16(bo + 64 * PADB * 4,  &W4[(size_t)(gr + 64) * K4 + ko]);
        }
        asm volatile("cp.async.commit_group;");
    }

    const int bn0 = blockIdx.x * 128 + nw;
#pragma unroll
    for (int mi = 0; mi < 4; mi++) {
        size_t row = rowA0 + mw + mi * 16 + gid;
#pragma unroll
        for (int ni = 0; ni < 4; ni++) {
            int col = bn0 + ni * 8 + 2 * tig;
            float b0 = bias ? bias[col]     : 0.f;
            float b1 = bias ? bias[col + 1] : 0.f;
            float v0 = acc[mi][ni][0] + b0, v1 = acc[mi][ni][1] + b1;
            float v2 = acc[mi][ni][2] + b0, v3 = acc[mi][ni][3] + b1;
            v0 = fminf(fmaxf(v0, lo), hi); v1 = fminf(fmaxf(v1, lo), hi);
            v2 = fminf(fmaxf(v2, lo), hi); v3 = fminf(fmaxf(v3, lo), hi);
            if (relu) {
                v0 = fmaxf(v0, 0.f); v1 = fmaxf(v1, 0.f);
                v2 = fmaxf(v2, 0.f); v3 = fmaxf(v3, 0.f);
            }
            if (Cf) {
                *(float2*)(Cf + row * N + col)       = make_float2(v0, v1);
                *(float2*)(Cf + (row + 8) * N + col) = make_float2(v2, v3);
            }
            if (Ch) {
                *(uint32_t*)(Ch + row * N + col)       = pack_h2(v0, v1);
                *(uint32_t*)(Ch + (row + 8) * N + col) = pack_h2(v2, v3);
            }
        }
    }
}

// =============== flash-style tensor-core attention per (b,h) ================
#define SP 208
#define QKS 36
#define VTS 108
#define ATTN_SMEM ((SP*QKS*2 + 64*VTS)*4 + SP*4)   // 88384 bytes -> 2 CTAs/SM
// exp(clip(2.5 s, +-3) - 3) == exp2(clip(3.60674 s, +-4.32809) - 4.32809)
#define ESC 3.60673760f
#define ECL 4.32808512f

__global__ __launch_bounds__(256, 2) void attn_flash_kernel()
{
    extern __shared__ uint32_t smu[];
    uint32_t* Q2 = smu;
    uint32_t* K2 = smu + SP * QKS;
    uint32_t* V2 = K2 + SP * QKS;
    float* msk = (float*)(V2 + 64 * VTS);
    __half* Vh = (__half*)V2;

    const int h = blockIdx.x, b = blockIdx.y;
    const int tid = threadIdx.x;
    const int lane = tid & 31, wid = tid >> 5;
    const int gid = lane >> 2, tig = lane & 3;
    const __half* base = g_qkvh + (size_t)b * Sn * 1536 + h * 64;

    for (int idx = tid; idx < SP * 32; idx += 256) {
        int row = idx >> 5, c2 = idx & 31;
        uint32_t pq = 0u, pk = 0u;
        if (row < Sn) {
            const uint32_t* rp = (const uint32_t*)(base + (size_t)row * 1536);
            pq = rp[c2];
            pk = rp[256 + c2];
        }
        Q2[row * QKS + c2] = pq;
        K2[row * QKS + c2] = pk;
    }
    for (int idx = tid; idx < SP * 64; idx += 256) {
        int row = idx >> 6, col = idx & 63;
        __half v = (row < Sn) ? base[(size_t)row * 1536 + 1024 + col] : __half(0.f);
        Vh[col * (2 * VTS) + row] = v;
    }
    if (tid < SP) msk[tid] = (tid < Sn) ? g_mask[b * Sn + tid] : 0.f;
    __syncthreads();

    for (int mt = wid; mt < 13; mt += 8) {
        int r = mt * 16 + gid;
        uint32_t af[4][4];
#pragma unroll
        for (int kc = 0; kc < 4; kc++) {
            af[kc][0] = Q2[r * QKS + kc * 8 + tig];
            af[kc][1] = Q2[(r + 8) * QKS + kc * 8 + tig];
            af[kc][2] = Q2[r * QKS + kc * 8 + tig + 4];
            af[kc][3] = Q2[(r + 8) * QKS + kc * 8 + tig + 4];
        }
        float o[8][4];
#pragma unroll
        for (int nt = 0; nt < 8; nt++)
#pragma unroll
            for (int j = 0; j < 4; j++) o[nt][j] = 0.f;
        float lr = 0.f, lr8 = 0.f;

        for (int ch = 0; ch < 13; ch++) {
            float s0[4] = {0.f,0.f,0.f,0.f}, s1[4] = {0.f,0.f,0.f,0.f};
            int n0 = ch * 16 + gid, n1 = n0 + 8;
#pragma unroll
            for (int kc = 0; kc < 4; kc++) {
                mma16816(s0, af[kc][0], af[kc][1], af[kc][2], af[kc][3],
                         K2[n0 * QKS + kc * 8 + tig], K2[n0 * QKS + kc * 8 + tig + 4]);
                mma16816(s1, af[kc][0], af[kc][1], af[kc][2], af[kc][3],
                         K2[n1 * QKS + kc * 8 + tig], K2[n1 * QKS + kc * 8 + tig + 4]);
            }
            int c0 = ch * 16 + 2 * tig;
            float m00 = msk[c0], m01 = msk[c0 + 1];
            float m10 = msk[c0 + 8], m11 = msk[c0 + 9];
            float e00 = m00 * exp2f(fminf(fmaxf(s0[0] * ESC, -ECL), ECL) - ECL);
            float e01 = m01 * exp2f(fminf(fmaxf(s0[1] * ESC, -ECL), ECL) - ECL);
            float e02 = m00 * exp2f(fminf(fmaxf(s0[2] * ESC, -ECL), ECL) - ECL);
            float e03 = m01 * exp2f(fminf(fmaxf(s0[3] * ESC, -ECL), ECL) - ECL);
            float e10 = m10 * exp2f(fminf(fmaxf(s1[0] * ESC, -ECL), ECL) - ECL);
            float e11 = m11 * exp2f(fminf(fmaxf(s1[1] * ESC, -ECL), ECL) - ECL);
            float e12 = m10 * exp2f(fminf(fmaxf(s1[2] * ESC, -ECL), ECL) - ECL);
            float e13 = m11 * exp2f(fminf(fmaxf(s1[3] * ESC, -ECL), ECL) - ECL);
            lr  += e00 + e01 + e10 + e11;
            lr8 += e02 + e03 + e12 + e13;
            uint32_t a0 = pack_h2(e00, e01);
            uint32_t a1 = pack_h2(e02, e03);
            uint32_t a2 = pack_h2(e10, e11);
            uint32_t a3 = pack_h2(e12, e13);
#pragma unroll
            for (int nt = 0; nt < 8; nt++) {
                int d = nt * 8 + gid;
                mma16816(o[nt], a0, a1, a2, a3,
                         V2[d * VTS + ch * 8 + tig], V2[d * VTS + ch * 8 + tig + 4]);
            }
        }
        lr  += __shfl_xor_sync(0xffffffffu, lr, 1);
        lr  += __shfl_xor_sync(0xffffffffu, lr, 2);
        lr8 += __shfl_xor_sync(0xffffffffu, lr8, 1);
        lr8 += __shfl_xor_sync(0xffffffffu, lr8, 2);
        float i0 = 1.f / lr, i1 = 1.f / lr8;

        if (r < Sn) {
            __half* op = g_attnh + (size_t)(b * Sn + r) * Dn + h * 64 + 2 * tig;
#pragma unroll
            for (int nt = 0; nt < 8; nt++)
                *(uint32_t*)(op + nt * 8) = pack_h2(o[nt][0] * i0, o[nt][1] * i0);
        }
        if (r + 8 < Sn) {
            __half* op = g_attnh + (size_t)(b * Sn + r + 8) * Dn + h * 64 + 2 * tig;
#pragma unroll
            for (int nt = 0; nt < 8; nt++)
                *(uint32_t*)(op + nt * 8) = pack_h2(o[nt][2] * i1, o[nt][3] * i1);
        }
    }
}

// ---------------- embedding + mask (fp16 output only) -----------------------
__global__ void embed_kernel(const int* __restrict__ seq, const float* __restrict__ tab)
{
    int i = blockIdx.x;
    int t = threadIdx.x;
    int item = seq[i];
    if (t == 0) g_mask[i] = (item == 0) ? 0.f : 1.f;
    float4 v = ((const float4*)(tab + (size_t)item * Dn))[t];
    v.x = fminf(fmaxf(v.x * 0.5f, -1.f), 1.f);
    v.y = fminf(fmaxf(v.y * 0.5f, -1.f), 1.f);
    v.z = fminf(fmaxf(v.z * 0.5f, -1.f), 1.f);
    v.w = fminf(fmaxf(v.w * 0.5f, -1.f), 1.f);
    ((uint2*)(g_xh + (size_t)i * Dn))[t] = make_uint2(pack_h2(v.x, v.y), pack_h2(v.z, v.w));
}

// ---------------- fp32 SIMT GEMM (final tiny head GEMM only) ----------------
__global__ __launch_bounds__(256) void gemm_nt(
    const float* __restrict__ A, const float* __restrict__ W,
    const float* __restrict__ bias, float* __restrict__ C,
    int M, int N, int K, float lo, float hi, int relu)
{
    __shared__ float As[16][128];
    __shared__ float Bs[16][128];
    int tid = threadIdx.x;
    int tx = tid & 15, ty = tid >> 4;
    int lrow = tid >> 2;
    int lc4  = (tid & 3) * 4;
    const float* Ab = A + (size_t)blockIdx.y * 128 * K;
    const float* Wb = W + (size_t)blockIdx.x * 128 * K;
    int nbase = blockIdx.x * 128;

    float acc[8][8];
#pragma unroll
    for (int i = 0; i < 8; i++)
#pragma unroll
        for (int j = 0; j < 8; j++) acc[i][j] = 0.f;

    for (int k0 = 0; k0 < K; k0 += 16) {
#pragma unroll
        for (int r = 0; r < 2; r++) {
            int row = lrow + r * 64;
            float4 a = *(const float4*)(Ab + (size_t)row * K + k0 + lc4);
            As[lc4+0][row] = a.x; As[lc4+1][row] = a.y;
            As[lc4+2][row] = a.z; As[lc4+3][row] = a.w;
            float4 w4 = make_float4(0.f, 0.f, 0.f, 0.f);
            if (nbase + row < N)
                w4 = *(const float4*)(Wb + (size_t)row * K + k0 + lc4);
            Bs[lc4+0][row] = w4.x; Bs[lc4+1][row] = w4.y;
            Bs[lc4+2][row] = w4.z; Bs[lc4+3][row] = w4.w;
        }
        __syncthreads();
#pragma unroll
        for (int kk = 0; kk < 16; kk++) {
            float af[8], bf[8];
            *(float4*)&af[0] = *(const float4*)&As[kk][ty*8];
            *(float4*)&af[4] = *(const float4*)&As[kk][ty*8+4];
            *(float4*)&bf[0] = *(const float4*)&Bs[kk][tx*8];
            *(float4*)&bf[4] = *(const float4*)&Bs[kk][tx*8+4];
#pragma unroll
            for (int i = 0; i < 8; i++)
#pragma unroll
                for (int j = 0; j < 8; j++)
                    acc[i][j] = fmaf(af[i], bf[j], acc[i][j]);
        }
        __syncthreads();
    }

    int row0 = blockIdx.y * 128 + ty * 8;
    int col0 = nbase + tx * 8;
#pragma unroll
    for (int i = 0; i < 8; i++) {
#pragma unroll
        for (int j = 0; j < 8; j++) {
            int c = col0 + j;
            if (c < N) {
                float v = acc[i][j] + (bias ? bias[c] : 0.f);
                v = fminf(fmaxf(v, lo), hi);
                if (relu) v = fmaxf(v, 0.f);
                C[(size_t)(row0 + i) * N + c] = v;
            }
        }
    }
}

// ---------------- fused double residual+LN: warp-per-row, no barriers -------
__global__ __launch_bounds__(256) void ln_chain_kernel(
    const __half* __restrict__ x, const __half* __restrict__ p,
    const float* __restrict__ g, const float* __restrict__ bt,
    __half* __restrict__ out, float clipv)
{
    const int row  = blockIdx.x * 8 + (threadIdx.x >> 5);
    const int lane = threadIdx.x & 31;
    const __half2* xr = (const __half2*)(x + (size_t)row * Dn);
    const __half2* pr = (const __half2*)(p + (size_t)row * Dn);

    float2 xv[8], tv[8];
    float s1 = 0.f, s2 = 0.f;
#pragma unroll
    for (int i = 0; i < 8; i++) {
        xv[i] = __half22float2(xr[lane + 32 * i]);
        float2 pv = __half22float2(pr[lane + 32 * i]);
        float t0 = xv[i].x + pv.x, t1 = xv[i].y + pv.y;
        tv[i] = make_float2(t0, t1);
        s1 += t0 + t1;
        s2 += t0 * t0 + t1 * t1;
    }
#pragma unroll
    for (int o = 16; o > 0; o >>= 1) {
        s1 += __shfl_xor_sync(0xffffffffu, s1, o);
        s2 += __shfl_xor_sync(0xffffffffu, s2, o);
    }
    float mean = s1 * (1.f / Dn);
    float inv = rsqrtf(s2 * (1.f / Dn) - mean * mean + 1e-6f);

    float2 gv[8], bv[8], uv[8];
    float u1s = 0.f, u2s = 0.f;
#pragma unroll
    for (int i = 0; i < 8; i++) {
        gv[i] = ((const float2*)g)[lane + 32 * i];
        bv[i] = ((const float2*)bt)[lane + 32 * i];
        float sa0 = (tv[i].x - mean) * inv * gv[i].x + bv[i].x;
        float sa1 = (tv[i].y - mean) * inv * gv[i].y + bv[i].y;
        float u0 = xv[i].x + sa0, u1 = xv[i].y + sa1;
        uv[i] = make_float2(u0, u1);
        u1s += u0 + u1;
        u2s += u0 * u0 + u1 * u1;
    }
#pragma unroll
    for (int o = 16; o > 0; o >>= 1) {
        u1s += __shfl_xor_sync(0xffffffffu, u1s, o);
        u2s += __shfl_xor_sync(0xffffffffu, u2s, o);
    }
    mean = u1s * (1.f / Dn);
    inv = rsqrtf(u2s * (1.f / Dn) - mean * mean + 1e-6f);

    uint32_t* orow = (uint32_t*)(out + (size_t)row * Dn);
#pragma unroll
    for (int i = 0; i < 8; i++) {
        float o0 = (uv[i].x - mean) * inv * gv[i].x + bv[i].x;
        float o1 = (uv[i].y - mean) * inv * gv[i].y + bv[i].y;
        if (clipv > 0.f) {
            o0 = fminf(fmaxf(o0, -clipv), clipv);
            o1 = fminf(fmaxf(o1, -clipv), clipv);
        }
        orow[lane + 32 * i] = pack_h2(o0, o1);
    }
}

// ---------------- masked mean pool + user feature concat (fp16 in/out) ------
__global__ void pool_u_kernel(
    const float* __restrict__ uctr, const float* __restrict__ uti,
    const int* __restrict__ age, const int* __restrict__ gen, const int* __restrict__ cms,
    const float* __restrict__ atab, const float* __restrict__ gtab, const float* __restrict__ ctab,
    const float* __restrict__ cw, const float* __restrict__ cb,
    const float* __restrict__ tw, const float* __restrict__ tb)
{
    int b = blockIdx.x, j = threadIdx.x;
    const __half* base = g_xh + (size_t)b * Sn * Dn;
    float sum = 0.f, ms = 0.f;
    for (int s = 0; s < Sn; s++) {
        float m = g_mask[b * Sn + s];
        sum = fmaf(__half2float(base[(size_t)s * Dn + j]), m, sum);
        ms += m;
    }
    float rep = sum / (ms + 1e-8f);
    rep = fminf(fmaxf(rep, -5.f), 5.f);
    __half* u = g_uh + b * UD;
    u[j] = __float2half(rep);
    if (j < EMBn) {
        u[512 + j]  = __float2half(fmaf(uctr[b], cw[j], cb[j]));
        u[640 + j]  = __float2half(fmaf(uti[b],  tw[j], tb[j]));
        u[768 + j]  = __float2half(atab[age[b] * EMBn + j]);
        u[896 + j]  = __float2half(gtab[gen[b] * EMBn + j]);
        u[1024 + j] = __float2half(ctab[cms[b] * EMBn + j]);
    }
}

// ---------------- launch ----------------------------------------------------
extern "C" void kernel_launch(void* const* d_in, const int* in_sizes, int n_in,
                              void* d_out, int out_size)
{
    const int*   item_seq = (const int*)d_in[0];
    const float* uctr = (const float*)d_in[1];
    const float* uti  = (const float*)d_in[2];
    const int*   age  = (const int*)d_in[3];
    const int*   gen  = (const int*)d_in[4];
    const int*   cms  = (const int*)d_in[5];
    const float* emb  = (const float*)d_in[6];
    const float* inw  = (const float*)d_in[7];
    const float* outw = (const float*)d_in[8];
    const float* outb = (const float*)d_in[9];
    const float* ln1g = (const float*)d_in[10];
    const float* ln1b = (const float*)d_in[11];
    const float* ln2g = (const float*)d_in[12];
    const float* ln2b = (const float*)d_in[13];
    const float* l1w  = (const float*)d_in[14];
    const float* l1b  = (const float*)d_in[15];
    const float* l2w  = (const float*)d_in[16];
    const float* l2b  = (const float*)d_in[17];
    const float* atab = (const float*)d_in[18];
    const float* gtab = (const float*)d_in[19];
    const float* ctab = (const float*)d_in[20];
    const float* cw   = (const float*)d_in[21];
    const float* cb   = (const float*)d_in[22];
    const float* tw   = (const float*)d_in[23];
    const float* tb   = (const float*)d_in[24];
    const float* m1w  = (const float*)d_in[25];
    const float* m1b  = (const float*)d_in[26];
    const float* m2w  = (const float*)d_in[27];
    const float* m2b  = (const float*)d_in[28];
    float* out = (float*)d_out;

    float  *ph2;
    __half *pxh, *pqkvh, *pattnh, *pxnh, *phh, *pfh, *puh;
    __half *pinwh, *poutwh, *pl1wh, *pl2wh, *pm1wh;
    cudaGetSymbolAddress((void**)&ph2,    g_h2);
    cudaGetSymbolAddress((void**)&pxh,    g_xh);
    cudaGetSymbolAddress((void**)&pqkvh,  g_qkvh);
    cudaGetSymbolAddress((void**)&pattnh, g_attnh);
    cudaGetSymbolAddress((void**)&pxnh,   g_xnh);
    cudaGetSymbolAddress((void**)&phh,    g_hh);
    cudaGetSymbolAddress((void**)&pfh,    g_fh);
    cudaGetSymbolAddress((void**)&puh,    g_uh);
    cudaGetSymbolAddress((void**)&pinwh,  g_inwh);
    cudaGetSymbolAddress((void**)&poutwh, g_outwh);
    cudaGetSymbolAddress((void**)&pl1wh,  g_l1wh);
    cudaGetSymbolAddress((void**)&pl2wh,  g_l2wh);
    cudaGetSymbolAddress((void**)&pm1wh,  g_m1wh);

    cudaFuncSetAttribute(attn_flash_kernel,
                         cudaFuncAttributeMaxDynamicSharedMemorySize, ATTN_SMEM);
    cudaFuncSetAttribute(hgemm,
                         cudaFuncAttributeMaxDynamicSharedMemorySize, HG_SMEM);

    const float INF = 1e30f;

    // all weight conversions in one launch
    w2h_all_kernel<<<3200, 256>>>(inw, outw, l1w, l2w, m1w,
                                  pinwh, poutwh, pl1wh, pl2wh, pm1wh);

    // x = clip(emb*0.5) -> fp16, mask
    embed_kernel<<<BS, 128>>>(item_seq, emb);
    // qkv = clip(x @ in_proj^T, +-1) -> fp16
    hgemm<<<dim3(12, 800), 256, HG_SMEM>>>(pxh, pinwh, nullptr, nullptr, pqkvh, 1536, 512, -1.f, 1.f, 0);
    // flash tensor-core attention (fp16 in/out)
    attn_flash_kernel<<<dim3(Hn, Bn), 256, ATTN_SMEM>>>();
    // attn_proj = clip(attn @ out_w^T + b, +-3) -> fp16
    hgemm<<<dim3(4, 800), 256, HG_SMEM>>>(pattnh, poutwh, outb, nullptr, pfh, 512, 512, -3.f, 3.f, 0);
    // x_new = LN(x + LN(x + attn_proj)) -> fp16
    ln_chain_kernel<<<BS/8, 256>>>(pxh, pfh, ln1g, ln1b, pxnh, 0.f);
    // h = relu(clip(x_new @ lin1^T + b, +-2)) -> fp16
    hgemm<<<dim3(8, 800), 256, HG_SMEM>>>(pxnh, pl1wh, l1b, nullptr, phh, 1024, 512, -2.f, 2.f, 1);
    // f2 = clip(h @ lin2^T + b, +-2) -> fp16
    hgemm<<<dim3(4, 800), 256, HG_SMEM>>>(phh, pl2wh, l2b, nullptr, pfh, 512, 1024, -2.f, 2.f, 0);
    // x_final = clip(LN(x_new + LN(x_new + f2)), +-5) -> fp16 (reuse g_xh)
    ln_chain_kernel<<<BS/8, 256>>>(pxnh, pfh, ln2g, ln2b, pxh, 5.f);
    // seq_rep + user features -> u (fp16)
    pool_u_kernel<<<Bn, 512>>>(uctr, uti, age, gen, cms, atab, gtab, ctab, cw, cb, tw, tb);
    // mlp head: h2 = relu(u @ m1w^T + b)  [fp16 mma]
    hgemm<<<dim3(8, 4), 256, HG_SMEM>>>(puh, pm1wh, m1b, ph2, nullptr, 1024, 1152, -INF, INF, 1);
    // out = h2 @ m2w^T + b  (tiny; fp32 SIMT)
    gemm_nt<<<dim3(1, 4), 256>>>(ph2, m2w, m2b, out, Bn, FINn, HIDn, -INF, INF, 0);
}

// round 12
// speedup vs baseline: 1.8308x; 1.0249x over previous
#include <cuda_runtime.h>
#include <cuda_fp16.h>
#include <cstdint>

#define Bn   512
#define Sn   200
#define Dn   512
#define Hn   8
#define FFn  1024
#define EMBn 128
#define HIDn 1024
#define FINn 64
#define UD   1152        // D + 5*EMB
#define BS   (Bn*Sn)     // 102400

// ---------------- scratch (static device globals; no runtime allocation) ----
__device__ __half g_fh[(size_t)BS*Dn];     // half attn_proj / f2 (LN "p" input)
__device__ __half g_xh[(size_t)BS*Dn];     // half embeddings -> later x_final
__device__ __half g_qkvh[(size_t)BS*3*Dn]; // half qkv
__device__ __half g_attnh[(size_t)BS*Dn];  // half attention out
__device__ __half g_xnh[(size_t)BS*Dn];    // half x_new
__device__ __half g_hh[(size_t)BS*FFn];    // half FFN hidden
__device__ __half g_inwh[1536*Dn];
__device__ __half g_outwh[Dn*Dn];
__device__ __half g_l1wh[FFn*Dn];
__device__ __half g_l2wh[Dn*FFn];
__device__ __half g_m1wh[HIDn*UD];
__device__ __half g_uh[Bn*UD];
__device__ float  g_mask[BS];
__device__ float  g_h2[Bn*HIDn];

__device__ __forceinline__ uint32_t pack_h2(float a, float b) {
    __half2 h = __floats2half2_rn(a, b);
    return *(uint32_t*)&h;
}

__device__ __forceinline__ void mma16816(float* c,
    uint32_t a0, uint32_t a1, uint32_t a2, uint32_t a3,
    uint32_t b0, uint32_t b1)
{
    asm volatile(
        "mma.sync.aligned.m16n8k16.row.col.f32.f16.f16.f32 "
        "{%0,%1,%2,%3}, {%4,%5,%6,%7}, {%8,%9}, {%0,%1,%2,%3};"
        : "+f"(c[0]), "+f"(c[1]), "+f"(c[2]), "+f"(c[3])
        : "r"(a0), "r"(a1), "r"(a2), "r"(a3), "r"(b0), "r"(b1));
}

__device__ __forceinline__ void ldsm_x4(uint32_t* r, uint32_t saddr) {
    asm volatile("ldmatrix.sync.aligned.m8n8.x4.shared.b16 {%0,%1,%2,%3}, [%4];"
        : "=r"(r[0]), "=r"(r[1]), "=r"(r[2]), "=r"(r[3]) : "r"(saddr));
}

__device__ __forceinline__ void cp16(uint32_t saddr, const void* g) {
    asm volatile("cp.async.cg.shared.global [%0], [%1], 16;" :: "r"(saddr), "l"(g));
}

// ---------------- all weight fp32 -> fp16 in one launch ---------------------
__global__ void w2h_all_kernel(const float* __restrict__ s0, const float* __restrict__ s1,
                               const float* __restrict__ s2, const float* __restrict__ s3,
                               const float* __restrict__ s4,
                               __half* __restrict__ d0, __half* __restrict__ d1,
                               __half* __restrict__ d2, __half* __restrict__ d3,
                               __half* __restrict__ d4)
{
    int i = blockIdx.x * 256 + threadIdx.x;   // 0..819199
    const float* s; __half* d; int off;
    if      (i < 196608) { s = s0; d = d0; off = i; }
    else if (i < 262144) { s = s1; d = d1; off = i - 196608; }
    else if (i < 393216) { s = s2; d = d2; off = i - 262144; }
    else if (i < 524288) { s = s3; d = d3; off = i - 393216; }
    else                 { s = s4; d = d4; off = i - 524288; }
    float4 v = ((const float4*)s)[off];
    ((uint2*)d)[off] = make_uint2(pack_h2(v.x, v.y), pack_h2(v.z, v.w));
}

// =================== fp16 GEMM: C[M,N] = epi(A @ W^T + bias) ================
// CTA 128x128, BK=32, 8 warps (2M x 4N), warp 64x32. cp.async 4-stage pipeline.
#define PADB 20
#define TILE_B (128*PADB*4)
#define HG_STAGES 4
#define HG_SMEM (HG_STAGES*2*TILE_B)       // 81920 bytes

__global__ __launch_bounds__(256) void hgemm(
    const __half* __restrict__ A, const __half* __restrict__ W,
    const float* __restrict__ bias, float* __restrict__ Cf, __half* __restrict__ Ch,
    int N, int K, float lo, float hi, int relu)
{
    extern __shared__ uint32_t ds[];
    const uint32_t sb = (uint32_t)__cvta_generic_to_shared(ds);

    const int tid  = threadIdx.x;
    const int lane = tid & 31;
    const int wid  = tid >> 5;
    const int gid  = lane >> 2;
    const int tig  = lane & 3;
    const int mw = (wid >> 2) * 64;
    const int nw = (wid & 3) * 32;

    const size_t rowA0 = (size_t)blockIdx.y * 128;
    const size_t rowW0 = (size_t)blockIdx.x * 128;
    const int K4 = K >> 3;
    const uint4* A4 = (const uint4*)A + rowA0 * K4;
    const uint4* W4 = (const uint4*)W + rowW0 * K4;
    const int gr = tid >> 2;
    const int gc = tid & 3;
    const uint32_t gdst = (uint32_t)(gr * PADB + gc * 4) * 4;

    const int aRow = (lane & 7) + ((lane >> 3) & 1) * 8;
    const int aCol = (lane >> 4) * 4;
    const int bRow = (lane & 7) + (lane >> 4) * 8;
    const int bCol = ((lane >> 3) & 1) * 4;

    float acc[4][4][4];
#pragma unroll
    for (int mi = 0; mi < 4; mi++)
#pragma unroll
        for (int ni = 0; ni < 4; ni++)
#pragma unroll
            for (int j = 0; j < 4; j++) acc[mi][ni][j] = 0.f;

    const int nit = K >> 5;

#pragma unroll
    for (int s = 0; s < 3; s++) {
        uint32_t ao = sb + (uint32_t)s * TILE_B + gdst;
        uint32_t bo = ao + (uint32_t)HG_STAGES * TILE_B;
        int ko = s * 4 + gc;
        if (s < nit) {
            cp16(ao,                  &A4[(size_t)gr * K4 + ko]);
            cp16(ao + 64 * PADB * 4,  &A4[(size_t)(gr + 64) * K4 + ko]);
            cp16(bo,                  &W4[(size_t)gr * K4 + ko]);
            cp16(bo + 64 * PADB * 4,  &W4[(size_t)(gr + 64) * K4 + ko]);
        }
        asm volatile("cp.async.commit_group;");
    }

    for (int ck = 0; ck < nit; ck++) {
        asm volatile("cp.async.wait_group 2;");
        __syncthreads();
        const int buf = ck & (HG_STAGES - 1);
        const uint32_t aB = sb + (uint32_t)buf * TILE_B;
        const uint32_t bB = aB + (uint32_t)HG_STAGES * TILE_B;
#pragma unroll
        for (int ks = 0; ks < 2; ks++) {
            uint32_t af[4][4], bf[4][2];
#pragma unroll
            for (int mi = 0; mi < 4; mi++)
                ldsm_x4(af[mi], aB + ((mw + mi * 16 + aRow) * PADB + ks * 8 + aCol) * 4);
#pragma unroll
            for (int p = 0; p < 2; p++) {
                uint32_t t[4];
                ldsm_x4(t, bB + ((nw + p * 16 + bRow) * PADB + ks * 8 + bCol) * 4);
                bf[2*p][0] = t[0]; bf[2*p][1] = t[1];
                bf[2*p+1][0] = t[2]; bf[2*p+1][1] = t[3];
            }
#pragma unroll
            for (int mi = 0; mi < 4; mi++)
#pragma unroll
                for (int ni = 0; ni < 4; ni++)
                    mma16816(acc[mi][ni], af[mi][0], af[mi][1], af[mi][2], af[mi][3],
                             bf[ni][0], bf[ni][1]);
        }
        const int s = ck + 3;
        if (s < nit) {
            uint32_t ao = sb + (uint32_t)(s & (HG_STAGES - 1)) * TILE_B + gdst;
            uint32_t bo = ao + (uint32_t)HG_STAGES * TILE_B;
            int ko = s * 4 + gc;
            cp16(ao,                  &A4[(size_t)gr * K4 + ko]);
            cp16(ao + 64 * PADB * 4,  &A4[(size_t)(gr + 64) * K4 + ko]);
            cp16(bo,                  &W4[(size_t)gr * K4 + ko]);
            cp16(bo + 64 * PADB * 4,  &W4[(size_t)(gr + 64) * K4 + ko]);
        }
        asm volatile("cp.async.commit_group;");
    }

    const int bn0 = blockIdx.x * 128 + nw;
#pragma unroll
    for (int mi = 0; mi < 4; mi++) {
        size_t row = rowA0 + mw + mi * 16 + gid;
#pragma unroll
        for (int ni = 0; ni < 4; ni++) {
            int col = bn0 + ni * 8 + 2 * tig;
            float b0 = bias ? bias[col]     : 0.f;
            float b1 = bias ? bias[col + 1] : 0.f;
            float v0 = acc[mi][ni][0] + b0, v1 = acc[mi][ni][1] + b1;
            float v2 = acc[mi][ni][2] + b0, v3 = acc[mi][ni][3] + b1;
            v0 = fminf(fmaxf(v0, lo), hi); v1 = fminf(fmaxf(v1, lo), hi);
            v2 = fminf(fmaxf(v2, lo), hi); v3 = fminf(fmaxf(v3, lo), hi);
            if (relu) {
                v0 = fmaxf(v0, 0.f); v1 = fmaxf(v1, 0.f);
                v2 = fmaxf(v2, 0.f); v3 = fmaxf(v3, 0.f);
            }
            if (Cf) {
                *(float2*)(Cf + row * N + col)       = make_float2(v0, v1);
                *(float2*)(Cf + (row + 8) * N + col) = make_float2(v2, v3);
            }
            if (Ch) {
                *(uint32_t*)(Ch + row * N + col)       = pack_h2(v0, v1);
                *(uint32_t*)(Ch + (row + 8) * N + col) = pack_h2(v2, v3);
            }
        }
    }
}

// =============== flash-style tensor-core attention per (b,h) ================
// Q fragments straight from gmem; K XOR-swizzled at stride 32; Vt stride 108.
// Smem 55.1 KB -> 3 CTAs/SM.
#define SP 208
#define KS2 32    // b32 stride for K rows (XOR swizzled)
#define VTS 108   // b32 stride for Vt rows (104 used + 4 pad)
#define ATTN_SMEM ((SP*KS2 + 64*VTS)*4 + SP*4)   // 55104 bytes
// exp(clip(2.5 s, +-3) - 3) == exp2(clip(3.60674 s, +-4.32809) - 4.32809)
#define ESC 3.60673760f
#define ECL 4.32808512f

__global__ __launch_bounds__(256, 3) void attn_flash_kernel()
{
    extern __shared__ uint32_t smu[];
    uint32_t* K2 = smu;
    uint32_t* V2 = smu + SP * KS2;
    float* msk = (float*)(V2 + 64 * VTS);
    __half* Vh = (__half*)V2;

    const int h = blockIdx.x, b = blockIdx.y;
    const int tid = threadIdx.x;
    const int lane = tid & 31, wid = tid >> 5;
    const int gid = lane >> 2, tig = lane & 3;
    const __half* base = g_qkvh + (size_t)b * Sn * 1536 + h * 64;

    // K rows, XOR swizzle within stride-32 rows
    for (int idx = tid; idx < SP * 32; idx += 256) {
        int row = idx >> 5, c2 = idx & 31;
        uint32_t pk = 0u;
        if (row < Sn)
            pk = ((const uint32_t*)(base + (size_t)row * 1536))[256 + c2];
        K2[row * KS2 + (c2 ^ ((row & 7) << 2))] = pk;
    }
    // V transposed: Vt[d][key]
    for (int idx = tid; idx < SP * 64; idx += 256) {
        int row = idx >> 6, col = idx & 63;
        __half v = (row < Sn) ? base[(size_t)row * 1536 + 1024 + col] : __half(0.f);
        Vh[col * (2 * VTS) + row] = v;
    }
    if (tid < SP) msk[tid] = (tid < Sn) ? g_mask[b * Sn + tid] : 0.f;
    __syncthreads();

    const int sw = gid << 2;   // K swizzle term: n&7 == gid for all fragment rows

    for (int mt = wid; mt < 13; mt += 8) {
        int r = mt * 16 + gid;
        // Q fragments direct from gmem (rows clamped for the pad region)
        const uint32_t* q0 = (const uint32_t*)(base + (size_t)((r     < Sn) ? r     : 0) * 1536);
        const uint32_t* q1 = (const uint32_t*)(base + (size_t)((r + 8 < Sn) ? r + 8 : 0) * 1536);
        uint32_t af[4][4];
#pragma unroll
        for (int kc = 0; kc < 4; kc++) {
            af[kc][0] = q0[kc * 8 + tig];
            af[kc][1] = q1[kc * 8 + tig];
            af[kc][2] = q0[kc * 8 + tig + 4];
            af[kc][3] = q1[kc * 8 + tig + 4];
        }
        float o[8][4];
#pragma unroll
        for (int nt = 0; nt < 8; nt++)
#pragma unroll
            for (int j = 0; j < 4; j++) o[nt][j] = 0.f;
        float lr = 0.f, lr8 = 0.f;

        for (int ch = 0; ch < 13; ch++) {
            float s0[4] = {0.f,0.f,0.f,0.f}, s1[4] = {0.f,0.f,0.f,0.f};
            int n0 = ch * 16 + gid, n1 = n0 + 8;
#pragma unroll
            for (int kc = 0; kc < 4; kc++) {
                mma16816(s0, af[kc][0], af[kc][1], af[kc][2], af[kc][3],
                         K2[n0 * KS2 + ((kc * 8 + tig) ^ sw)],
                         K2[n0 * KS2 + ((kc * 8 + tig + 4) ^ sw)]);
                mma16816(s1, af[kc][0], af[kc][1], af[kc][2], af[kc][3],
                         K2[n1 * KS2 + ((kc * 8 + tig) ^ sw)],
                         K2[n1 * KS2 + ((kc * 8 + tig + 4) ^ sw)]);
            }
            int c0 = ch * 16 + 2 * tig;
            float m00 = msk[c0], m01 = msk[c0 + 1];
            float m10 = msk[c0 + 8], m11 = msk[c0 + 9];
            float e00 = m00 * exp2f(fminf(fmaxf(s0[0] * ESC, -ECL), ECL) - ECL);
            float e01 = m01 * exp2f(fminf(fmaxf(s0[1] * ESC, -ECL), ECL) - ECL);
            float e02 = m00 * exp2f(fminf(fmaxf(s0[2] * ESC, -ECL), ECL) - ECL);
            float e03 = m01 * exp2f(fminf(fmaxf(s0[3] * ESC, -ECL), ECL) - ECL);
            float e10 = m10 * exp2f(fminf(fmaxf(s1[0] * ESC, -ECL), ECL) - ECL);
            float e11 = m11 * exp2f(fminf(fmaxf(s1[1] * ESC, -ECL), ECL) - ECL);
            float e12 = m10 * exp2f(fminf(fmaxf(s1[2] * ESC, -ECL), ECL) - ECL);
            float e13 = m11 * exp2f(fminf(fmaxf(s1[3] * ESC, -ECL), ECL) - ECL);
            lr  += e00 + e01 + e10 + e11;
            lr8 += e02 + e03 + e12 + e13;
            uint32_t a0 = pack_h2(e00, e01);
            uint32_t a1 = pack_h2(e02, e03);
            uint32_t a2 = pack_h2(e10, e11);
            uint32_t a3 = pack_h2(e12, e13);
#pragma unroll
            for (int nt = 0; nt < 8; nt++) {
                int d = nt * 8 + gid;
                mma16816(o[nt], a0, a1, a2, a3,
                         V2[d * VTS + ch * 8 + tig], V2[d * VTS + ch * 8 + tig + 4]);
            }
        }
        lr  += __shfl_xor_sync(0xffffffffu, lr, 1);
        lr  += __shfl_xor_sync(0xffffffffu, lr, 2);
        lr8 += __shfl_xor_sync(0xffffffffu, lr8, 1);
        lr8 += __shfl_xor_sync(0xffffffffu, lr8, 2);
        float i0 = 1.f / lr, i1 = 1.f / lr8;

        if (r < Sn) {
            __half* op = g_attnh + (size_t)(b * Sn + r) * Dn + h * 64 + 2 * tig;
#pragma unroll
            for (int nt = 0; nt < 8; nt++)
                *(uint32_t*)(op + nt * 8) = pack_h2(o[nt][0] * i0, o[nt][1] * i0);
        }
        if (r + 8 < Sn) {
            __half* op = g_attnh + (size_t)(b * Sn + r + 8) * Dn + h * 64 + 2 * tig;
#pragma unroll
            for (int nt = 0; nt < 8; nt++)
                *(uint32_t*)(op + nt * 8) = pack_h2(o[nt][2] * i1, o[nt][3] * i1);
        }
    }
}

// ---------------- embedding + mask (fp16 output only) -----------------------
__global__ void embed_kernel(const int* __restrict__ seq, const float* __restrict__ tab)
{
    int i = blockIdx.x;
    int t = threadIdx.x;
    int item = seq[i];
    if (t == 0) g_mask[i] = (item == 0) ? 0.f : 1.f;
    float4 v = ((const float4*)(tab + (size_t)item * Dn))[t];
    v.x = fminf(fmaxf(v.x * 0.5f, -1.f), 1.f);
    v.y = fminf(fmaxf(v.y * 0.5f, -1.f), 1.f);
    v.z = fminf(fmaxf(v.z * 0.5f, -1.f), 1.f);
    v.w = fminf(fmaxf(v.w * 0.5f, -1.f), 1.f);
    ((uint2*)(g_xh + (size_t)i * Dn))[t] = make_uint2(pack_h2(v.x, v.y), pack_h2(v.z, v.w));
}

// ---------------- fp32 SIMT GEMM (final tiny head GEMM only) ----------------
__global__ __launch_bounds__(256) void gemm_nt(
    const float* __restrict__ A, const float* __restrict__ W,
    const float* __restrict__ bias, float* __restrict__ C,
    int M, int N, int K, float lo, float hi, int relu)
{
    __shared__ float As[16][128];
    __shared__ float Bs[16][128];
    int tid = threadIdx.x;
    int tx = tid & 15, ty = tid >> 4;
    int lrow = tid >> 2;
    int lc4  = (tid & 3) * 4;
    const float* Ab = A + (size_t)blockIdx.y * 128 * K;
    const float* Wb = W + (size_t)blockIdx.x * 128 * K;
    int nbase = blockIdx.x * 128;

    float acc[8][8];
#pragma unroll
    for (int i = 0; i < 8; i++)
#pragma unroll
        for (int j = 0; j < 8; j++) acc[i][j] = 0.f;

    for (int k0 = 0; k0 < K; k0 += 16) {
#pragma unroll
        for (int r = 0; r < 2; r++) {
            int row = lrow + r * 64;
            float4 a = *(const float4*)(Ab + (size_t)row * K + k0 + lc4);
            As[lc4+0][row] = a.x; As[lc4+1][row] = a.y;
            As[lc4+2][row] = a.z; As[lc4+3][row] = a.w;
            float4 w4 = make_float4(0.f, 0.f, 0.f, 0.f);
            if (nbase + row < N)
                w4 = *(const float4*)(Wb + (size_t)row * K + k0 + lc4);
            Bs[lc4+0][row] = w4.x; Bs[lc4+1][row] = w4.y;
            Bs[lc4+2][row] = w4.z; Bs[lc4+3][row] = w4.w;
        }
        __syncthreads();
#pragma unroll
        for (int kk = 0; kk < 16; kk++) {
            float af[8], bf[8];
            *(float4*)&af[0] = *(const float4*)&As[kk][ty*8];
            *(float4*)&af[4] = *(const float4*)&As[kk][ty*8+4];
            *(float4*)&bf[0] = *(const float4*)&Bs[kk][tx*8];
            *(float4*)&bf[4] = *(const float4*)&Bs[kk][tx*8+4];
#pragma unroll
            for (int i = 0; i < 8; i++)
#pragma unroll
                for (int j = 0; j < 8; j++)
                    acc[i][j] = fmaf(af[i], bf[j], acc[i][j]);
        }
        __syncthreads();
    }

    int row0 = blockIdx.y * 128 + ty * 8;
    int col0 = nbase + tx * 8;
#pragma unroll
    for (int i = 0; i < 8; i++) {
#pragma unroll
        for (int j = 0; j < 8; j++) {
            int c = col0 + j;
            if (c < N) {
                float v = acc[i][j] + (bias ? bias[c] : 0.f);
                v = fminf(fmaxf(v, lo), hi);
                if (relu) v = fmaxf(v, 0.f);
                C[(size_t)(row0 + i) * N + c] = v;
            }
        }
    }
}

// ---------------- fused double residual+LN: warp-per-row, no barriers -------
__global__ __launch_bounds__(256) void ln_chain_kernel(
    const __half* __restrict__ x, const __half* __restrict__ p,
    const float* __restrict__ g, const float* __restrict__ bt,
    __half* __restrict__ out, float clipv)
{
    const int row  = blockIdx.x * 8 + (threadIdx.x >> 5);
    const int lane = threadIdx.x & 31;
    const __half2* xr = (const __half2*)(x + (size_t)row * Dn);
    const __half2* pr = (const __half2*)(p + (size_t)row * Dn);

    float2 xv[8], tv[8];
    float s1 = 0.f, s2 = 0.f;
#pragma unroll
    for (int i = 0; i < 8; i++) {
        xv[i] = __half22float2(xr[lane + 32 * i]);
        float2 pv = __half22float2(pr[lane + 32 * i]);
        float t0 = xv[i].x + pv.x, t1 = xv[i].y + pv.y;
        tv[i] = make_float2(t0, t1);
        s1 += t0 + t1;
        s2 += t0 * t0 + t1 * t1;
    }
#pragma unroll
    for (int o = 16; o > 0; o >>= 1) {
        s1 += __shfl_xor_sync(0xffffffffu, s1, o);
        s2 += __shfl_xor_sync(0xffffffffu, s2, o);
    }
    float mean = s1 * (1.f / Dn);
    float inv = rsqrtf(s2 * (1.f / Dn) - mean * mean + 1e-6f);

    float2 gv[8], bv[8], uv[8];
    float u1s = 0.f, u2s = 0.f;
#pragma unroll
    for (int i = 0; i < 8; i++) {
        gv[i] = ((const float2*)g)[lane + 32 * i];
        bv[i] = ((const float2*)bt)[lane + 32 * i];
        float sa0 = (tv[i].x - mean) * inv * gv[i].x + bv[i].x;
        float sa1 = (tv[i].y - mean) * inv * gv[i].y + bv[i].y;
        float u0 = xv[i].x + sa0, u1 = xv[i].y + sa1;
        uv[i] = make_float2(u0, u1);
        u1s += u0 + u1;
        u2s += u0 * u0 + u1 * u1;
    }
#pragma unroll
    for (int o = 16; o > 0; o >>= 1) {
        u1s += __shfl_xor_sync(0xffffffffu, u1s, o);
        u2s += __shfl_xor_sync(0xffffffffu, u2s, o);
    }
    mean = u1s * (1.f / Dn);
    inv = rsqrtf(u2s * (1.f / Dn) - mean * mean + 1e-6f);

    uint32_t* orow = (uint32_t*)(out + (size_t)row * Dn);
#pragma unroll
    for (int i = 0; i < 8; i++) {
        float o0 = (uv[i].x - mean) * inv * gv[i].x + bv[i].x;
        float o1 = (uv[i].y - mean) * inv * gv[i].y + bv[i].y;
        if (clipv > 0.f) {
            o0 = fminf(fmaxf(o0, -clipv), clipv);
            o1 = fminf(fmaxf(o1, -clipv), clipv);
        }
        orow[lane + 32 * i] = pack_h2(o0, o1);
    }
}

// ---------------- masked mean pool + user feature concat (fp16 in/out) ------
__global__ void pool_u_kernel(
    const float* __restrict__ uctr, const float* __restrict__ uti,
    const int* __restrict__ age, const int* __restrict__ gen, const int* __restrict__ cms,
    const float* __restrict__ atab, const float* __restrict__ gtab, const float* __restrict__ ctab,
    const float* __restrict__ cw, const float* __restrict__ cb,
    const float* __restrict__ tw, const float* __restrict__ tb)
{
    int b = blockIdx.x, j = threadIdx.x;
    const __half* base = g_xh + (size_t)b * Sn * Dn;
    float sum = 0.f, ms = 0.f;
#pragma unroll 4
    for (int s = 0; s < Sn; s++) {
        float m = g_mask[b * Sn + s];
        sum = fmaf(__half2float(base[(size_t)s * Dn + j]), m, sum);
        ms += m;
    }
    float rep = sum / (ms + 1e-8f);
    rep = fminf(fmaxf(rep, -5.f), 5.f);
    __half* u = g_uh + b * UD;
    u[j] = __float2half(rep);
    if (j < EMBn) {
        u[512 + j]  = __float2half(fmaf(uctr[b], cw[j], cb[j]));
        u[640 + j]  = __float2half(fmaf(uti[b],  tw[j], tb[j]));
        u[768 + j]  = __float2half(atab[age[b] * EMBn + j]);
        u[896 + j]  = __float2half(gtab[gen[b] * EMBn + j]);
        u[1024 + j] = __float2half(ctab[cms[b] * EMBn + j]);
    }
}

// ---------------- launch ----------------------------------------------------
extern "C" void kernel_launch(void* const* d_in, const int* in_sizes, int n_in,
                              void* d_out, int out_size)
{
    const int*   item_seq = (const int*)d_in[0];
    const float* uctr = (const float*)d_in[1];
    const float* uti  = (const float*)d_in[2];
    const int*   age  = (const int*)d_in[3];
    const int*   gen  = (const int*)d_in[4];
    const int*   cms  = (const int*)d_in[5];
    const float* emb  = (const float*)d_in[6];
    const float* inw  = (const float*)d_in[7];
    const float* outw = (const float*)d_in[8];
    const float* outb = (const float*)d_in[9];
    const float* ln1g = (const float*)d_in[10];
    const float* ln1b = (const float*)d_in[11];
    const float* ln2g = (const float*)d_in[12];
    const float* ln2b = (const float*)d_in[13];
    const float* l1w  = (const float*)d_in[14];
    const float* l1b  = (const float*)d_in[15];
    const float* l2w  = (const float*)d_in[16];
    const float* l2b  = (const float*)d_in[17];
    const float* atab = (const float*)d_in[18];
    const float* gtab = (const float*)d_in[19];
    const float* ctab = (const float*)d_in[20];
    const float* cw   = (const float*)d_in[21];
    const float* cb   = (const float*)d_in[22];
    const float* tw   = (const float*)d_in[23];
    const float* tb   = (const float*)d_in[24];
    const float* m1w  = (const float*)d_in[25];
    const float* m1b  = (const float*)d_in[26];
    const float* m2w  = (const float*)d_in[27];
    const float* m2b  = (const float*)d_in[28];
    float* out = (float*)d_out;

    float  *ph2;
    __half *pxh, *pqkvh, *pattnh, *pxnh, *phh, *pfh, *puh;
    __half *pinwh, *poutwh, *pl1wh, *pl2wh, *pm1wh;
    cudaGetSymbolAddress((void**)&ph2,    g_h2);
    cudaGetSymbolAddress((void**)&pxh,    g_xh);
    cudaGetSymbolAddress((void**)&pqkvh,  g_qkvh);
    cudaGetSymbolAddress((void**)&pattnh, g_attnh);
    cudaGetSymbolAddress((void**)&pxnh,   g_xnh);
    cudaGetSymbolAddress((void**)&phh,    g_hh);
    cudaGetSymbolAddress((void**)&pfh,    g_fh);
    cudaGetSymbolAddress((void**)&puh,    g_uh);
    cudaGetSymbolAddress((void**)&pinwh,  g_inwh);
    cudaGetSymbolAddress((void**)&poutwh, g_outwh);
    cudaGetSymbolAddress((void**)&pl1wh,  g_l1wh);
    cudaGetSymbolAddress((void**)&pl2wh,  g_l2wh);
    cudaGetSymbolAddress((void**)&pm1wh,  g_m1wh);

    cudaFuncSetAttribute(attn_flash_kernel,
                         cudaFuncAttributeMaxDynamicSharedMemorySize, ATTN_SMEM);
    cudaFuncSetAttribute(hgemm,
                         cudaFuncAttributeMaxDynamicSharedMemorySize, HG_SMEM);

    const float INF = 1e30f;

    // all weight conversions in one launch
    w2h_all_kernel<<<3200, 256>>>(inw, outw, l1w, l2w, m1w,
                                  pinwh, poutwh, pl1wh, pl2wh, pm1wh);

    // x = clip(emb*0.5) -> fp16, mask
    embed_kernel<<<BS, 128>>>(item_seq, emb);
    // qkv = clip(x @ in_proj^T, +-1) -> fp16
    hgemm<<<dim3(12, 800), 256, HG_SMEM>>>(pxh, pinwh, nullptr, nullptr, pqkvh, 1536, 512, -1.f, 1.f, 0);
    // flash tensor-core attention (fp16 in/out)
    attn_flash_kernel<<<dim3(Hn, Bn), 256, ATTN_SMEM>>>();
    // attn_proj = clip(attn @ out_w^T + b, +-3) -> fp16
    hgemm<<<dim3(4, 800), 256, HG_SMEM>>>(pattnh, poutwh, outb, nullptr, pfh, 512, 512, -3.f, 3.f, 0);
    // x_new = LN(x + LN(x + attn_proj)) -> fp16
    ln_chain_kernel<<<BS/8, 256>>>(pxh, pfh, ln1g, ln1b, pxnh, 0.f);
    // h = relu(clip(x_new @ lin1^T + b, +-2)) -> fp16
    hgemm<<<dim3(8, 800), 256, HG_SMEM>>>(pxnh, pl1wh, l1b, nullptr, phh, 1024, 512, -2.f, 2.f, 1);
    // f2 = clip(h @ lin2^T + b, +-2) -> fp16
    hgemm<<<dim3(4, 800), 256, HG_SMEM>>>(phh, pl2wh, l2b, nullptr, pfh, 512, 1024, -2.f, 2.f, 0);
    // x_final = clip(LN(x_new + LN(x_new + f2)), +-5) -> fp16 (reuse g_xh)
    ln_chain_kernel<<<BS/8, 256>>>(pxnh, pfh, ln2g, ln2b, pxh, 5.f);
    // seq_rep + user features -> u (fp16)
    pool_u_kernel<<<Bn, 512>>>(uctr, uti, age, gen, cms, atab, gtab, ctab, cw, cb, tw, tb);
    // mlp head: h2 = relu(u @ m1w^T + b)  [fp16 mma]
    hgemm<<<dim3(8, 4), 256, HG_SMEM>>>(puh, pm1wh, m1b, ph2, nullptr, 1024, 1152, -INF, INF, 1);
    // out = h2 @ m2w^T + b  (tiny; fp32 SIMT)
    gemm_nt<<<dim3(1, 4), 256>>>(ph2, m2w, m2b, out, Bn, FINn, HIDn, -INF, INF, 0);
}